// round 9
// baseline (speedup 1.0000x reference)
#include <cuda_runtime.h>
#include <cuda_bf16.h>
#include <cuda_fp16.h>
#include <math.h>
#include <cstdint>

#define BB 2
#define SS 2048
#define DD 1024
#define HH 16
#define DH 64
#define M_TOTAL (BB*SS)      // 4096
#define N_TOTAL (3*DD)       // 3072

// ---------------- device scratch (no cudaMalloc allowed) -------------------
__device__ __align__(16) __nv_bfloat16 g_xh[M_TOTAL*DD];
__device__ __align__(16) __nv_bfloat16 g_xl[M_TOTAL*DD];
__device__ __align__(16) __nv_bfloat16 g_wth[3*DD*DD];   // W^T, [n][k]
__device__ __align__(16) __nv_bfloat16 g_wtl[3*DD*DD];
// projected Q/K bf16 hi/lo, V fp16, [B,H,S,DH]  (Q pre-scaled by log2(e))
__device__ __align__(16) __nv_bfloat16 g_qh[BB*HH*SS*DH];
__device__ __align__(16) __nv_bfloat16 g_ql[BB*HH*SS*DH];
__device__ __align__(16) __nv_bfloat16 g_kh[BB*HH*SS*DH];
__device__ __align__(16) __nv_bfloat16 g_kl[BB*HH*SS*DH];
__device__ __align__(16) __half        g_vf[BB*HH*SS*DH];

// ---------------- warp-mma helpers (plain sm_80+ PTX) ----------------------
__device__ __forceinline__ uint32_t smem_to_u32(const void* p) {
    uint32_t a;
    asm("{ .reg .u64 t; cvta.to.shared.u64 t, %1; cvt.u32.u64 %0, t; }"
        : "=r"(a) : "l"(p));
    return a;
}
__device__ __forceinline__ float ex2f(float x) {
    float y;
    asm("ex2.approx.f32 %0, %1;" : "=f"(y) : "f"(x));
    return y;
}

#define CP_ASYNC_16(dst, src) \
    asm volatile("cp.async.cg.shared.global [%0], [%1], 16;" :: "r"(dst), "l"(src))
#define CP_ASYNC_COMMIT() asm volatile("cp.async.commit_group;" ::: "memory")
#define CP_ASYNC_WAIT_ALL() asm volatile("cp.async.wait_group 0;" ::: "memory")

#define LDMATRIX_X4(r0, r1, r2, r3, addr) \
    asm volatile("ldmatrix.sync.aligned.m8n8.x4.shared.b16 {%0,%1,%2,%3}, [%4];" \
        : "=r"(r0), "=r"(r1), "=r"(r2), "=r"(r3) : "r"(addr))
#define LDMATRIX_X4_T(r0, r1, r2, r3, addr) \
    asm volatile("ldmatrix.sync.aligned.m8n8.x4.trans.shared.b16 {%0,%1,%2,%3}, [%4];" \
        : "=r"(r0), "=r"(r1), "=r"(r2), "=r"(r3) : "r"(addr))

#define MMA_BF16(cc, a0, a1, a2, a3, b0, b1) \
    asm volatile("mma.sync.aligned.m16n8k16.row.col.f32.bf16.bf16.f32 " \
        "{%0,%1,%2,%3}, {%4,%5,%6,%7}, {%8,%9}, {%0,%1,%2,%3};" \
        : "+f"((cc)[0]), "+f"((cc)[1]), "+f"((cc)[2]), "+f"((cc)[3]) \
        : "r"(a0), "r"(a1), "r"(a2), "r"(a3), "r"(b0), "r"(b1))

#define MMA_F16(cc, a0, a1, a2, a3, b0, b1) \
    asm volatile("mma.sync.aligned.m16n8k16.row.col.f32.f16.f16.f32 " \
        "{%0,%1,%2,%3}, {%4,%5,%6,%7}, {%8,%9}, {%0,%1,%2,%3};" \
        : "+f"((cc)[0]), "+f"((cc)[1]), "+f"((cc)[2]), "+f"((cc)[3]) \
        : "r"(a0), "r"(a1), "r"(a2), "r"(a3), "r"(b0), "r"(b1))

// ---------------------------------------------------------------------------
// Split kernels: fp32 -> bf16 hi + bf16 lo
// ---------------------------------------------------------------------------
__global__ void __launch_bounds__(256) split_x_kernel(const float* __restrict__ x) {
    int i = blockIdx.x * 256 + threadIdx.x;
    float v = x[i];
    __nv_bfloat16 hi = __float2bfloat16(v);
    g_xh[i] = hi;
    g_xl[i] = __float2bfloat16(v - __bfloat162float(hi));
}

__global__ void __launch_bounds__(256) split_w_kernel(
    const float* __restrict__ Wq, const float* __restrict__ Wk, const float* __restrict__ Wv)
{
    const float* W = (blockIdx.z == 0) ? Wq : (blockIdx.z == 1) ? Wk : Wv;
    __shared__ float t[32][33];
    int n0 = blockIdx.x * 32, k0 = blockIdx.y * 32;
    int tx = threadIdx.x, ty = threadIdx.y;   // block (32, 8)
    for (int r = ty; r < 32; r += 8)
        t[r][tx] = W[(size_t)(k0 + r) * DD + n0 + tx];
    __syncthreads();
    size_t base = (size_t)blockIdx.z * DD * DD;
    for (int r = ty; r < 32; r += 8) {
        float v = t[tx][r];
        __nv_bfloat16 hi = __float2bfloat16(v);
        size_t idx = base + (size_t)(n0 + r) * DD + k0 + tx;
        g_wth[idx] = hi;
        g_wtl[idx] = __float2bfloat16(v - __bfloat162float(hi));
    }
}

// ---------------------------------------------------------------------------
// Projection via mma.sync (unchanged from R8).
// ---------------------------------------------------------------------------
#define BK 32
#define STAGE_BYTES 32768
#define PROJ_SMEM (128*132*4)

__global__ void __launch_bounds__(256, 2) proj_mma_kernel(
    const float* __restrict__ bq, const float* __restrict__ bk, const float* __restrict__ bv)
{
    extern __shared__ __align__(1024) char smem[];
    const uint32_t smem_base = smem_to_u32(smem);
    float* Cs = (float*)smem;

    const int tid  = threadIdx.x;
    const int lane = tid & 31;
    const int warp = tid >> 5;
    const int wm   = warp >> 2;
    const int wn   = warp & 3;

    const int ntile = blockIdx.x;
    const int mtile = blockIdx.y;
    const int wsel  = ntile >> 3;
    const int ncol0 = (ntile & 7) * 128;
    const int m0    = mtile * 128;

    const __nv_bfloat16* Ah_g = g_xh;
    const __nv_bfloat16* Al_g = g_xl;
    const __nv_bfloat16* Bh_g = g_wth + (size_t)wsel * DD * DD;
    const __nv_bfloat16* Bl_g = g_wtl + (size_t)wsel * DD * DD;

    int ldsw[2];
    size_t ldga[2], ldgb[2];
    #pragma unroll
    for (int q = 0; q < 2; q++) {
        int idx = q * 256 + tid;
        int row = idx >> 2, c = idx & 3;
        ldsw[q]  = row * 64 + ((c ^ ((row >> 1) & 3)) << 4);
        ldga[q]  = (size_t)(m0 + row) * DD + c * 8;
        ldgb[q]  = (size_t)(ncol0 + row) * DD + c * 8;
    }

    int rA[4], gA[4];
    #pragma unroll
    for (int mt = 0; mt < 4; mt++) {
        rA[mt] = wm * 64 + mt * 16 + (lane & 15);
        gA[mt] = (rA[mt] >> 1) & 3;
    }
    const int khalfA = lane >> 4;

    float acc[4][4][4];
    #pragma unroll
    for (int i = 0; i < 4; i++)
        #pragma unroll
        for (int j = 0; j < 4; j++)
            #pragma unroll
            for (int r = 0; r < 4; r++) acc[i][j][r] = 0.f;

    const int NKC = DD / BK;

    {
        uint32_t sb = smem_base;
        #pragma unroll
        for (int q = 0; q < 2; q++) {
            CP_ASYNC_16(sb +         ldsw[q], Ah_g + ldga[q]);
            CP_ASYNC_16(sb +  8192 + ldsw[q], Al_g + ldga[q]);
            CP_ASYNC_16(sb + 16384 + ldsw[q], Bh_g + ldgb[q]);
            CP_ASYNC_16(sb + 24576 + ldsw[q], Bl_g + ldgb[q]);
        }
        CP_ASYNC_COMMIT();
    }

    for (int kc = 0; kc < NKC; kc++) {
        CP_ASYNC_WAIT_ALL();
        __syncthreads();

        if (kc + 1 < NKC) {
            uint32_t sb = smem_base + ((kc + 1) & 1) * STAGE_BYTES;
            size_t koff = (size_t)(kc + 1) * BK;
            #pragma unroll
            for (int q = 0; q < 2; q++) {
                CP_ASYNC_16(sb +         ldsw[q], Ah_g + ldga[q] + koff);
                CP_ASYNC_16(sb +  8192 + ldsw[q], Al_g + ldga[q] + koff);
                CP_ASYNC_16(sb + 16384 + ldsw[q], Bh_g + ldgb[q] + koff);
                CP_ASYNC_16(sb + 24576 + ldsw[q], Bl_g + ldgb[q] + koff);
            }
            CP_ASYNC_COMMIT();
        }

        const uint32_t sb = smem_base + (kc & 1) * STAGE_BYTES;
        const uint32_t ah = sb, al = sb + 8192, bh = sb + 16384, bl = sb + 24576;

        #pragma unroll
        for (int kf = 0; kf < 2; kf++) {
            const int cA = kf * 2 + khalfA;

            uint32_t B_h[4][2], B_l[4][2];
            #pragma unroll
            for (int ntp = 0; ntp < 2; ntp++) {
                int row = wn * 32 + ntp * 16 + ((lane >> 4) & 1) * 8 + (lane & 7);
                int chunk = kf * 2 + ((lane >> 3) & 1);
                uint32_t boff = row * 64 + (((chunk ^ ((row >> 1) & 3))) << 4);
                LDMATRIX_X4(B_h[2*ntp][0], B_h[2*ntp][1],
                            B_h[2*ntp+1][0], B_h[2*ntp+1][1], bh + boff);
                LDMATRIX_X4(B_l[2*ntp][0], B_l[2*ntp][1],
                            B_l[2*ntp+1][0], B_l[2*ntp+1][1], bl + boff);
            }
            uint32_t A[4][4];
            #pragma unroll
            for (int mt = 0; mt < 4; mt++) {
                uint32_t aoff = rA[mt] * 64 + (((cA ^ gA[mt])) << 4);
                LDMATRIX_X4(A[mt][0], A[mt][1], A[mt][2], A[mt][3], ah + aoff);
            }
            #pragma unroll
            for (int mt = 0; mt < 4; mt++)
                #pragma unroll
                for (int nt = 0; nt < 4; nt++) {
                    MMA_BF16(acc[mt][nt], A[mt][0], A[mt][1], A[mt][2], A[mt][3],
                             B_h[nt][0], B_h[nt][1]);
                    MMA_BF16(acc[mt][nt], A[mt][0], A[mt][1], A[mt][2], A[mt][3],
                             B_l[nt][0], B_l[nt][1]);
                }
            #pragma unroll
            for (int mt = 0; mt < 4; mt++) {
                uint32_t aoff = rA[mt] * 64 + (((cA ^ gA[mt])) << 4);
                LDMATRIX_X4(A[mt][0], A[mt][1], A[mt][2], A[mt][3], al + aoff);
            }
            #pragma unroll
            for (int mt = 0; mt < 4; mt++)
                #pragma unroll
                for (int nt = 0; nt < 4; nt++)
                    MMA_BF16(acc[mt][nt], A[mt][0], A[mt][1], A[mt][2], A[mt][3],
                             B_h[nt][0], B_h[nt][1]);
        }
    }
    __syncthreads();

    // ---- epilogue: bias + GELU (+log2e on Q), stage fp32, then store ----
    const float* bias = (wsel == 0) ? bq : (wsel == 1) ? bk : bv;

    const int fr = lane >> 2;
    const int fc = (lane & 3) * 2;
    #pragma unroll
    for (int mt = 0; mt < 4; mt++) {
        #pragma unroll
        for (int nt = 0; nt < 4; nt++) {
            int row0 = wm * 64 + mt * 16 + fr;
            int col0 = wn * 32 + nt * 8 + fc;
            float b0 = bias[ncol0 + col0], b1 = bias[ncol0 + col0 + 1];
            #pragma unroll
            for (int half = 0; half < 2; half++) {
                int r = row0 + half * 8;
                float v0 = acc[mt][nt][half * 2 + 0] + b0;
                float v1 = acc[mt][nt][half * 2 + 1] + b1;
                if (wsel == 0) {
                    v0 = 0.5f * v0 * (1.0f + erff(v0 * 0.70710678118654752f));
                    v1 = 0.5f * v1 * (1.0f + erff(v1 * 0.70710678118654752f));
                    v0 *= 1.44269504088896340736f;   // log2(e): softmax in base-2
                    v1 *= 1.44269504088896340736f;
                }
                Cs[r * 132 + col0]     = v0;
                Cs[r * 132 + col0 + 1] = v1;
            }
        }
    }
    __syncthreads();

    const int b  = m0 >> 11;
    const int s0 = m0 & 2047;
    if (wsel < 2) {
        __nv_bfloat16* dsth = (wsel == 0) ? g_qh : g_kh;
        __nv_bfloat16* dstl = (wsel == 0) ? g_ql : g_kl;
        #pragma unroll
        for (int hb = 0; hb < 2; hb++) {
            int h = (ncol0 >> 6) + hb;
            size_t base = (((size_t)(b * HH + h)) * SS + s0) * DH;
            for (int i = tid; i < 128 * 64; i += 256) {
                int s = i >> 6, dh = i & 63;
                float v = Cs[s * 132 + hb * 64 + dh];
                __nv_bfloat16 hi = __float2bfloat16(v);
                dsth[base + (size_t)s * DH + dh] = hi;
                dstl[base + (size_t)s * DH + dh] =
                    __float2bfloat16(v - __bfloat162float(hi));
            }
        }
    } else {
        #pragma unroll
        for (int hb = 0; hb < 2; hb++) {
            int h = (ncol0 >> 6) + hb;
            size_t base = (((size_t)(b * HH + h)) * SS + s0) * DH;
            for (int i = tid; i < 128 * 64; i += 256) {
                int s = i >> 6, dh = i & 63;
                g_vf[base + (size_t)s * DH + dh] =
                    __float2half_rn(Cs[s * 132 + hb * 64 + dh]);
            }
        }
    }
}

// ---------------------------------------------------------------------------
// Flash attention via mma.sync. 128 q-rows/CTA, 8 warps, KT=64.
// Q hi/lo frags register-resident (no per-iter Q LDSM; Q smem overlaid
// with KV stages -> 48KB smem). Half-tile pipelining: QK both halves,
// one combined max, then PV(half a) interleaved with exp/pack(half b).
// ---------------------------------------------------------------------------
#define FQT 128
#define FKT 64
#define FNIT (SS/FKT)
#define FST 24576                       // K/V stage stride (Kh|Kl|Vf x 8KB)
#define FLASH_SMEM (2*FST)              // 49152 (Q staging fits: 32KB < 48KB)

__global__ void __launch_bounds__(256, 2) flash_mma_kernel(float* __restrict__ out)
{
    extern __shared__ __align__(1024) char smem[];
    const uint32_t sb = smem_to_u32(smem);
    const int tid = threadIdx.x, lane = tid & 31, warp = tid >> 5;
    const int qb = blockIdx.x * FQT;
    const int h  = blockIdx.y, b = blockIdx.z;
    const size_t gbase = ((size_t)(b * HH + h)) * SS * DH;
    const __nv_bfloat16* Qh_g = g_qh + gbase;
    const __nv_bfloat16* Ql_g = g_ql + gbase;
    const __nv_bfloat16* Kh_g = g_kh + gbase;
    const __nv_bfloat16* Kl_g = g_kl + gbase;
    const __half*        Vf_g = g_vf + gbase;

    // ---- stage Q into smem temporarily (overlaid with KV stages) ----
    {
        #pragma unroll
        for (int q = 0; q < 4; q++) {
            int id = q * 256 + tid;            // 1024 chunks
            int row = id >> 3, c = id & 7;
            uint32_t dst = sb + row * 128 + ((c ^ (row & 7)) << 4);
            size_t src = (size_t)(qb + row) * DH + c * 8;
            CP_ASYNC_16(dst,         Qh_g + src);
            CP_ASYNC_16(dst + 16384, Ql_g + src);
        }
        CP_ASYNC_COMMIT();
        CP_ASYNC_WAIT_ALL();
        __syncthreads();
    }
    // extract Q frags to registers (resident for the whole kernel)
    uint32_t qh[4][4], ql[4][4];
    #pragma unroll
    for (int ks = 0; ks < 4; ks++) {
        int row = warp * 16 + (lane & 15);
        int chunk = 2 * ks + (lane >> 4);
        uint32_t addr = sb + row * 128 + ((chunk ^ (row & 7)) << 4);
        LDMATRIX_X4(qh[ks][0], qh[ks][1], qh[ks][2], qh[ks][3], addr);
        LDMATRIX_X4(ql[ks][0], ql[ks][1], ql[ks][2], ql[ks][3], addr + 16384);
    }
    __syncthreads();   // all warps extracted before KV overwrites staging

    int f_row[2], f_c[2];
    #pragma unroll
    for (int q = 0; q < 2; q++) {
        int id = q * 256 + tid;
        f_row[q] = id >> 3;
        f_c[q]   = id & 7;
    }

    // KV stage 0
    {
        #pragma unroll
        for (int q = 0; q < 2; q++) {
            int row = f_row[q], c = f_c[q];
            uint32_t o = row * 128 + ((c ^ (row & 7)) << 4);
            size_t src = (size_t)row * DH + c * 8;
            CP_ASYNC_16(sb +         o, Kh_g + src);
            CP_ASYNC_16(sb +  8192 + o, Kl_g + src);
            CP_ASYNC_16(sb + 16384 + o, Vf_g + src);
        }
        CP_ASYNC_COMMIT();
    }

    float oacc[8][4];
    #pragma unroll
    for (int i = 0; i < 8; i++)
        #pragma unroll
        for (int j = 0; j < 4; j++) oacc[i][j] = 0.f;
    float m0r = -INFINITY, m1r = -INFINITY, l0 = 0.f, l1 = 0.f;

    for (int it = 0; it < FNIT; it++) {
        CP_ASYNC_WAIT_ALL();
        __syncthreads();

        if (it + 1 < FNIT) {
            uint32_t buf = sb + ((it + 1) & 1) * FST;
            size_t kadd = (size_t)(it + 1) * FKT * DH;
            #pragma unroll
            for (int q = 0; q < 2; q++) {
                int row = f_row[q], c = f_c[q];
                uint32_t o = row * 128 + ((c ^ (row & 7)) << 4);
                size_t src = kadd + (size_t)row * DH + c * 8;
                CP_ASYNC_16(buf +         o, Kh_g + src);
                CP_ASYNC_16(buf +  8192 + o, Kl_g + src);
                CP_ASYNC_16(buf + 16384 + o, Vf_g + src);
            }
            CP_ASYNC_COMMIT();
        }

        const uint32_t buf = sb + (it & 1) * FST;
        const uint32_t kh = buf, kl = buf + 8192, vf = buf + 16384;

        // ---- S = Q K^T, both 32-key halves (3 split passes) ----
        float sacc[8][4];
        #pragma unroll
        for (int i = 0; i < 8; i++)
            #pragma unroll
            for (int j = 0; j < 4; j++) sacc[i][j] = 0.f;

        #pragma unroll
        for (int ks = 0; ks < 4; ks++) {
            #pragma unroll
            for (int ntp = 0; ntp < 4; ntp++) {
                int row = ntp * 16 + ((lane >> 4) & 1) * 8 + (lane & 7);
                int chunk = 2 * ks + ((lane >> 3) & 1);
                uint32_t addr = kh + row * 128 + ((chunk ^ (row & 7)) << 4);
                uint32_t bh0, bh1, bh2, bh3, bl0, bl1, bl2, bl3;
                LDMATRIX_X4(bh0, bh1, bh2, bh3, addr);
                LDMATRIX_X4(bl0, bl1, bl2, bl3, addr + 8192);
                MMA_BF16(sacc[2*ntp],   qh[ks][0], qh[ks][1], qh[ks][2], qh[ks][3], bh0, bh1);
                MMA_BF16(sacc[2*ntp],   ql[ks][0], ql[ks][1], ql[ks][2], ql[ks][3], bh0, bh1);
                MMA_BF16(sacc[2*ntp],   qh[ks][0], qh[ks][1], qh[ks][2], qh[ks][3], bl0, bl1);
                MMA_BF16(sacc[2*ntp+1], qh[ks][0], qh[ks][1], qh[ks][2], qh[ks][3], bh2, bh3);
                MMA_BF16(sacc[2*ntp+1], ql[ks][0], ql[ks][1], ql[ks][2], ql[ks][3], bh2, bh3);
                MMA_BF16(sacc[2*ntp+1], qh[ks][0], qh[ks][1], qh[ks][2], qh[ks][3], bl2, bl3);
            }
        }

        // ---- combined row max over both halves (base 2) ----
        float tm0 = -INFINITY, tm1 = -INFINITY;
        #pragma unroll
        for (int nt = 0; nt < 8; nt++) {
            tm0 = fmaxf(tm0, fmaxf(sacc[nt][0], sacc[nt][1]));
            tm1 = fmaxf(tm1, fmaxf(sacc[nt][2], sacc[nt][3]));
        }
        tm0 = fmaxf(tm0, __shfl_xor_sync(0xffffffffu, tm0, 1));
        tm0 = fmaxf(tm0, __shfl_xor_sync(0xffffffffu, tm0, 2));
        tm1 = fmaxf(tm1, __shfl_xor_sync(0xffffffffu, tm1, 1));
        tm1 = fmaxf(tm1, __shfl_xor_sync(0xffffffffu, tm1, 2));
        float mn0 = fmaxf(m0r, tm0), mn1 = fmaxf(m1r, tm1);
        float a0 = ex2f(m0r - mn0), a1 = ex2f(m1r - mn1);
        m0r = mn0; m1r = mn1;
        #pragma unroll
        for (int nt = 0; nt < 8; nt++) {
            oacc[nt][0] *= a0; oacc[nt][1] *= a0;
            oacc[nt][2] *= a1; oacc[nt][3] *= a1;
        }

        float rs0 = 0.f, rs1 = 0.f;
        uint32_t ph[4][4];
        // ---- pack half a (keys 0..31, nt 0..3 -> ph[0..1]) ----
        #pragma unroll
        for (int nt = 0; nt < 4; nt++) {
            float p00 = ex2f(sacc[nt][0] - mn0);
            float p01 = ex2f(sacc[nt][1] - mn0);
            float p10 = ex2f(sacc[nt][2] - mn1);
            float p11 = ex2f(sacc[nt][3] - mn1);
            rs0 += p00 + p01; rs1 += p10 + p11;
            __half2 h0 = __floats2half2_rn(p00, p01);
            __half2 h1 = __floats2half2_rn(p10, p11);
            int ks = nt >> 1, hf = (nt & 1) * 2;
            ph[ks][hf]     = *(uint32_t*)&h0;
            ph[ks][hf + 1] = *(uint32_t*)&h1;
        }
        // ---- PV(half a) interleaved with exp/pack(half b) ----
        #pragma unroll
        for (int pks = 0; pks < 2; pks++) {
            // pack 2 nts of half b (fills ph[2+pks])
            #pragma unroll
            for (int j = 0; j < 2; j++) {
                int nt = 4 + 2 * pks + j;
                float p00 = ex2f(sacc[nt][0] - mn0);
                float p01 = ex2f(sacc[nt][1] - mn0);
                float p10 = ex2f(sacc[nt][2] - mn1);
                float p11 = ex2f(sacc[nt][3] - mn1);
                rs0 += p00 + p01; rs1 += p10 + p11;
                __half2 h0 = __floats2half2_rn(p00, p01);
                __half2 h1 = __floats2half2_rn(p10, p11);
                int hf = (nt & 1) * 2;
                ph[2 + pks][hf]     = *(uint32_t*)&h0;
                ph[2 + pks][hf + 1] = *(uint32_t*)&h1;
            }
            // PV MMAs for key-group pks (V rows pks*16..+15)
            #pragma unroll
            for (int ntp = 0; ntp < 4; ntp++) {
                int row = pks * 16 + ((lane >> 3) & 1) * 8 + (lane & 7);
                int chunk = 2 * ntp + (lane >> 4);
                uint32_t addr = vf + row * 128 + ((chunk ^ (row & 7)) << 4);
                uint32_t b0, b1, b2, b3;
                LDMATRIX_X4_T(b0, b1, b2, b3, addr);
                MMA_F16(oacc[2*ntp],   ph[pks][0], ph[pks][1], ph[pks][2], ph[pks][3], b0, b1);
                MMA_F16(oacc[2*ntp+1], ph[pks][0], ph[pks][1], ph[pks][2], ph[pks][3], b2, b3);
            }
        }
        // ---- PV(half b) ----
        #pragma unroll
        for (int pks = 2; pks < 4; pks++) {
            #pragma unroll
            for (int ntp = 0; ntp < 4; ntp++) {
                int row = pks * 16 + ((lane >> 3) & 1) * 8 + (lane & 7);
                int chunk = 2 * ntp + (lane >> 4);
                uint32_t addr = vf + row * 128 + ((chunk ^ (row & 7)) << 4);
                uint32_t b0, b1, b2, b3;
                LDMATRIX_X4_T(b0, b1, b2, b3, addr);
                MMA_F16(oacc[2*ntp],   ph[pks][0], ph[pks][1], ph[pks][2], ph[pks][3], b0, b1);
                MMA_F16(oacc[2*ntp+1], ph[pks][0], ph[pks][1], ph[pks][2], ph[pks][3], b2, b3);
            }
        }
        l0 = l0 * a0 + rs0;
        l1 = l1 * a1 + rs1;
        // top-of-iteration barrier of it+1 orders these reads before the
        // prefetch that overwrites this buffer.
    }

    // ---- epilogue: reduce l across the 4-lane row group, store fp32 ----
    {
        l0 += __shfl_xor_sync(0xffffffffu, l0, 1);
        l0 += __shfl_xor_sync(0xffffffffu, l0, 2);
        l1 += __shfl_xor_sync(0xffffffffu, l1, 1);
        l1 += __shfl_xor_sync(0xffffffffu, l1, 2);
        const int r = lane >> 2, c2 = (lane & 3) * 2;
        float inv0 = 1.0f / l0, inv1 = 1.0f / l1;
        int row0 = qb + warp * 16 + r;
        size_t o0 = ((size_t)b * SS + row0) * DD + h * DH;
        size_t o1 = ((size_t)b * SS + row0 + 8) * DD + h * DH;
        #pragma unroll
        for (int nt = 0; nt < 8; nt++) {
            *(float2*)(out + o0 + nt * 8 + c2) =
                make_float2(oacc[nt][0] * inv0, oacc[nt][1] * inv0);
            *(float2*)(out + o1 + nt * 8 + c2) =
                make_float2(oacc[nt][2] * inv1, oacc[nt][3] * inv1);
        }
    }
}

// ---------------------------------------------------------------------------
extern "C" void kernel_launch(void* const* d_in, const int* in_sizes, int n_in,
                              void* d_out, int out_size) {
    const float* x  = (const float*)d_in[0];
    const float* Wq = (const float*)d_in[1];
    const float* bq = (const float*)d_in[2];
    const float* Wk = (const float*)d_in[3];
    const float* bk = (const float*)d_in[4];
    const float* Wv = (const float*)d_in[5];
    const float* bv = (const float*)d_in[6];
    float* out = (float*)d_out;

    split_x_kernel<<<M_TOTAL * DD / 256, 256>>>(x);
    split_w_kernel<<<dim3(DD/32, DD/32, 3), dim3(32, 8)>>>(Wq, Wk, Wv);

    cudaFuncSetAttribute(proj_mma_kernel,
                         cudaFuncAttributeMaxDynamicSharedMemorySize, PROJ_SMEM);
    proj_mma_kernel<<<dim3(N_TOTAL/128, M_TOTAL/128), 256, PROJ_SMEM>>>(bq, bk, bv);

    cudaFuncSetAttribute(flash_mma_kernel,
                         cudaFuncAttributeMaxDynamicSharedMemorySize, FLASH_SMEM);
    flash_mma_kernel<<<dim3(SS/FQT, HH, BB), 256, FLASH_SMEM>>>(out);
}

// round 10
// speedup vs baseline: 1.0270x; 1.0270x over previous
#include <cuda_runtime.h>
#include <cuda_bf16.h>
#include <cuda_fp16.h>
#include <math.h>
#include <cstdint>

#define BB 2
#define SS 2048
#define DD 1024
#define HH 16
#define DH 64
#define M_TOTAL (BB*SS)      // 4096
#define N_TOTAL (3*DD)       // 3072

// ---------------- device scratch (no cudaMalloc allowed) -------------------
__device__ __align__(16) __nv_bfloat16 g_xh[M_TOTAL*DD];
__device__ __align__(16) __nv_bfloat16 g_xl[M_TOTAL*DD];
__device__ __align__(16) __nv_bfloat16 g_wth[3*DD*DD];   // W^T, [n][k]
__device__ __align__(16) __nv_bfloat16 g_wtl[3*DD*DD];
// projected Q/K bf16 hi/lo, V fp16, [B,H,S,DH]  (Q pre-scaled by log2(e))
__device__ __align__(16) __nv_bfloat16 g_qh[BB*HH*SS*DH];
__device__ __align__(16) __nv_bfloat16 g_ql[BB*HH*SS*DH];
__device__ __align__(16) __nv_bfloat16 g_kh[BB*HH*SS*DH];
__device__ __align__(16) __nv_bfloat16 g_kl[BB*HH*SS*DH];
__device__ __align__(16) __half        g_vf[BB*HH*SS*DH];

// ---------------- warp-mma helpers (plain sm_80+ PTX) ----------------------
__device__ __forceinline__ uint32_t smem_to_u32(const void* p) {
    uint32_t a;
    asm("{ .reg .u64 t; cvta.to.shared.u64 t, %1; cvt.u32.u64 %0, t; }"
        : "=r"(a) : "l"(p));
    return a;
}
__device__ __forceinline__ float ex2f(float x) {
    float y;
    asm("ex2.approx.f32 %0, %1;" : "=f"(y) : "f"(x));
    return y;
}

#define CP_ASYNC_16(dst, src) \
    asm volatile("cp.async.cg.shared.global [%0], [%1], 16;" :: "r"(dst), "l"(src))
#define CP_ASYNC_COMMIT() asm volatile("cp.async.commit_group;" ::: "memory")
#define CP_ASYNC_WAIT_ALL() asm volatile("cp.async.wait_group 0;" ::: "memory")
#define CP_ASYNC_WAIT_1()  asm volatile("cp.async.wait_group 1;" ::: "memory")

#define LDMATRIX_X4(r0, r1, r2, r3, addr) \
    asm volatile("ldmatrix.sync.aligned.m8n8.x4.shared.b16 {%0,%1,%2,%3}, [%4];" \
        : "=r"(r0), "=r"(r1), "=r"(r2), "=r"(r3) : "r"(addr))
#define LDMATRIX_X4_T(r0, r1, r2, r3, addr) \
    asm volatile("ldmatrix.sync.aligned.m8n8.x4.trans.shared.b16 {%0,%1,%2,%3}, [%4];" \
        : "=r"(r0), "=r"(r1), "=r"(r2), "=r"(r3) : "r"(addr))

#define MMA_BF16(cc, a0, a1, a2, a3, b0, b1) \
    asm volatile("mma.sync.aligned.m16n8k16.row.col.f32.bf16.bf16.f32 " \
        "{%0,%1,%2,%3}, {%4,%5,%6,%7}, {%8,%9}, {%0,%1,%2,%3};" \
        : "+f"((cc)[0]), "+f"((cc)[1]), "+f"((cc)[2]), "+f"((cc)[3]) \
        : "r"(a0), "r"(a1), "r"(a2), "r"(a3), "r"(b0), "r"(b1))

#define MMA_F16(cc, a0, a1, a2, a3, b0, b1) \
    asm volatile("mma.sync.aligned.m16n8k16.row.col.f32.f16.f16.f32 " \
        "{%0,%1,%2,%3}, {%4,%5,%6,%7}, {%8,%9}, {%0,%1,%2,%3};" \
        : "+f"((cc)[0]), "+f"((cc)[1]), "+f"((cc)[2]), "+f"((cc)[3]) \
        : "r"(a0), "r"(a1), "r"(a2), "r"(a3), "r"(b0), "r"(b1))

// ---------------------------------------------------------------------------
// Split kernels: fp32 -> bf16 hi + bf16 lo
// ---------------------------------------------------------------------------
__global__ void __launch_bounds__(256) split_x_kernel(const float* __restrict__ x) {
    int i = blockIdx.x * 256 + threadIdx.x;
    float v = x[i];
    __nv_bfloat16 hi = __float2bfloat16(v);
    g_xh[i] = hi;
    g_xl[i] = __float2bfloat16(v - __bfloat162float(hi));
}

__global__ void __launch_bounds__(256) split_w_kernel(
    const float* __restrict__ Wq, const float* __restrict__ Wk, const float* __restrict__ Wv)
{
    const float* W = (blockIdx.z == 0) ? Wq : (blockIdx.z == 1) ? Wk : Wv;
    __shared__ float t[32][33];
    int n0 = blockIdx.x * 32, k0 = blockIdx.y * 32;
    int tx = threadIdx.x, ty = threadIdx.y;   // block (32, 8)
    for (int r = ty; r < 32; r += 8)
        t[r][tx] = W[(size_t)(k0 + r) * DD + n0 + tx];
    __syncthreads();
    size_t base = (size_t)blockIdx.z * DD * DD;
    for (int r = ty; r < 32; r += 8) {
        float v = t[tx][r];
        __nv_bfloat16 hi = __float2bfloat16(v);
        size_t idx = base + (size_t)(n0 + r) * DD + k0 + tx;
        g_wth[idx] = hi;
        g_wtl[idx] = __float2bfloat16(v - __bfloat162float(hi));
    }
}

// ---------------------------------------------------------------------------
// Projection via mma.sync. 3-stage cp.async ring, wait_group(1): every load
// gets two compute iterations to land instead of one.
// ---------------------------------------------------------------------------
#define BK 32
#define STAGE_BYTES 32768
#define PROJ_SMEM 98304                  // 3 stages; Cs(67.6KB) overlays

__global__ void __launch_bounds__(256, 2) proj_mma_kernel(
    const float* __restrict__ bq, const float* __restrict__ bk, const float* __restrict__ bv)
{
    extern __shared__ __align__(1024) char smem[];
    const uint32_t smem_base = smem_to_u32(smem);
    float* Cs = (float*)smem;

    const int tid  = threadIdx.x;
    const int lane = tid & 31;
    const int warp = tid >> 5;
    const int wm   = warp >> 2;
    const int wn   = warp & 3;

    const int ntile = blockIdx.x;
    const int mtile = blockIdx.y;
    const int wsel  = ntile >> 3;
    const int ncol0 = (ntile & 7) * 128;
    const int m0    = mtile * 128;

    const __nv_bfloat16* Ah_g = g_xh;
    const __nv_bfloat16* Al_g = g_xl;
    const __nv_bfloat16* Bh_g = g_wth + (size_t)wsel * DD * DD;
    const __nv_bfloat16* Bl_g = g_wtl + (size_t)wsel * DD * DD;

    int ldsw[2];
    size_t ldga[2], ldgb[2];
    #pragma unroll
    for (int q = 0; q < 2; q++) {
        int idx = q * 256 + tid;
        int row = idx >> 2, c = idx & 3;
        ldsw[q]  = row * 64 + ((c ^ ((row >> 1) & 3)) << 4);
        ldga[q]  = (size_t)(m0 + row) * DD + c * 8;
        ldgb[q]  = (size_t)(ncol0 + row) * DD + c * 8;
    }

    int rA[4], gA[4];
    #pragma unroll
    for (int mt = 0; mt < 4; mt++) {
        rA[mt] = wm * 64 + mt * 16 + (lane & 15);
        gA[mt] = (rA[mt] >> 1) & 3;
    }
    const int khalfA = lane >> 4;

    float acc[4][4][4];
    #pragma unroll
    for (int i = 0; i < 4; i++)
        #pragma unroll
        for (int j = 0; j < 4; j++)
            #pragma unroll
            for (int r = 0; r < 4; r++) acc[i][j][r] = 0.f;

    const int NKC = DD / BK;              // 32

    // prologue: stages 0 and 1, separate commit groups
    #pragma unroll
    for (int ps = 0; ps < 2; ps++) {
        uint32_t sb = smem_base + ps * STAGE_BYTES;
        size_t koff = (size_t)ps * BK;
        #pragma unroll
        for (int q = 0; q < 2; q++) {
            CP_ASYNC_16(sb +         ldsw[q], Ah_g + ldga[q] + koff);
            CP_ASYNC_16(sb +  8192 + ldsw[q], Al_g + ldga[q] + koff);
            CP_ASYNC_16(sb + 16384 + ldsw[q], Bh_g + ldgb[q] + koff);
            CP_ASYNC_16(sb + 24576 + ldsw[q], Bl_g + ldgb[q] + koff);
        }
        CP_ASYNC_COMMIT();
    }

    for (int kc = 0; kc < NKC; kc++) {
        if (kc + 1 < NKC) CP_ASYNC_WAIT_1();   // stage kc done; kc+1 may fly
        else              CP_ASYNC_WAIT_ALL();
        __syncthreads();

        if (kc + 2 < NKC) {
            uint32_t sb = smem_base + ((kc + 2) % 3) * STAGE_BYTES;
            size_t koff = (size_t)(kc + 2) * BK;
            #pragma unroll
            for (int q = 0; q < 2; q++) {
                CP_ASYNC_16(sb +         ldsw[q], Ah_g + ldga[q] + koff);
                CP_ASYNC_16(sb +  8192 + ldsw[q], Al_g + ldga[q] + koff);
                CP_ASYNC_16(sb + 16384 + ldsw[q], Bh_g + ldgb[q] + koff);
                CP_ASYNC_16(sb + 24576 + ldsw[q], Bl_g + ldgb[q] + koff);
            }
            CP_ASYNC_COMMIT();
        }

        const uint32_t sb = smem_base + (kc % 3) * STAGE_BYTES;
        const uint32_t ah = sb, al = sb + 8192, bh = sb + 16384, bl = sb + 24576;

        #pragma unroll
        for (int kf = 0; kf < 2; kf++) {
            const int cA = kf * 2 + khalfA;

            uint32_t B_h[4][2], B_l[4][2];
            #pragma unroll
            for (int ntp = 0; ntp < 2; ntp++) {
                int row = wn * 32 + ntp * 16 + ((lane >> 4) & 1) * 8 + (lane & 7);
                int chunk = kf * 2 + ((lane >> 3) & 1);
                uint32_t boff = row * 64 + (((chunk ^ ((row >> 1) & 3))) << 4);
                LDMATRIX_X4(B_h[2*ntp][0], B_h[2*ntp][1],
                            B_h[2*ntp+1][0], B_h[2*ntp+1][1], bh + boff);
                LDMATRIX_X4(B_l[2*ntp][0], B_l[2*ntp][1],
                            B_l[2*ntp+1][0], B_l[2*ntp+1][1], bl + boff);
            }
            uint32_t A[4][4];
            #pragma unroll
            for (int mt = 0; mt < 4; mt++) {
                uint32_t aoff = rA[mt] * 64 + (((cA ^ gA[mt])) << 4);
                LDMATRIX_X4(A[mt][0], A[mt][1], A[mt][2], A[mt][3], ah + aoff);
            }
            #pragma unroll
            for (int mt = 0; mt < 4; mt++)
                #pragma unroll
                for (int nt = 0; nt < 4; nt++) {
                    MMA_BF16(acc[mt][nt], A[mt][0], A[mt][1], A[mt][2], A[mt][3],
                             B_h[nt][0], B_h[nt][1]);
                    MMA_BF16(acc[mt][nt], A[mt][0], A[mt][1], A[mt][2], A[mt][3],
                             B_l[nt][0], B_l[nt][1]);
                }
            #pragma unroll
            for (int mt = 0; mt < 4; mt++) {
                uint32_t aoff = rA[mt] * 64 + (((cA ^ gA[mt])) << 4);
                LDMATRIX_X4(A[mt][0], A[mt][1], A[mt][2], A[mt][3], al + aoff);
            }
            #pragma unroll
            for (int mt = 0; mt < 4; mt++)
                #pragma unroll
                for (int nt = 0; nt < 4; nt++)
                    MMA_BF16(acc[mt][nt], A[mt][0], A[mt][1], A[mt][2], A[mt][3],
                             B_h[nt][0], B_h[nt][1]);
        }
    }
    __syncthreads();

    // ---- epilogue: bias + GELU (+log2e on Q), stage fp32, then store ----
    const float* bias = (wsel == 0) ? bq : (wsel == 1) ? bk : bv;

    const int fr = lane >> 2;
    const int fc = (lane & 3) * 2;
    #pragma unroll
    for (int mt = 0; mt < 4; mt++) {
        #pragma unroll
        for (int nt = 0; nt < 4; nt++) {
            int row0 = wm * 64 + mt * 16 + fr;
            int col0 = wn * 32 + nt * 8 + fc;
            float b0 = bias[ncol0 + col0], b1 = bias[ncol0 + col0 + 1];
            #pragma unroll
            for (int half = 0; half < 2; half++) {
                int r = row0 + half * 8;
                float v0 = acc[mt][nt][half * 2 + 0] + b0;
                float v1 = acc[mt][nt][half * 2 + 1] + b1;
                if (wsel == 0) {
                    v0 = 0.5f * v0 * (1.0f + erff(v0 * 0.70710678118654752f));
                    v1 = 0.5f * v1 * (1.0f + erff(v1 * 0.70710678118654752f));
                    v0 *= 1.44269504088896340736f;   // log2(e): softmax in base-2
                    v1 *= 1.44269504088896340736f;
                }
                Cs[r * 132 + col0]     = v0;
                Cs[r * 132 + col0 + 1] = v1;
            }
        }
    }
    __syncthreads();

    const int b  = m0 >> 11;
    const int s0 = m0 & 2047;
    if (wsel < 2) {
        __nv_bfloat16* dsth = (wsel == 0) ? g_qh : g_kh;
        __nv_bfloat16* dstl = (wsel == 0) ? g_ql : g_kl;
        #pragma unroll
        for (int hb = 0; hb < 2; hb++) {
            int h = (ncol0 >> 6) + hb;
            size_t base = (((size_t)(b * HH + h)) * SS + s0) * DH;
            for (int i = tid; i < 128 * 64; i += 256) {
                int s = i >> 6, dh = i & 63;
                float v = Cs[s * 132 + hb * 64 + dh];
                __nv_bfloat16 hi = __float2bfloat16(v);
                dsth[base + (size_t)s * DH + dh] = hi;
                dstl[base + (size_t)s * DH + dh] =
                    __float2bfloat16(v - __bfloat162float(hi));
            }
        }
    } else {
        #pragma unroll
        for (int hb = 0; hb < 2; hb++) {
            int h = (ncol0 >> 6) + hb;
            size_t base = (((size_t)(b * HH + h)) * SS + s0) * DH;
            for (int i = tid; i < 128 * 64; i += 256) {
                int s = i >> 6, dh = i & 63;
                g_vf[base + (size_t)s * DH + dh] =
                    __float2half_rn(Cs[s * 132 + hb * 64 + dh]);
            }
        }
    }
}

// ---------------------------------------------------------------------------
// Flash attention via mma.sync (R8 structure: Q in smem, reload per ks;
// online max; fp16 P; single fp16 PV pass). NEW: 3-stage KV ring with
// wait_group(1) so each KV load gets two iterations of latency shadow.
// ---------------------------------------------------------------------------
#define FQT 128
#define FKT 64
#define FNIT (SS/FKT)
#define FQB 32768                       // Q region: hi 16KB + lo 16KB
#define FST 24576                       // K/V stage stride (Kh|Kl|Vf x 8KB)
#define FLASH_SMEM (FQB + 3*FST)        // 106496

__global__ void __launch_bounds__(256, 2) flash_mma_kernel(float* __restrict__ out)
{
    extern __shared__ __align__(1024) char smem[];
    const uint32_t sq = smem_to_u32(smem);      // Q hi at sq, Q lo at sq+16384
    const uint32_t sb = sq + FQB;               // K/V stages
    const int tid = threadIdx.x, lane = tid & 31, warp = tid >> 5;
    const int qb = blockIdx.x * FQT;
    const int h  = blockIdx.y, b = blockIdx.z;
    const size_t gbase = ((size_t)(b * HH + h)) * SS * DH;
    const __nv_bfloat16* Qh_g = g_qh + gbase;
    const __nv_bfloat16* Ql_g = g_ql + gbase;
    const __nv_bfloat16* Kh_g = g_kh + gbase;
    const __nv_bfloat16* Kl_g = g_kl + gbase;
    const __half*        Vf_g = g_vf + gbase;

    int f_row[2], f_c[2];
    #pragma unroll
    for (int q = 0; q < 2; q++) {
        int id = q * 256 + tid;
        f_row[q] = id >> 3;
        f_c[q]   = id & 7;
    }

    // ---- prologue: group0 = Q + KV stage 0; group1 = KV stage 1 ----
    {
        #pragma unroll
        for (int q = 0; q < 4; q++) {
            int id = q * 256 + tid;            // 1024 chunks
            int row = id >> 3, c = id & 7;
            uint32_t dst = sq + row * 128 + ((c ^ (row & 7)) << 4);
            size_t src = (size_t)(qb + row) * DH + c * 8;
            CP_ASYNC_16(dst,         Qh_g + src);
            CP_ASYNC_16(dst + 16384, Ql_g + src);
        }
        #pragma unroll
        for (int q = 0; q < 2; q++) {
            int row = f_row[q], c = f_c[q];
            uint32_t o = row * 128 + ((c ^ (row & 7)) << 4);
            size_t src = (size_t)row * DH + c * 8;
            CP_ASYNC_16(sb +         o, Kh_g + src);
            CP_ASYNC_16(sb +  8192 + o, Kl_g + src);
            CP_ASYNC_16(sb + 16384 + o, Vf_g + src);
        }
        CP_ASYNC_COMMIT();
        #pragma unroll
        for (int q = 0; q < 2; q++) {
            int row = f_row[q], c = f_c[q];
            uint32_t o = row * 128 + ((c ^ (row & 7)) << 4);
            size_t src = (size_t)(FKT * DH) + (size_t)row * DH + c * 8;
            CP_ASYNC_16(sb + FST +         o, Kh_g + src);
            CP_ASYNC_16(sb + FST +  8192 + o, Kl_g + src);
            CP_ASYNC_16(sb + FST + 16384 + o, Vf_g + src);
        }
        CP_ASYNC_COMMIT();
    }

    float oacc[8][4];
    #pragma unroll
    for (int i = 0; i < 8; i++)
        #pragma unroll
        for (int j = 0; j < 4; j++) oacc[i][j] = 0.f;
    float m0r = -INFINITY, m1r = -INFINITY, l0 = 0.f, l1 = 0.f;

    for (int it = 0; it < FNIT; it++) {
        if (it + 1 < FNIT) CP_ASYNC_WAIT_1();  // stage it done; it+1 may fly
        else               CP_ASYNC_WAIT_ALL();
        __syncthreads();

        if (it + 2 < FNIT) {
            uint32_t buf = sb + ((it + 2) % 3) * FST;
            size_t kadd = (size_t)(it + 2) * FKT * DH;
            #pragma unroll
            for (int q = 0; q < 2; q++) {
                int row = f_row[q], c = f_c[q];
                uint32_t o = row * 128 + ((c ^ (row & 7)) << 4);
                size_t src = kadd + (size_t)row * DH + c * 8;
                CP_ASYNC_16(buf +         o, Kh_g + src);
                CP_ASYNC_16(buf +  8192 + o, Kl_g + src);
                CP_ASYNC_16(buf + 16384 + o, Vf_g + src);
            }
            CP_ASYNC_COMMIT();
        }

        const uint32_t buf = sb + (it % 3) * FST;
        const uint32_t kh = buf, kl = buf + 8192, vf = buf + 16384;

        // ---- S = Q K^T (3 split passes); Q frags reloaded from smem ----
        float sacc[8][4];
        #pragma unroll
        for (int i = 0; i < 8; i++)
            #pragma unroll
            for (int j = 0; j < 4; j++) sacc[i][j] = 0.f;

        #pragma unroll
        for (int ks = 0; ks < 4; ks++) {
            int qrow = warp * 16 + (lane & 15);
            int qchunk = 2 * ks + (lane >> 4);
            uint32_t qaddr = sq + qrow * 128 + ((qchunk ^ (qrow & 7)) << 4);
            uint32_t qh0, qh1, qh2, qh3, ql0, ql1, ql2, ql3;
            LDMATRIX_X4(qh0, qh1, qh2, qh3, qaddr);
            LDMATRIX_X4(ql0, ql1, ql2, ql3, qaddr + 16384);
            #pragma unroll
            for (int ntp = 0; ntp < 4; ntp++) {
                int row = ntp * 16 + ((lane >> 4) & 1) * 8 + (lane & 7);
                int chunk = 2 * ks + ((lane >> 3) & 1);
                uint32_t addr = kh + row * 128 + ((chunk ^ (row & 7)) << 4);
                uint32_t bh0, bh1, bh2, bh3, bl0, bl1, bl2, bl3;
                LDMATRIX_X4(bh0, bh1, bh2, bh3, addr);
                LDMATRIX_X4(bl0, bl1, bl2, bl3, addr + 8192);
                MMA_BF16(sacc[2*ntp],   qh0, qh1, qh2, qh3, bh0, bh1);
                MMA_BF16(sacc[2*ntp],   ql0, ql1, ql2, ql3, bh0, bh1);
                MMA_BF16(sacc[2*ntp],   qh0, qh1, qh2, qh3, bl0, bl1);
                MMA_BF16(sacc[2*ntp+1], qh0, qh1, qh2, qh3, bh2, bh3);
                MMA_BF16(sacc[2*ntp+1], ql0, ql1, ql2, ql3, bh2, bh3);
                MMA_BF16(sacc[2*ntp+1], qh0, qh1, qh2, qh3, bl2, bl3);
            }
        }

        // ---- online softmax, base 2; p in (0,1] -> fp16 pack ----
        float tm0 = -INFINITY, tm1 = -INFINITY;
        #pragma unroll
        for (int nt = 0; nt < 8; nt++) {
            tm0 = fmaxf(tm0, fmaxf(sacc[nt][0], sacc[nt][1]));
            tm1 = fmaxf(tm1, fmaxf(sacc[nt][2], sacc[nt][3]));
        }
        tm0 = fmaxf(tm0, __shfl_xor_sync(0xffffffffu, tm0, 1));
        tm0 = fmaxf(tm0, __shfl_xor_sync(0xffffffffu, tm0, 2));
        tm1 = fmaxf(tm1, __shfl_xor_sync(0xffffffffu, tm1, 1));
        tm1 = fmaxf(tm1, __shfl_xor_sync(0xffffffffu, tm1, 2));
        float mn0 = fmaxf(m0r, tm0), mn1 = fmaxf(m1r, tm1);
        float a0 = ex2f(m0r - mn0), a1 = ex2f(m1r - mn1);
        m0r = mn0; m1r = mn1;

        float rs0 = 0.f, rs1 = 0.f;
        uint32_t ph[4][4];
        #pragma unroll
        for (int nt = 0; nt < 8; nt++) {
            float p00 = ex2f(sacc[nt][0] - mn0);
            float p01 = ex2f(sacc[nt][1] - mn0);
            float p10 = ex2f(sacc[nt][2] - mn1);
            float p11 = ex2f(sacc[nt][3] - mn1);
            rs0 += p00 + p01; rs1 += p10 + p11;
            __half2 h0 = __floats2half2_rn(p00, p01);
            __half2 h1 = __floats2half2_rn(p10, p11);
            int ks = nt >> 1, half = (nt & 1) * 2;
            ph[ks][half]     = *(uint32_t*)&h0;
            ph[ks][half + 1] = *(uint32_t*)&h1;
        }
        // per-lane partial l (row reduce deferred; a row-uniform)
        l0 = l0 * a0 + rs0;
        l1 = l1 * a1 + rs1;
        #pragma unroll
        for (int nt = 0; nt < 8; nt++) {
            oacc[nt][0] *= a0; oacc[nt][1] *= a0;
            oacc[nt][2] *= a1; oacc[nt][3] *= a1;
        }

        // ---- O += P V, single fp16 pass; V via ldmatrix.trans ----
        #pragma unroll
        for (int ks = 0; ks < 4; ks++) {
            #pragma unroll
            for (int ntp = 0; ntp < 4; ntp++) {
                int row = ks * 16 + ((lane >> 3) & 1) * 8 + (lane & 7);
                int chunk = 2 * ntp + (lane >> 4);
                uint32_t addr = vf + row * 128 + ((chunk ^ (row & 7)) << 4);
                uint32_t b0, b1, b2, b3;
                LDMATRIX_X4_T(b0, b1, b2, b3, addr);
                MMA_F16(oacc[2*ntp],   ph[ks][0], ph[ks][1], ph[ks][2], ph[ks][3], b0, b1);
                MMA_F16(oacc[2*ntp+1], ph[ks][0], ph[ks][1], ph[ks][2], ph[ks][3], b2, b3);
            }
        }
        // top-of-iteration barrier of it+1 orders these reads before the
        // prefetch that overwrites this buffer (prefetch targets (it+2)%3,
        // last read at it-1, ordered by this iteration's barrier).
    }

    // ---- epilogue: reduce l across the 4-lane row group, store fp32 ----
    {
        l0 += __shfl_xor_sync(0xffffffffu, l0, 1);
        l0 += __shfl_xor_sync(0xffffffffu, l0, 2);
        l1 += __shfl_xor_sync(0xffffffffu, l1, 1);
        l1 += __shfl_xor_sync(0xffffffffu, l1, 2);
        const int r = lane >> 2, c2 = (lane & 3) * 2;
        float inv0 = 1.0f / l0, inv1 = 1.0f / l1;
        int row0 = qb + warp * 16 + r;
        size_t o0 = ((size_t)b * SS + row0) * DD + h * DH;
        size_t o1 = ((size_t)b * SS + row0 + 8) * DD + h * DH;
        #pragma unroll
        for (int nt = 0; nt < 8; nt++) {
            *(float2*)(out + o0 + nt * 8 + c2) =
                make_float2(oacc[nt][0] * inv0, oacc[nt][1] * inv0);
            *(float2*)(out + o1 + nt * 8 + c2) =
                make_float2(oacc[nt][2] * inv1, oacc[nt][3] * inv1);
        }
    }
}

// ---------------------------------------------------------------------------
extern "C" void kernel_launch(void* const* d_in, const int* in_sizes, int n_in,
                              void* d_out, int out_size) {
    const float* x  = (const float*)d_in[0];
    const float* Wq = (const float*)d_in[1];
    const float* bq = (const float*)d_in[2];
    const float* Wk = (const float*)d_in[3];
    const float* bk = (const float*)d_in[4];
    const float* Wv = (const float*)d_in[5];
    const float* bv = (const float*)d_in[6];
    float* out = (float*)d_out;

    split_x_kernel<<<M_TOTAL * DD / 256, 256>>>(x);
    split_w_kernel<<<dim3(DD/32, DD/32, 3), dim3(32, 8)>>>(Wq, Wk, Wv);

    cudaFuncSetAttribute(proj_mma_kernel,
                         cudaFuncAttributeMaxDynamicSharedMemorySize, PROJ_SMEM);
    proj_mma_kernel<<<dim3(N_TOTAL/128, M_TOTAL/128), 256, PROJ_SMEM>>>(bq, bk, bv);

    cudaFuncSetAttribute(flash_mma_kernel,
                         cudaFuncAttributeMaxDynamicSharedMemorySize, FLASH_SMEM);
    flash_mma_kernel<<<dim3(SS/FQT, HH, BB), 256, FLASH_SMEM>>>(out);
}

// round 11
// speedup vs baseline: 1.1212x; 1.0917x over previous
#include <cuda_runtime.h>
#include <cuda_bf16.h>
#include <cuda_fp16.h>
#include <math.h>
#include <cstdint>

#define BB 2
#define SS 2048
#define DD 1024
#define HH 16
#define DH 64
#define M_TOTAL (BB*SS)      // 4096
#define N_TOTAL (3*DD)       // 3072

// ---------------- device scratch (no cudaMalloc allowed) -------------------
__device__ __align__(16) __nv_bfloat16 g_xh[M_TOTAL*DD];
__device__ __align__(16) __nv_bfloat16 g_xl[M_TOTAL*DD];
__device__ __align__(16) __half        g_xf[M_TOTAL*DD];   // fp16 x (V proj)
__device__ __align__(16) __nv_bfloat16 g_wth[2*DD*DD];     // Wq^T, Wk^T hi
__device__ __align__(16) __nv_bfloat16 g_wtl[2*DD*DD];     // Wq^T, Wk^T lo
__device__ __align__(16) __half        g_wvf[DD*DD];       // Wv^T fp16
// projected Q/K bf16 hi/lo, V fp16, [B,H,S,DH]  (Q pre-scaled by log2(e))
__device__ __align__(16) __nv_bfloat16 g_qh[BB*HH*SS*DH];
__device__ __align__(16) __nv_bfloat16 g_ql[BB*HH*SS*DH];
__device__ __align__(16) __nv_bfloat16 g_kh[BB*HH*SS*DH];
__device__ __align__(16) __nv_bfloat16 g_kl[BB*HH*SS*DH];
__device__ __align__(16) __half        g_vf[BB*HH*SS*DH];

// ---------------- warp-mma helpers (plain sm_80+ PTX) ----------------------
__device__ __forceinline__ uint32_t smem_to_u32(const void* p) {
    uint32_t a;
    asm("{ .reg .u64 t; cvta.to.shared.u64 t, %1; cvt.u32.u64 %0, t; }"
        : "=r"(a) : "l"(p));
    return a;
}
__device__ __forceinline__ float ex2f(float x) {
    float y;
    asm("ex2.approx.f32 %0, %1;" : "=f"(y) : "f"(x));
    return y;
}

#define CP_ASYNC_16(dst, src) \
    asm volatile("cp.async.cg.shared.global [%0], [%1], 16;" :: "r"(dst), "l"(src))
#define CP_ASYNC_COMMIT() asm volatile("cp.async.commit_group;" ::: "memory")
#define CP_ASYNC_WAIT_ALL() asm volatile("cp.async.wait_group 0;" ::: "memory")
#define CP_ASYNC_WAIT_1()  asm volatile("cp.async.wait_group 1;" ::: "memory")

#define LDMATRIX_X4(r0, r1, r2, r3, addr) \
    asm volatile("ldmatrix.sync.aligned.m8n8.x4.shared.b16 {%0,%1,%2,%3}, [%4];" \
        : "=r"(r0), "=r"(r1), "=r"(r2), "=r"(r3) : "r"(addr))
#define LDMATRIX_X4_T(r0, r1, r2, r3, addr) \
    asm volatile("ldmatrix.sync.aligned.m8n8.x4.trans.shared.b16 {%0,%1,%2,%3}, [%4];" \
        : "=r"(r0), "=r"(r1), "=r"(r2), "=r"(r3) : "r"(addr))

#define MMA_BF16(cc, a0, a1, a2, a3, b0, b1) \
    asm volatile("mma.sync.aligned.m16n8k16.row.col.f32.bf16.bf16.f32 " \
        "{%0,%1,%2,%3}, {%4,%5,%6,%7}, {%8,%9}, {%0,%1,%2,%3};" \
        : "+f"((cc)[0]), "+f"((cc)[1]), "+f"((cc)[2]), "+f"((cc)[3]) \
        : "r"(a0), "r"(a1), "r"(a2), "r"(a3), "r"(b0), "r"(b1))

#define MMA_F16(cc, a0, a1, a2, a3, b0, b1) \
    asm volatile("mma.sync.aligned.m16n8k16.row.col.f32.f16.f16.f32 " \
        "{%0,%1,%2,%3}, {%4,%5,%6,%7}, {%8,%9}, {%0,%1,%2,%3};" \
        : "+f"((cc)[0]), "+f"((cc)[1]), "+f"((cc)[2]), "+f"((cc)[3]) \
        : "r"(a0), "r"(a1), "r"(a2), "r"(a3), "r"(b0), "r"(b1))

// ---------------------------------------------------------------------------
// Split kernels
// ---------------------------------------------------------------------------
__global__ void __launch_bounds__(256) split_x_kernel(const float* __restrict__ x) {
    int i = blockIdx.x * 256 + threadIdx.x;
    float v = x[i];
    __nv_bfloat16 hi = __float2bfloat16(v);
    g_xh[i] = hi;
    g_xl[i] = __float2bfloat16(v - __bfloat162float(hi));
    g_xf[i] = __float2half_rn(v);
}

__global__ void __launch_bounds__(256) split_w_kernel(
    const float* __restrict__ Wq, const float* __restrict__ Wk, const float* __restrict__ Wv)
{
    const float* W = (blockIdx.z == 0) ? Wq : (blockIdx.z == 1) ? Wk : Wv;
    __shared__ float t[32][33];
    int n0 = blockIdx.x * 32, k0 = blockIdx.y * 32;
    int tx = threadIdx.x, ty = threadIdx.y;   // block (32, 8)
    for (int r = ty; r < 32; r += 8)
        t[r][tx] = W[(size_t)(k0 + r) * DD + n0 + tx];
    __syncthreads();
    if (blockIdx.z < 2) {
        size_t base = (size_t)blockIdx.z * DD * DD;
        for (int r = ty; r < 32; r += 8) {
            float v = t[tx][r];
            __nv_bfloat16 hi = __float2bfloat16(v);
            size_t idx = base + (size_t)(n0 + r) * DD + k0 + tx;
            g_wth[idx] = hi;
            g_wtl[idx] = __float2bfloat16(v - __bfloat162float(hi));
        }
    } else {
        for (int r = ty; r < 32; r += 8) {
            size_t idx = (size_t)(n0 + r) * DD + k0 + tx;
            g_wvf[idx] = __float2half_rn(t[tx][r]);
        }
    }
}

// ---------------------------------------------------------------------------
// Projection via mma.sync. Q/K: 3-pass split-bf16 (logit accuracy).
// V: SINGLE fp16 pass (x_fp16 @ Wv_fp16, fp32 accum) -> 1/3 the MMAs; V feeds
// only the weighted average, which needs ~5e-4, and fp16 1-pass gives ~2e-4.
// 3-stage cp.async ring (wait_group 1).
// ---------------------------------------------------------------------------
#define BK 32
#define STAGE_BYTES 32768
#define PROJ_SMEM 98304                  // 3 stages; Cs(67.6KB) overlays

__global__ void __launch_bounds__(256, 2) proj_mma_kernel(
    const float* __restrict__ bq, const float* __restrict__ bk, const float* __restrict__ bv)
{
    extern __shared__ __align__(1024) char smem[];
    const uint32_t smem_base = smem_to_u32(smem);
    float* Cs = (float*)smem;

    const int tid  = threadIdx.x;
    const int lane = tid & 31;
    const int warp = tid >> 5;
    const int wm   = warp >> 2;
    const int wn   = warp & 3;

    const int ntile = blockIdx.x;
    const int mtile = blockIdx.y;
    const int wsel  = ntile >> 3;
    const int ncol0 = (ntile & 7) * 128;
    const int m0    = mtile * 128;

    int ldsw[2];
    size_t ldga[2], ldgb[2];
    #pragma unroll
    for (int q = 0; q < 2; q++) {
        int idx = q * 256 + tid;
        int row = idx >> 2, c = idx & 3;
        ldsw[q]  = row * 64 + ((c ^ ((row >> 1) & 3)) << 4);
        ldga[q]  = (size_t)(m0 + row) * DD + c * 8;
        ldgb[q]  = (size_t)(ncol0 + row) * DD + c * 8;
    }

    int rA[4], gA[4];
    #pragma unroll
    for (int mt = 0; mt < 4; mt++) {
        rA[mt] = wm * 64 + mt * 16 + (lane & 15);
        gA[mt] = (rA[mt] >> 1) & 3;
    }
    const int khalfA = lane >> 4;

    float acc[4][4][4];
    #pragma unroll
    for (int i = 0; i < 4; i++)
        #pragma unroll
        for (int j = 0; j < 4; j++)
            #pragma unroll
            for (int r = 0; r < 4; r++) acc[i][j][r] = 0.f;

    const int NKC = DD / BK;              // 32

    if (wsel < 2) {
        // ================= Q/K path: 3-pass split-bf16 =================
        const __nv_bfloat16* Ah_g = g_xh;
        const __nv_bfloat16* Al_g = g_xl;
        const __nv_bfloat16* Bh_g = g_wth + (size_t)wsel * DD * DD;
        const __nv_bfloat16* Bl_g = g_wtl + (size_t)wsel * DD * DD;

        #pragma unroll
        for (int ps = 0; ps < 2; ps++) {
            uint32_t sb = smem_base + ps * STAGE_BYTES;
            size_t koff = (size_t)ps * BK;
            #pragma unroll
            for (int q = 0; q < 2; q++) {
                CP_ASYNC_16(sb +         ldsw[q], Ah_g + ldga[q] + koff);
                CP_ASYNC_16(sb +  8192 + ldsw[q], Al_g + ldga[q] + koff);
                CP_ASYNC_16(sb + 16384 + ldsw[q], Bh_g + ldgb[q] + koff);
                CP_ASYNC_16(sb + 24576 + ldsw[q], Bl_g + ldgb[q] + koff);
            }
            CP_ASYNC_COMMIT();
        }

        for (int kc = 0; kc < NKC; kc++) {
            if (kc + 1 < NKC) CP_ASYNC_WAIT_1();
            else              CP_ASYNC_WAIT_ALL();
            __syncthreads();

            if (kc + 2 < NKC) {
                uint32_t sb = smem_base + ((kc + 2) % 3) * STAGE_BYTES;
                size_t koff = (size_t)(kc + 2) * BK;
                #pragma unroll
                for (int q = 0; q < 2; q++) {
                    CP_ASYNC_16(sb +         ldsw[q], Ah_g + ldga[q] + koff);
                    CP_ASYNC_16(sb +  8192 + ldsw[q], Al_g + ldga[q] + koff);
                    CP_ASYNC_16(sb + 16384 + ldsw[q], Bh_g + ldgb[q] + koff);
                    CP_ASYNC_16(sb + 24576 + ldsw[q], Bl_g + ldgb[q] + koff);
                }
                CP_ASYNC_COMMIT();
            }

            const uint32_t sb = smem_base + (kc % 3) * STAGE_BYTES;
            const uint32_t ah = sb, al = sb + 8192, bh = sb + 16384, bl = sb + 24576;

            #pragma unroll
            for (int kf = 0; kf < 2; kf++) {
                const int cA = kf * 2 + khalfA;

                uint32_t B_h[4][2], B_l[4][2];
                #pragma unroll
                for (int ntp = 0; ntp < 2; ntp++) {
                    int row = wn * 32 + ntp * 16 + ((lane >> 4) & 1) * 8 + (lane & 7);
                    int chunk = kf * 2 + ((lane >> 3) & 1);
                    uint32_t boff = row * 64 + (((chunk ^ ((row >> 1) & 3))) << 4);
                    LDMATRIX_X4(B_h[2*ntp][0], B_h[2*ntp][1],
                                B_h[2*ntp+1][0], B_h[2*ntp+1][1], bh + boff);
                    LDMATRIX_X4(B_l[2*ntp][0], B_l[2*ntp][1],
                                B_l[2*ntp+1][0], B_l[2*ntp+1][1], bl + boff);
                }
                uint32_t A[4][4];
                #pragma unroll
                for (int mt = 0; mt < 4; mt++) {
                    uint32_t aoff = rA[mt] * 64 + (((cA ^ gA[mt])) << 4);
                    LDMATRIX_X4(A[mt][0], A[mt][1], A[mt][2], A[mt][3], ah + aoff);
                }
                #pragma unroll
                for (int mt = 0; mt < 4; mt++)
                    #pragma unroll
                    for (int nt = 0; nt < 4; nt++) {
                        MMA_BF16(acc[mt][nt], A[mt][0], A[mt][1], A[mt][2], A[mt][3],
                                 B_h[nt][0], B_h[nt][1]);
                        MMA_BF16(acc[mt][nt], A[mt][0], A[mt][1], A[mt][2], A[mt][3],
                                 B_l[nt][0], B_l[nt][1]);
                    }
                #pragma unroll
                for (int mt = 0; mt < 4; mt++) {
                    uint32_t aoff = rA[mt] * 64 + (((cA ^ gA[mt])) << 4);
                    LDMATRIX_X4(A[mt][0], A[mt][1], A[mt][2], A[mt][3], al + aoff);
                }
                #pragma unroll
                for (int mt = 0; mt < 4; mt++)
                    #pragma unroll
                    for (int nt = 0; nt < 4; nt++)
                        MMA_BF16(acc[mt][nt], A[mt][0], A[mt][1], A[mt][2], A[mt][3],
                                 B_h[nt][0], B_h[nt][1]);
            }
        }
    } else {
        // ================= V path: 1-pass fp16 =================
        const __half* Af_g = g_xf;
        const __half* Bf_g = g_wvf;

        #pragma unroll
        for (int ps = 0; ps < 2; ps++) {
            uint32_t sb = smem_base + ps * STAGE_BYTES;
            size_t koff = (size_t)ps * BK;
            #pragma unroll
            for (int q = 0; q < 2; q++) {
                CP_ASYNC_16(sb +         ldsw[q], Af_g + ldga[q] + koff);
                CP_ASYNC_16(sb + 16384 + ldsw[q], Bf_g + ldgb[q] + koff);
            }
            CP_ASYNC_COMMIT();
        }

        for (int kc = 0; kc < NKC; kc++) {
            if (kc + 1 < NKC) CP_ASYNC_WAIT_1();
            else              CP_ASYNC_WAIT_ALL();
            __syncthreads();

            if (kc + 2 < NKC) {
                uint32_t sb = smem_base + ((kc + 2) % 3) * STAGE_BYTES;
                size_t koff = (size_t)(kc + 2) * BK;
                #pragma unroll
                for (int q = 0; q < 2; q++) {
                    CP_ASYNC_16(sb +         ldsw[q], Af_g + ldga[q] + koff);
                    CP_ASYNC_16(sb + 16384 + ldsw[q], Bf_g + ldgb[q] + koff);
                }
                CP_ASYNC_COMMIT();
            }

            const uint32_t sb = smem_base + (kc % 3) * STAGE_BYTES;
            const uint32_t af = sb, bf = sb + 16384;

            #pragma unroll
            for (int kf = 0; kf < 2; kf++) {
                const int cA = kf * 2 + khalfA;

                uint32_t B_f[4][2];
                #pragma unroll
                for (int ntp = 0; ntp < 2; ntp++) {
                    int row = wn * 32 + ntp * 16 + ((lane >> 4) & 1) * 8 + (lane & 7);
                    int chunk = kf * 2 + ((lane >> 3) & 1);
                    uint32_t boff = row * 64 + (((chunk ^ ((row >> 1) & 3))) << 4);
                    LDMATRIX_X4(B_f[2*ntp][0], B_f[2*ntp][1],
                                B_f[2*ntp+1][0], B_f[2*ntp+1][1], bf + boff);
                }
                uint32_t A[4][4];
                #pragma unroll
                for (int mt = 0; mt < 4; mt++) {
                    uint32_t aoff = rA[mt] * 64 + (((cA ^ gA[mt])) << 4);
                    LDMATRIX_X4(A[mt][0], A[mt][1], A[mt][2], A[mt][3], af + aoff);
                }
                #pragma unroll
                for (int mt = 0; mt < 4; mt++)
                    #pragma unroll
                    for (int nt = 0; nt < 4; nt++)
                        MMA_F16(acc[mt][nt], A[mt][0], A[mt][1], A[mt][2], A[mt][3],
                                B_f[nt][0], B_f[nt][1]);
            }
        }
    }
    __syncthreads();

    // ---- epilogue: bias (+GELU +log2e on Q), stage fp32, then store ----
    const float* bias = (wsel == 0) ? bq : (wsel == 1) ? bk : bv;

    const int fr = lane >> 2;
    const int fc = (lane & 3) * 2;
    #pragma unroll
    for (int mt = 0; mt < 4; mt++) {
        #pragma unroll
        for (int nt = 0; nt < 4; nt++) {
            int row0 = wm * 64 + mt * 16 + fr;
            int col0 = wn * 32 + nt * 8 + fc;
            float b0 = bias[ncol0 + col0], b1 = bias[ncol0 + col0 + 1];
            #pragma unroll
            for (int half = 0; half < 2; half++) {
                int r = row0 + half * 8;
                float v0 = acc[mt][nt][half * 2 + 0] + b0;
                float v1 = acc[mt][nt][half * 2 + 1] + b1;
                if (wsel == 0) {
                    v0 = 0.5f * v0 * (1.0f + erff(v0 * 0.70710678118654752f));
                    v1 = 0.5f * v1 * (1.0f + erff(v1 * 0.70710678118654752f));
                    v0 *= 1.44269504088896340736f;   // log2(e): softmax in base-2
                    v1 *= 1.44269504088896340736f;
                }
                Cs[r * 132 + col0]     = v0;
                Cs[r * 132 + col0 + 1] = v1;
            }
        }
    }
    __syncthreads();

    const int b  = m0 >> 11;
    const int s0 = m0 & 2047;
    if (wsel < 2) {
        __nv_bfloat16* dsth = (wsel == 0) ? g_qh : g_kh;
        __nv_bfloat16* dstl = (wsel == 0) ? g_ql : g_kl;
        #pragma unroll
        for (int hb = 0; hb < 2; hb++) {
            int h = (ncol0 >> 6) + hb;
            size_t base = (((size_t)(b * HH + h)) * SS + s0) * DH;
            for (int i = tid; i < 128 * 64; i += 256) {
                int s = i >> 6, dh = i & 63;
                float v = Cs[s * 132 + hb * 64 + dh];
                __nv_bfloat16 hi = __float2bfloat16(v);
                dsth[base + (size_t)s * DH + dh] = hi;
                dstl[base + (size_t)s * DH + dh] =
                    __float2bfloat16(v - __bfloat162float(hi));
            }
        }
    } else {
        #pragma unroll
        for (int hb = 0; hb < 2; hb++) {
            int h = (ncol0 >> 6) + hb;
            size_t base = (((size_t)(b * HH + h)) * SS + s0) * DH;
            for (int i = tid; i < 128 * 64; i += 256) {
                int s = i >> 6, dh = i & 63;
                g_vf[base + (size_t)s * DH + dh] =
                    __float2half_rn(Cs[s * 132 + hb * 64 + dh]);
            }
        }
    }
}

// ---------------------------------------------------------------------------
// Flash attention via mma.sync (R8 config — best measured: 2-stage ring,
// Q in smem reloaded per ks, online max base-2, fp16 P, single fp16 PV).
// ---------------------------------------------------------------------------
#define FQT 128
#define FKT 64
#define FNIT (SS/FKT)
#define FQB 32768                       // Q region: hi 16KB + lo 16KB
#define FST 24576                       // K/V stage stride (Kh|Kl|Vf x 8KB)
#define FLASH_SMEM (FQB + 2*FST)        // 81920

__global__ void __launch_bounds__(256, 2) flash_mma_kernel(float* __restrict__ out)
{
    extern __shared__ __align__(1024) char smem[];
    const uint32_t sq = smem_to_u32(smem);      // Q hi at sq, Q lo at sq+16384
    const uint32_t sb = sq + FQB;               // K/V stages
    const int tid = threadIdx.x, lane = tid & 31, warp = tid >> 5;
    const int qb = blockIdx.x * FQT;
    const int h  = blockIdx.y, b = blockIdx.z;
    const size_t gbase = ((size_t)(b * HH + h)) * SS * DH;
    const __nv_bfloat16* Qh_g = g_qh + gbase;
    const __nv_bfloat16* Ql_g = g_ql + gbase;
    const __nv_bfloat16* Kh_g = g_kh + gbase;
    const __nv_bfloat16* Kl_g = g_kl + gbase;
    const __half*        Vf_g = g_vf + gbase;

    int f_row[2], f_c[2];
    #pragma unroll
    for (int q = 0; q < 2; q++) {
        int id = q * 256 + tid;
        f_row[q] = id >> 3;
        f_c[q]   = id & 7;
    }

    // ---- prologue: stage Q (resident) + KV iter 0, single commit group ----
    {
        #pragma unroll
        for (int q = 0; q < 4; q++) {
            int id = q * 256 + tid;            // 1024 chunks
            int row = id >> 3, c = id & 7;
            uint32_t dst = sq + row * 128 + ((c ^ (row & 7)) << 4);
            size_t src = (size_t)(qb + row) * DH + c * 8;
            CP_ASYNC_16(dst,         Qh_g + src);
            CP_ASYNC_16(dst + 16384, Ql_g + src);
        }
        #pragma unroll
        for (int q = 0; q < 2; q++) {
            int row = f_row[q], c = f_c[q];
            uint32_t o = row * 128 + ((c ^ (row & 7)) << 4);
            size_t src = (size_t)row * DH + c * 8;
            CP_ASYNC_16(sb +         o, Kh_g + src);
            CP_ASYNC_16(sb +  8192 + o, Kl_g + src);
            CP_ASYNC_16(sb + 16384 + o, Vf_g + src);
        }
        CP_ASYNC_COMMIT();
    }

    float oacc[8][4];
    #pragma unroll
    for (int i = 0; i < 8; i++)
        #pragma unroll
        for (int j = 0; j < 4; j++) oacc[i][j] = 0.f;
    float m0r = -INFINITY, m1r = -INFINITY, l0 = 0.f, l1 = 0.f;

    for (int it = 0; it < FNIT; it++) {
        CP_ASYNC_WAIT_ALL();
        __syncthreads();

        if (it + 1 < FNIT) {
            uint32_t buf = sb + ((it + 1) & 1) * FST;
            size_t kadd = (size_t)(it + 1) * FKT * DH;
            #pragma unroll
            for (int q = 0; q < 2; q++) {
                int row = f_row[q], c = f_c[q];
                uint32_t o = row * 128 + ((c ^ (row & 7)) << 4);
                size_t src = kadd + (size_t)row * DH + c * 8;
                CP_ASYNC_16(buf +         o, Kh_g + src);
                CP_ASYNC_16(buf +  8192 + o, Kl_g + src);
                CP_ASYNC_16(buf + 16384 + o, Vf_g + src);
            }
            CP_ASYNC_COMMIT();
        }

        const uint32_t buf = sb + (it & 1) * FST;
        const uint32_t kh = buf, kl = buf + 8192, vf = buf + 16384;

        // ---- S = Q K^T (3 split passes); Q frags reloaded from smem ----
        float sacc[8][4];
        #pragma unroll
        for (int i = 0; i < 8; i++)
            #pragma unroll
            for (int j = 0; j < 4; j++) sacc[i][j] = 0.f;

        #pragma unroll
        for (int ks = 0; ks < 4; ks++) {
            int qrow = warp * 16 + (lane & 15);
            int qchunk = 2 * ks + (lane >> 4);
            uint32_t qaddr = sq + qrow * 128 + ((qchunk ^ (qrow & 7)) << 4);
            uint32_t qh0, qh1, qh2, qh3, ql0, ql1, ql2, ql3;
            LDMATRIX_X4(qh0, qh1, qh2, qh3, qaddr);
            LDMATRIX_X4(ql0, ql1, ql2, ql3, qaddr + 16384);
            #pragma unroll
            for (int ntp = 0; ntp < 4; ntp++) {
                int row = ntp * 16 + ((lane >> 4) & 1) * 8 + (lane & 7);
                int chunk = 2 * ks + ((lane >> 3) & 1);
                uint32_t addr = kh + row * 128 + ((chunk ^ (row & 7)) << 4);
                uint32_t bh0, bh1, bh2, bh3, bl0, bl1, bl2, bl3;
                LDMATRIX_X4(bh0, bh1, bh2, bh3, addr);
                LDMATRIX_X4(bl0, bl1, bl2, bl3, addr + 8192);
                MMA_BF16(sacc[2*ntp],   qh0, qh1, qh2, qh3, bh0, bh1);
                MMA_BF16(sacc[2*ntp],   ql0, ql1, ql2, ql3, bh0, bh1);
                MMA_BF16(sacc[2*ntp],   qh0, qh1, qh2, qh3, bl0, bl1);
                MMA_BF16(sacc[2*ntp+1], qh0, qh1, qh2, qh3, bh2, bh3);
                MMA_BF16(sacc[2*ntp+1], ql0, ql1, ql2, ql3, bh2, bh3);
                MMA_BF16(sacc[2*ntp+1], qh0, qh1, qh2, qh3, bl2, bl3);
            }
        }

        // ---- online softmax, base 2; p in (0,1] -> fp16 pack ----
        float tm0 = -INFINITY, tm1 = -INFINITY;
        #pragma unroll
        for (int nt = 0; nt < 8; nt++) {
            tm0 = fmaxf(tm0, fmaxf(sacc[nt][0], sacc[nt][1]));
            tm1 = fmaxf(tm1, fmaxf(sacc[nt][2], sacc[nt][3]));
        }
        tm0 = fmaxf(tm0, __shfl_xor_sync(0xffffffffu, tm0, 1));
        tm0 = fmaxf(tm0, __shfl_xor_sync(0xffffffffu, tm0, 2));
        tm1 = fmaxf(tm1, __shfl_xor_sync(0xffffffffu, tm1, 1));
        tm1 = fmaxf(tm1, __shfl_xor_sync(0xffffffffu, tm1, 2));
        float mn0 = fmaxf(m0r, tm0), mn1 = fmaxf(m1r, tm1);
        float a0 = ex2f(m0r - mn0), a1 = ex2f(m1r - mn1);
        m0r = mn0; m1r = mn1;

        float rs0 = 0.f, rs1 = 0.f;
        uint32_t ph[4][4];
        #pragma unroll
        for (int nt = 0; nt < 8; nt++) {
            float p00 = ex2f(sacc[nt][0] - mn0);
            float p01 = ex2f(sacc[nt][1] - mn0);
            float p10 = ex2f(sacc[nt][2] - mn1);
            float p11 = ex2f(sacc[nt][3] - mn1);
            rs0 += p00 + p01; rs1 += p10 + p11;
            __half2 h0 = __floats2half2_rn(p00, p01);
            __half2 h1 = __floats2half2_rn(p10, p11);
            int ks = nt >> 1, half = (nt & 1) * 2;
            ph[ks][half]     = *(uint32_t*)&h0;
            ph[ks][half + 1] = *(uint32_t*)&h1;
        }
        // per-lane partial l (row reduce deferred; a row-uniform)
        l0 = l0 * a0 + rs0;
        l1 = l1 * a1 + rs1;
        #pragma unroll
        for (int nt = 0; nt < 8; nt++) {
            oacc[nt][0] *= a0; oacc[nt][1] *= a0;
            oacc[nt][2] *= a1; oacc[nt][3] *= a1;
        }

        // ---- O += P V, single fp16 pass; V via ldmatrix.trans ----
        #pragma unroll
        for (int ks = 0; ks < 4; ks++) {
            #pragma unroll
            for (int ntp = 0; ntp < 4; ntp++) {
                int row = ks * 16 + ((lane >> 3) & 1) * 8 + (lane & 7);
                int chunk = 2 * ntp + (lane >> 4);
                uint32_t addr = vf + row * 128 + ((chunk ^ (row & 7)) << 4);
                uint32_t b0, b1, b2, b3;
                LDMATRIX_X4_T(b0, b1, b2, b3, addr);
                MMA_F16(oacc[2*ntp],   ph[ks][0], ph[ks][1], ph[ks][2], ph[ks][3], b0, b1);
                MMA_F16(oacc[2*ntp+1], ph[ks][0], ph[ks][1], ph[ks][2], ph[ks][3], b2, b3);
            }
        }
        // top-of-iteration barrier of it+1 orders these reads before the
        // prefetch that overwrites this buffer.
    }

    // ---- epilogue: reduce l across the 4-lane row group, store fp32 ----
    {
        l0 += __shfl_xor_sync(0xffffffffu, l0, 1);
        l0 += __shfl_xor_sync(0xffffffffu, l0, 2);
        l1 += __shfl_xor_sync(0xffffffffu, l1, 1);
        l1 += __shfl_xor_sync(0xffffffffu, l1, 2);
        const int r = lane >> 2, c2 = (lane & 3) * 2;
        float inv0 = 1.0f / l0, inv1 = 1.0f / l1;
        int row0 = qb + warp * 16 + r;
        size_t o0 = ((size_t)b * SS + row0) * DD + h * DH;
        size_t o1 = ((size_t)b * SS + row0 + 8) * DD + h * DH;
        #pragma unroll
        for (int nt = 0; nt < 8; nt++) {
            *(float2*)(out + o0 + nt * 8 + c2) =
                make_float2(oacc[nt][0] * inv0, oacc[nt][1] * inv0);
            *(float2*)(out + o1 + nt * 8 + c2) =
                make_float2(oacc[nt][2] * inv1, oacc[nt][3] * inv1);
        }
    }
}

// ---------------------------------------------------------------------------
extern "C" void kernel_launch(void* const* d_in, const int* in_sizes, int n_in,
                              void* d_out, int out_size) {
    const float* x  = (const float*)d_in[0];
    const float* Wq = (const float*)d_in[1];
    const float* bq = (const float*)d_in[2];
    const float* Wk = (const float*)d_in[3];
    const float* bk = (const float*)d_in[4];
    const float* Wv = (const float*)d_in[5];
    const float* bv = (const float*)d_in[6];
    float* out = (float*)d_out;

    split_x_kernel<<<M_TOTAL * DD / 256, 256>>>(x);
    split_w_kernel<<<dim3(DD/32, DD/32, 3), dim3(32, 8)>>>(Wq, Wk, Wv);

    cudaFuncSetAttribute(proj_mma_kernel,
                         cudaFuncAttributeMaxDynamicSharedMemorySize, PROJ_SMEM);
    proj_mma_kernel<<<dim3(N_TOTAL/128, M_TOTAL/128), 256, PROJ_SMEM>>>(bq, bk, bv);

    cudaFuncSetAttribute(flash_mma_kernel,
                         cudaFuncAttributeMaxDynamicSharedMemorySize, FLASH_SMEM);
    flash_mma_kernel<<<dim3(SS/FQT, HH, BB), 256, FLASH_SMEM>>>(out);
}

// round 12
// speedup vs baseline: 1.1507x; 1.0264x over previous
#include <cuda_runtime.h>
#include <cuda_bf16.h>
#include <cuda_fp16.h>
#include <math.h>
#include <cstdint>

#define BB 2
#define SS 2048
#define DD 1024
#define HH 16
#define DH 64
#define M_TOTAL (BB*SS)      // 4096
#define N_TOTAL (3*DD)       // 3072

// ---------------- device scratch (no cudaMalloc allowed) -------------------
__device__ __align__(16) __nv_bfloat16 g_xh[M_TOTAL*DD];
__device__ __align__(16) __nv_bfloat16 g_xl[M_TOTAL*DD];
__device__ __align__(16) __half        g_xf[M_TOTAL*DD];   // fp16 x (V proj)
__device__ __align__(16) __nv_bfloat16 g_wth[2*DD*DD];     // Wq^T, Wk^T hi
__device__ __align__(16) __nv_bfloat16 g_wtl[2*DD*DD];     // Wq^T, Wk^T lo
__device__ __align__(16) __half        g_wvf[DD*DD];       // Wv^T fp16
// projected Q/K bf16 hi/lo, V fp16, [B,H,S,DH]  (Q pre-scaled by log2(e))
__device__ __align__(16) __nv_bfloat16 g_qh[BB*HH*SS*DH];
__device__ __align__(16) __nv_bfloat16 g_ql[BB*HH*SS*DH];
__device__ __align__(16) __nv_bfloat16 g_kh[BB*HH*SS*DH];
__device__ __align__(16) __nv_bfloat16 g_kl[BB*HH*SS*DH];
__device__ __align__(16) __half        g_vf[BB*HH*SS*DH];

// ---------------- warp-mma helpers (plain sm_80+ PTX) ----------------------
__device__ __forceinline__ uint32_t smem_to_u32(const void* p) {
    uint32_t a;
    asm("{ .reg .u64 t; cvta.to.shared.u64 t, %1; cvt.u32.u64 %0, t; }"
        : "=r"(a) : "l"(p));
    return a;
}
__device__ __forceinline__ float ex2f(float x) {
    float y;
    asm("ex2.approx.f32 %0, %1;" : "=f"(y) : "f"(x));
    return y;
}

#define CP_ASYNC_16(dst, src) \
    asm volatile("cp.async.cg.shared.global [%0], [%1], 16;" :: "r"(dst), "l"(src))
#define CP_ASYNC_COMMIT() asm volatile("cp.async.commit_group;" ::: "memory")
#define CP_ASYNC_WAIT_ALL() asm volatile("cp.async.wait_group 0;" ::: "memory")
#define CP_ASYNC_WAIT_1()  asm volatile("cp.async.wait_group 1;" ::: "memory")

#define LDMATRIX_X4(r0, r1, r2, r3, addr) \
    asm volatile("ldmatrix.sync.aligned.m8n8.x4.shared.b16 {%0,%1,%2,%3}, [%4];" \
        : "=r"(r0), "=r"(r1), "=r"(r2), "=r"(r3) : "r"(addr))
#define LDMATRIX_X4_T(r0, r1, r2, r3, addr) \
    asm volatile("ldmatrix.sync.aligned.m8n8.x4.trans.shared.b16 {%0,%1,%2,%3}, [%4];" \
        : "=r"(r0), "=r"(r1), "=r"(r2), "=r"(r3) : "r"(addr))

#define MMA_BF16(cc, a0, a1, a2, a3, b0, b1) \
    asm volatile("mma.sync.aligned.m16n8k16.row.col.f32.bf16.bf16.f32 " \
        "{%0,%1,%2,%3}, {%4,%5,%6,%7}, {%8,%9}, {%0,%1,%2,%3};" \
        : "+f"((cc)[0]), "+f"((cc)[1]), "+f"((cc)[2]), "+f"((cc)[3]) \
        : "r"(a0), "r"(a1), "r"(a2), "r"(a3), "r"(b0), "r"(b1))

#define MMA_F16(cc, a0, a1, a2, a3, b0, b1) \
    asm volatile("mma.sync.aligned.m16n8k16.row.col.f32.f16.f16.f32 " \
        "{%0,%1,%2,%3}, {%4,%5,%6,%7}, {%8,%9}, {%0,%1,%2,%3};" \
        : "+f"((cc)[0]), "+f"((cc)[1]), "+f"((cc)[2]), "+f"((cc)[3]) \
        : "r"(a0), "r"(a1), "r"(a2), "r"(a3), "r"(b0), "r"(b1))

// ---------------------------------------------------------------------------
// Split kernels
// ---------------------------------------------------------------------------
__global__ void __launch_bounds__(256) split_x_kernel(const float* __restrict__ x) {
    int i = blockIdx.x * 256 + threadIdx.x;
    float v = x[i];
    __nv_bfloat16 hi = __float2bfloat16(v);
    g_xh[i] = hi;
    g_xl[i] = __float2bfloat16(v - __bfloat162float(hi));
    g_xf[i] = __float2half_rn(v);
}

__global__ void __launch_bounds__(256) split_w_kernel(
    const float* __restrict__ Wq, const float* __restrict__ Wk, const float* __restrict__ Wv)
{
    const float* W = (blockIdx.z == 0) ? Wq : (blockIdx.z == 1) ? Wk : Wv;
    __shared__ float t[32][33];
    int n0 = blockIdx.x * 32, k0 = blockIdx.y * 32;
    int tx = threadIdx.x, ty = threadIdx.y;   // block (32, 8)
    for (int r = ty; r < 32; r += 8)
        t[r][tx] = W[(size_t)(k0 + r) * DD + n0 + tx];
    __syncthreads();
    if (blockIdx.z < 2) {
        size_t base = (size_t)blockIdx.z * DD * DD;
        for (int r = ty; r < 32; r += 8) {
            float v = t[tx][r];
            __nv_bfloat16 hi = __float2bfloat16(v);
            size_t idx = base + (size_t)(n0 + r) * DD + k0 + tx;
            g_wth[idx] = hi;
            g_wtl[idx] = __float2bfloat16(v - __bfloat162float(hi));
        }
    } else {
        for (int r = ty; r < 32; r += 8) {
            size_t idx = (size_t)(n0 + r) * DD + k0 + tx;
            g_wvf[idx] = __float2half_rn(t[tx][r]);
        }
    }
}

// ---------------------------------------------------------------------------
// Projection via mma.sync (R11 config, unchanged). Q/K: 3-pass split-bf16;
// V: single fp16 pass. 3-stage cp.async ring.
// ---------------------------------------------------------------------------
#define BK 32
#define STAGE_BYTES 32768
#define PROJ_SMEM 98304                  // 3 stages; Cs(67.6KB) overlays

__global__ void __launch_bounds__(256, 2) proj_mma_kernel(
    const float* __restrict__ bq, const float* __restrict__ bk, const float* __restrict__ bv)
{
    extern __shared__ __align__(1024) char smem[];
    const uint32_t smem_base = smem_to_u32(smem);
    float* Cs = (float*)smem;

    const int tid  = threadIdx.x;
    const int lane = tid & 31;
    const int warp = tid >> 5;
    const int wm   = warp >> 2;
    const int wn   = warp & 3;

    const int ntile = blockIdx.x;
    const int mtile = blockIdx.y;
    const int wsel  = ntile >> 3;
    const int ncol0 = (ntile & 7) * 128;
    const int m0    = mtile * 128;

    int ldsw[2];
    size_t ldga[2], ldgb[2];
    #pragma unroll
    for (int q = 0; q < 2; q++) {
        int idx = q * 256 + tid;
        int row = idx >> 2, c = idx & 3;
        ldsw[q]  = row * 64 + ((c ^ ((row >> 1) & 3)) << 4);
        ldga[q]  = (size_t)(m0 + row) * DD + c * 8;
        ldgb[q]  = (size_t)(ncol0 + row) * DD + c * 8;
    }

    int rA[4], gA[4];
    #pragma unroll
    for (int mt = 0; mt < 4; mt++) {
        rA[mt] = wm * 64 + mt * 16 + (lane & 15);
        gA[mt] = (rA[mt] >> 1) & 3;
    }
    const int khalfA = lane >> 4;

    float acc[4][4][4];
    #pragma unroll
    for (int i = 0; i < 4; i++)
        #pragma unroll
        for (int j = 0; j < 4; j++)
            #pragma unroll
            for (int r = 0; r < 4; r++) acc[i][j][r] = 0.f;

    const int NKC = DD / BK;              // 32

    if (wsel < 2) {
        const __nv_bfloat16* Ah_g = g_xh;
        const __nv_bfloat16* Al_g = g_xl;
        const __nv_bfloat16* Bh_g = g_wth + (size_t)wsel * DD * DD;
        const __nv_bfloat16* Bl_g = g_wtl + (size_t)wsel * DD * DD;

        #pragma unroll
        for (int ps = 0; ps < 2; ps++) {
            uint32_t sb = smem_base + ps * STAGE_BYTES;
            size_t koff = (size_t)ps * BK;
            #pragma unroll
            for (int q = 0; q < 2; q++) {
                CP_ASYNC_16(sb +         ldsw[q], Ah_g + ldga[q] + koff);
                CP_ASYNC_16(sb +  8192 + ldsw[q], Al_g + ldga[q] + koff);
                CP_ASYNC_16(sb + 16384 + ldsw[q], Bh_g + ldgb[q] + koff);
                CP_ASYNC_16(sb + 24576 + ldsw[q], Bl_g + ldgb[q] + koff);
            }
            CP_ASYNC_COMMIT();
        }

        for (int kc = 0; kc < NKC; kc++) {
            if (kc + 1 < NKC) CP_ASYNC_WAIT_1();
            else              CP_ASYNC_WAIT_ALL();
            __syncthreads();

            if (kc + 2 < NKC) {
                uint32_t sb = smem_base + ((kc + 2) % 3) * STAGE_BYTES;
                size_t koff = (size_t)(kc + 2) * BK;
                #pragma unroll
                for (int q = 0; q < 2; q++) {
                    CP_ASYNC_16(sb +         ldsw[q], Ah_g + ldga[q] + koff);
                    CP_ASYNC_16(sb +  8192 + ldsw[q], Al_g + ldga[q] + koff);
                    CP_ASYNC_16(sb + 16384 + ldsw[q], Bh_g + ldgb[q] + koff);
                    CP_ASYNC_16(sb + 24576 + ldsw[q], Bl_g + ldgb[q] + koff);
                }
                CP_ASYNC_COMMIT();
            }

            const uint32_t sb = smem_base + (kc % 3) * STAGE_BYTES;
            const uint32_t ah = sb, al = sb + 8192, bh = sb + 16384, bl = sb + 24576;

            #pragma unroll
            for (int kf = 0; kf < 2; kf++) {
                const int cA = kf * 2 + khalfA;

                uint32_t B_h[4][2], B_l[4][2];
                #pragma unroll
                for (int ntp = 0; ntp < 2; ntp++) {
                    int row = wn * 32 + ntp * 16 + ((lane >> 4) & 1) * 8 + (lane & 7);
                    int chunk = kf * 2 + ((lane >> 3) & 1);
                    uint32_t boff = row * 64 + (((chunk ^ ((row >> 1) & 3))) << 4);
                    LDMATRIX_X4(B_h[2*ntp][0], B_h[2*ntp][1],
                                B_h[2*ntp+1][0], B_h[2*ntp+1][1], bh + boff);
                    LDMATRIX_X4(B_l[2*ntp][0], B_l[2*ntp][1],
                                B_l[2*ntp+1][0], B_l[2*ntp+1][1], bl + boff);
                }
                uint32_t A[4][4];
                #pragma unroll
                for (int mt = 0; mt < 4; mt++) {
                    uint32_t aoff = rA[mt] * 64 + (((cA ^ gA[mt])) << 4);
                    LDMATRIX_X4(A[mt][0], A[mt][1], A[mt][2], A[mt][3], ah + aoff);
                }
                #pragma unroll
                for (int mt = 0; mt < 4; mt++)
                    #pragma unroll
                    for (int nt = 0; nt < 4; nt++) {
                        MMA_BF16(acc[mt][nt], A[mt][0], A[mt][1], A[mt][2], A[mt][3],
                                 B_h[nt][0], B_h[nt][1]);
                        MMA_BF16(acc[mt][nt], A[mt][0], A[mt][1], A[mt][2], A[mt][3],
                                 B_l[nt][0], B_l[nt][1]);
                    }
                #pragma unroll
                for (int mt = 0; mt < 4; mt++) {
                    uint32_t aoff = rA[mt] * 64 + (((cA ^ gA[mt])) << 4);
                    LDMATRIX_X4(A[mt][0], A[mt][1], A[mt][2], A[mt][3], al + aoff);
                }
                #pragma unroll
                for (int mt = 0; mt < 4; mt++)
                    #pragma unroll
                    for (int nt = 0; nt < 4; nt++)
                        MMA_BF16(acc[mt][nt], A[mt][0], A[mt][1], A[mt][2], A[mt][3],
                                 B_h[nt][0], B_h[nt][1]);
            }
        }
    } else {
        // V path: 1-pass fp16
        const __half* Af_g = g_xf;
        const __half* Bf_g = g_wvf;

        #pragma unroll
        for (int ps = 0; ps < 2; ps++) {
            uint32_t sb = smem_base + ps * STAGE_BYTES;
            size_t koff = (size_t)ps * BK;
            #pragma unroll
            for (int q = 0; q < 2; q++) {
                CP_ASYNC_16(sb +         ldsw[q], Af_g + ldga[q] + koff);
                CP_ASYNC_16(sb + 16384 + ldsw[q], Bf_g + ldgb[q] + koff);
            }
            CP_ASYNC_COMMIT();
        }

        for (int kc = 0; kc < NKC; kc++) {
            if (kc + 1 < NKC) CP_ASYNC_WAIT_1();
            else              CP_ASYNC_WAIT_ALL();
            __syncthreads();

            if (kc + 2 < NKC) {
                uint32_t sb = smem_base + ((kc + 2) % 3) * STAGE_BYTES;
                size_t koff = (size_t)(kc + 2) * BK;
                #pragma unroll
                for (int q = 0; q < 2; q++) {
                    CP_ASYNC_16(sb +         ldsw[q], Af_g + ldga[q] + koff);
                    CP_ASYNC_16(sb + 16384 + ldsw[q], Bf_g + ldgb[q] + koff);
                }
                CP_ASYNC_COMMIT();
            }

            const uint32_t sb = smem_base + (kc % 3) * STAGE_BYTES;
            const uint32_t af = sb, bf = sb + 16384;

            #pragma unroll
            for (int kf = 0; kf < 2; kf++) {
                const int cA = kf * 2 + khalfA;

                uint32_t B_f[4][2];
                #pragma unroll
                for (int ntp = 0; ntp < 2; ntp++) {
                    int row = wn * 32 + ntp * 16 + ((lane >> 4) & 1) * 8 + (lane & 7);
                    int chunk = kf * 2 + ((lane >> 3) & 1);
                    uint32_t boff = row * 64 + (((chunk ^ ((row >> 1) & 3))) << 4);
                    LDMATRIX_X4(B_f[2*ntp][0], B_f[2*ntp][1],
                                B_f[2*ntp+1][0], B_f[2*ntp+1][1], bf + boff);
                }
                uint32_t A[4][4];
                #pragma unroll
                for (int mt = 0; mt < 4; mt++) {
                    uint32_t aoff = rA[mt] * 64 + (((cA ^ gA[mt])) << 4);
                    LDMATRIX_X4(A[mt][0], A[mt][1], A[mt][2], A[mt][3], af + aoff);
                }
                #pragma unroll
                for (int mt = 0; mt < 4; mt++)
                    #pragma unroll
                    for (int nt = 0; nt < 4; nt++)
                        MMA_F16(acc[mt][nt], A[mt][0], A[mt][1], A[mt][2], A[mt][3],
                                B_f[nt][0], B_f[nt][1]);
            }
        }
    }
    __syncthreads();

    // ---- epilogue: bias (+GELU +log2e on Q), stage fp32, then store ----
    const float* bias = (wsel == 0) ? bq : (wsel == 1) ? bk : bv;

    const int fr = lane >> 2;
    const int fc = (lane & 3) * 2;
    #pragma unroll
    for (int mt = 0; mt < 4; mt++) {
        #pragma unroll
        for (int nt = 0; nt < 4; nt++) {
            int row0 = wm * 64 + mt * 16 + fr;
            int col0 = wn * 32 + nt * 8 + fc;
            float b0 = bias[ncol0 + col0], b1 = bias[ncol0 + col0 + 1];
            #pragma unroll
            for (int half = 0; half < 2; half++) {
                int r = row0 + half * 8;
                float v0 = acc[mt][nt][half * 2 + 0] + b0;
                float v1 = acc[mt][nt][half * 2 + 1] + b1;
                if (wsel == 0) {
                    v0 = 0.5f * v0 * (1.0f + erff(v0 * 0.70710678118654752f));
                    v1 = 0.5f * v1 * (1.0f + erff(v1 * 0.70710678118654752f));
                    v0 *= 1.44269504088896340736f;   // log2(e): softmax in base-2
                    v1 *= 1.44269504088896340736f;
                }
                Cs[r * 132 + col0]     = v0;
                Cs[r * 132 + col0 + 1] = v1;
            }
        }
    }
    __syncthreads();

    const int b  = m0 >> 11;
    const int s0 = m0 & 2047;
    if (wsel < 2) {
        __nv_bfloat16* dsth = (wsel == 0) ? g_qh : g_kh;
        __nv_bfloat16* dstl = (wsel == 0) ? g_ql : g_kl;
        #pragma unroll
        for (int hb = 0; hb < 2; hb++) {
            int h = (ncol0 >> 6) + hb;
            size_t base = (((size_t)(b * HH + h)) * SS + s0) * DH;
            for (int i = tid; i < 128 * 64; i += 256) {
                int s = i >> 6, dh = i & 63;
                float v = Cs[s * 132 + hb * 64 + dh];
                __nv_bfloat16 hi = __float2bfloat16(v);
                dsth[base + (size_t)s * DH + dh] = hi;
                dstl[base + (size_t)s * DH + dh] =
                    __float2bfloat16(v - __bfloat162float(hi));
            }
        }
    } else {
        #pragma unroll
        for (int hb = 0; hb < 2; hb++) {
            int h = (ncol0 >> 6) + hb;
            size_t base = (((size_t)(b * HH + h)) * SS + s0) * DH;
            for (int i = tid; i < 128 * 64; i += 256) {
                int s = i >> 6, dh = i & 63;
                g_vf[base + (size_t)s * DH + dh] =
                    __float2half_rn(Cs[s * 132 + hb * 64 + dh]);
            }
        }
    }
}

// ---------------------------------------------------------------------------
// Flash attention via mma.sync. NEW: 128-thread CTAs (4 warps, 64 q-rows),
// 4 CTAs/SM -> 4 independent barrier domains hide softmax bubbles.
// q-lo register-resident (16 regs); q-hi in 8KB smem, reloaded per ks.
// 2-stage KV ring, online max base-2, fp16 P, single fp16 PV pass.
// ---------------------------------------------------------------------------
#define FQT 64
#define FKT 64
#define FNIT (SS/FKT)
#define FQB 8192                        // Q-hi region
#define FST 24576                       // K/V stage stride (Kh|Kl|Vf x 8KB)
#define FLASH_SMEM (FQB + 2*FST)        // 57344 -> 4 CTAs/SM

__global__ void __launch_bounds__(128, 4) flash_mma_kernel(float* __restrict__ out)
{
    extern __shared__ __align__(1024) char smem[];
    const uint32_t sq = smem_to_u32(smem);      // Q hi
    const uint32_t sb = sq + FQB;               // K/V stages
    const int tid = threadIdx.x, lane = tid & 31, warp = tid >> 5;  // warp 0-3
    const int qb = blockIdx.x * FQT;
    const int h  = blockIdx.y, b = blockIdx.z;
    const size_t gbase = ((size_t)(b * HH + h)) * SS * DH;
    const __nv_bfloat16* Qh_g = g_qh + gbase;
    const __nv_bfloat16* Ql_g = g_ql + gbase;
    const __nv_bfloat16* Kh_g = g_kh + gbase;
    const __nv_bfloat16* Kl_g = g_kl + gbase;
    const __half*        Vf_g = g_vf + gbase;

    // ---- prologue: Qh -> sq, Ql -> stage0 area (temp), then extract ----
    {
        #pragma unroll
        for (int q = 0; q < 4; q++) {
            int id = q * 128 + tid;            // 512 chunks (64 rows x 8)
            int row = id >> 3, c = id & 7;
            uint32_t o = row * 128 + ((c ^ (row & 7)) << 4);
            size_t src = (size_t)(qb + row) * DH + c * 8;
            CP_ASYNC_16(sq + o, Qh_g + src);
            CP_ASYNC_16(sb + o, Ql_g + src);   // temp in stage-0 Kh slot
        }
        CP_ASYNC_COMMIT();
        CP_ASYNC_WAIT_ALL();
        __syncthreads();
    }
    // extract q-lo fragments to registers (resident)
    uint32_t ql[4][4];
    #pragma unroll
    for (int ks = 0; ks < 4; ks++) {
        int row = warp * 16 + (lane & 15);
        int chunk = 2 * ks + (lane >> 4);
        uint32_t addr = sb + row * 128 + ((chunk ^ (row & 7)) << 4);
        LDMATRIX_X4(ql[ks][0], ql[ks][1], ql[ks][2], ql[ks][3], addr);
    }
    __syncthreads();   // all warps extracted before KV overwrites stage 0

    // KV stage 0
    {
        #pragma unroll
        for (int q = 0; q < 4; q++) {
            int id = q * 128 + tid;
            int row = id >> 3, c = id & 7;
            uint32_t o = row * 128 + ((c ^ (row & 7)) << 4);
            size_t src = (size_t)row * DH + c * 8;
            CP_ASYNC_16(sb +         o, Kh_g + src);
            CP_ASYNC_16(sb +  8192 + o, Kl_g + src);
            CP_ASYNC_16(sb + 16384 + o, Vf_g + src);
        }
        CP_ASYNC_COMMIT();
    }

    float oacc[8][4];
    #pragma unroll
    for (int i = 0; i < 8; i++)
        #pragma unroll
        for (int j = 0; j < 4; j++) oacc[i][j] = 0.f;
    float m0r = -INFINITY, m1r = -INFINITY, l0 = 0.f, l1 = 0.f;

    for (int it = 0; it < FNIT; it++) {
        CP_ASYNC_WAIT_ALL();
        __syncthreads();

        if (it + 1 < FNIT) {
            uint32_t buf = sb + ((it + 1) & 1) * FST;
            size_t kadd = (size_t)(it + 1) * FKT * DH;
            #pragma unroll
            for (int q = 0; q < 4; q++) {
                int id = q * 128 + tid;
                int row = id >> 3, c = id & 7;
                uint32_t o = row * 128 + ((c ^ (row & 7)) << 4);
                size_t src = kadd + (size_t)row * DH + c * 8;
                CP_ASYNC_16(buf +         o, Kh_g + src);
                CP_ASYNC_16(buf +  8192 + o, Kl_g + src);
                CP_ASYNC_16(buf + 16384 + o, Vf_g + src);
            }
            CP_ASYNC_COMMIT();
        }

        const uint32_t buf = sb + (it & 1) * FST;
        const uint32_t kh = buf, kl = buf + 8192, vf = buf + 16384;

        // ---- S = Q K^T (3 split passes); q-hi from smem, q-lo resident ----
        float sacc[8][4];
        #pragma unroll
        for (int i = 0; i < 8; i++)
            #pragma unroll
            for (int j = 0; j < 4; j++) sacc[i][j] = 0.f;

        #pragma unroll
        for (int ks = 0; ks < 4; ks++) {
            int qrow = warp * 16 + (lane & 15);
            int qchunk = 2 * ks + (lane >> 4);
            uint32_t qaddr = sq + qrow * 128 + ((qchunk ^ (qrow & 7)) << 4);
            uint32_t qh0, qh1, qh2, qh3;
            LDMATRIX_X4(qh0, qh1, qh2, qh3, qaddr);
            #pragma unroll
            for (int ntp = 0; ntp < 4; ntp++) {
                int row = ntp * 16 + ((lane >> 4) & 1) * 8 + (lane & 7);
                int chunk = 2 * ks + ((lane >> 3) & 1);
                uint32_t addr = kh + row * 128 + ((chunk ^ (row & 7)) << 4);
                uint32_t bh0, bh1, bh2, bh3, bl0, bl1, bl2, bl3;
                LDMATRIX_X4(bh0, bh1, bh2, bh3, addr);
                LDMATRIX_X4(bl0, bl1, bl2, bl3, addr + 8192);
                MMA_BF16(sacc[2*ntp],   qh0, qh1, qh2, qh3, bh0, bh1);
                MMA_BF16(sacc[2*ntp],   ql[ks][0], ql[ks][1], ql[ks][2], ql[ks][3], bh0, bh1);
                MMA_BF16(sacc[2*ntp],   qh0, qh1, qh2, qh3, bl0, bl1);
                MMA_BF16(sacc[2*ntp+1], qh0, qh1, qh2, qh3, bh2, bh3);
                MMA_BF16(sacc[2*ntp+1], ql[ks][0], ql[ks][1], ql[ks][2], ql[ks][3], bh2, bh3);
                MMA_BF16(sacc[2*ntp+1], qh0, qh1, qh2, qh3, bl2, bl3);
            }
        }

        // ---- online softmax, base 2; p in (0,1] -> fp16 pack ----
        float tm0 = -INFINITY, tm1 = -INFINITY;
        #pragma unroll
        for (int nt = 0; nt < 8; nt++) {
            tm0 = fmaxf(tm0, fmaxf(sacc[nt][0], sacc[nt][1]));
            tm1 = fmaxf(tm1, fmaxf(sacc[nt][2], sacc[nt][3]));
        }
        tm0 = fmaxf(tm0, __shfl_xor_sync(0xffffffffu, tm0, 1));
        tm0 = fmaxf(tm0, __shfl_xor_sync(0xffffffffu, tm0, 2));
        tm1 = fmaxf(tm1, __shfl_xor_sync(0xffffffffu, tm1, 1));
        tm1 = fmaxf(tm1, __shfl_xor_sync(0xffffffffu, tm1, 2));
        float mn0 = fmaxf(m0r, tm0), mn1 = fmaxf(m1r, tm1);
        float a0 = ex2f(m0r - mn0), a1 = ex2f(m1r - mn1);
        m0r = mn0; m1r = mn1;

        float rs0 = 0.f, rs1 = 0.f;
        uint32_t ph[4][4];
        #pragma unroll
        for (int nt = 0; nt < 8; nt++) {
            float p00 = ex2f(sacc[nt][0] - mn0);
            float p01 = ex2f(sacc[nt][1] - mn0);
            float p10 = ex2f(sacc[nt][2] - mn1);
            float p11 = ex2f(sacc[nt][3] - mn1);
            rs0 += p00 + p01; rs1 += p10 + p11;
            __half2 h0 = __floats2half2_rn(p00, p01);
            __half2 h1 = __floats2half2_rn(p10, p11);
            int ks = nt >> 1, half = (nt & 1) * 2;
            ph[ks][half]     = *(uint32_t*)&h0;
            ph[ks][half + 1] = *(uint32_t*)&h1;
        }
        l0 = l0 * a0 + rs0;
        l1 = l1 * a1 + rs1;
        #pragma unroll
        for (int nt = 0; nt < 8; nt++) {
            oacc[nt][0] *= a0; oacc[nt][1] *= a0;
            oacc[nt][2] *= a1; oacc[nt][3] *= a1;
        }

        // ---- O += P V, single fp16 pass; V via ldmatrix.trans ----
        #pragma unroll
        for (int ks = 0; ks < 4; ks++) {
            #pragma unroll
            for (int ntp = 0; ntp < 4; ntp++) {
                int row = ks * 16 + ((lane >> 3) & 1) * 8 + (lane & 7);
                int chunk = 2 * ntp + (lane >> 4);
                uint32_t addr = vf + row * 128 + ((chunk ^ (row & 7)) << 4);
                uint32_t b0, b1, b2, b3;
                LDMATRIX_X4_T(b0, b1, b2, b3, addr);
                MMA_F16(oacc[2*ntp],   ph[ks][0], ph[ks][1], ph[ks][2], ph[ks][3], b0, b1);
                MMA_F16(oacc[2*ntp+1], ph[ks][0], ph[ks][1], ph[ks][2], ph[ks][3], b2, b3);
            }
        }
        // top-of-iteration barrier of it+1 orders these reads before the
        // prefetch that overwrites this buffer.
    }

    // ---- epilogue: reduce l across the 4-lane row group, store fp32 ----
    {
        l0 += __shfl_xor_sync(0xffffffffu, l0, 1);
        l0 += __shfl_xor_sync(0xffffffffu, l0, 2);
        l1 += __shfl_xor_sync(0xffffffffu, l1, 1);
        l1 += __shfl_xor_sync(0xffffffffu, l1, 2);
        const int r = lane >> 2, c2 = (lane & 3) * 2;
        float inv0 = 1.0f / l0, inv1 = 1.0f / l1;
        int row0 = qb + warp * 16 + r;
        size_t o0 = ((size_t)b * SS + row0) * DD + h * DH;
        size_t o1 = ((size_t)b * SS + row0 + 8) * DD + h * DH;
        #pragma unroll
        for (int nt = 0; nt < 8; nt++) {
            *(float2*)(out + o0 + nt * 8 + c2) =
                make_float2(oacc[nt][0] * inv0, oacc[nt][1] * inv0);
            *(float2*)(out + o1 + nt * 8 + c2) =
                make_float2(oacc[nt][2] * inv1, oacc[nt][3] * inv1);
        }
    }
}

// ---------------------------------------------------------------------------
extern "C" void kernel_launch(void* const* d_in, const int* in_sizes, int n_in,
                              void* d_out, int out_size) {
    const float* x  = (const float*)d_in[0];
    const float* Wq = (const float*)d_in[1];
    const float* bq = (const float*)d_in[2];
    const float* Wk = (const float*)d_in[3];
    const float* bk = (const float*)d_in[4];
    const float* Wv = (const float*)d_in[5];
    const float* bv = (const float*)d_in[6];
    float* out = (float*)d_out;

    split_x_kernel<<<M_TOTAL * DD / 256, 256>>>(x);
    split_w_kernel<<<dim3(DD/32, DD/32, 3), dim3(32, 8)>>>(Wq, Wk, Wv);

    cudaFuncSetAttribute(proj_mma_kernel,
                         cudaFuncAttributeMaxDynamicSharedMemorySize, PROJ_SMEM);
    proj_mma_kernel<<<dim3(N_TOTAL/128, M_TOTAL/128), 256, PROJ_SMEM>>>(bq, bk, bv);

    cudaFuncSetAttribute(flash_mma_kernel,
                         cudaFuncAttributeMaxDynamicSharedMemorySize, FLASH_SMEM);
    flash_mma_kernel<<<dim3(SS/FQT, HH, BB), 128, FLASH_SMEM>>>(out);
}

// round 13
// speedup vs baseline: 1.1627x; 1.0104x over previous
#include <cuda_runtime.h>
#include <cuda_bf16.h>
#include <cuda_fp16.h>
#include <math.h>
#include <cstdint>

#define BB 2
#define SS 2048
#define DD 1024
#define HH 16
#define DH 64
#define M_TOTAL (BB*SS)      // 4096
#define N_TOTAL (3*DD)       // 3072

// ---------------- device scratch (no cudaMalloc allowed) -------------------
__device__ __align__(16) __nv_bfloat16 g_xh[M_TOTAL*DD];
__device__ __align__(16) __nv_bfloat16 g_xl[M_TOTAL*DD];
__device__ __align__(16) __half        g_xf[M_TOTAL*DD];   // fp16 x (V proj)
__device__ __align__(16) __nv_bfloat16 g_wth[2*DD*DD];     // Wq^T, Wk^T hi
__device__ __align__(16) __nv_bfloat16 g_wtl[2*DD*DD];     // Wq^T, Wk^T lo
__device__ __align__(16) __half        g_wvf[DD*DD];       // Wv^T fp16
// projected Q/K bf16 hi/lo, V fp16, [B,H,S,DH]  (Q pre-scaled by log2(e))
__device__ __align__(16) __nv_bfloat16 g_qh[BB*HH*SS*DH];
__device__ __align__(16) __nv_bfloat16 g_ql[BB*HH*SS*DH];
__device__ __align__(16) __nv_bfloat16 g_kh[BB*HH*SS*DH];
__device__ __align__(16) __nv_bfloat16 g_kl[BB*HH*SS*DH];
__device__ __align__(16) __half        g_vf[BB*HH*SS*DH];

// ---------------- warp-mma helpers (plain sm_80+ PTX) ----------------------
__device__ __forceinline__ uint32_t smem_to_u32(const void* p) {
    uint32_t a;
    asm("{ .reg .u64 t; cvta.to.shared.u64 t, %1; cvt.u32.u64 %0, t; }"
        : "=r"(a) : "l"(p));
    return a;
}
__device__ __forceinline__ float ex2f(float x) {
    float y;
    asm("ex2.approx.f32 %0, %1;" : "=f"(y) : "f"(x));
    return y;
}
// pack two fp32 into f16x2 ({lo=a, hi=b}) and 2^x both halves in one MUFU op
__device__ __forceinline__ uint32_t ex2_h2(float a, float b) {
    uint32_t h2;
    asm("cvt.rn.f16x2.f32 %0, %1, %2;" : "=r"(h2) : "f"(b), "f"(a));
    asm("ex2.approx.f16x2 %0, %1;" : "=r"(h2) : "r"(h2));
    return h2;
}

#define CP_ASYNC_16(dst, src) \
    asm volatile("cp.async.cg.shared.global [%0], [%1], 16;" :: "r"(dst), "l"(src))
#define CP_ASYNC_COMMIT() asm volatile("cp.async.commit_group;" ::: "memory")
#define CP_ASYNC_WAIT_ALL() asm volatile("cp.async.wait_group 0;" ::: "memory")
#define CP_ASYNC_WAIT_1()  asm volatile("cp.async.wait_group 1;" ::: "memory")

#define LDMATRIX_X4(r0, r1, r2, r3, addr) \
    asm volatile("ldmatrix.sync.aligned.m8n8.x4.shared.b16 {%0,%1,%2,%3}, [%4];" \
        : "=r"(r0), "=r"(r1), "=r"(r2), "=r"(r3) : "r"(addr))
#define LDMATRIX_X4_T(r0, r1, r2, r3, addr) \
    asm volatile("ldmatrix.sync.aligned.m8n8.x4.trans.shared.b16 {%0,%1,%2,%3}, [%4];" \
        : "=r"(r0), "=r"(r1), "=r"(r2), "=r"(r3) : "r"(addr))

#define MMA_BF16(cc, a0, a1, a2, a3, b0, b1) \
    asm volatile("mma.sync.aligned.m16n8k16.row.col.f32.bf16.bf16.f32 " \
        "{%0,%1,%2,%3}, {%4,%5,%6,%7}, {%8,%9}, {%0,%1,%2,%3};" \
        : "+f"((cc)[0]), "+f"((cc)[1]), "+f"((cc)[2]), "+f"((cc)[3]) \
        : "r"(a0), "r"(a1), "r"(a2), "r"(a3), "r"(b0), "r"(b1))

#define MMA_F16(cc, a0, a1, a2, a3, b0, b1) \
    asm volatile("mma.sync.aligned.m16n8k16.row.col.f32.f16.f16.f32 " \
        "{%0,%1,%2,%3}, {%4,%5,%6,%7}, {%8,%9}, {%0,%1,%2,%3};" \
        : "+f"((cc)[0]), "+f"((cc)[1]), "+f"((cc)[2]), "+f"((cc)[3]) \
        : "r"(a0), "r"(a1), "r"(a2), "r"(a3), "r"(b0), "r"(b1))

// ---------------------------------------------------------------------------
// Split kernels
// ---------------------------------------------------------------------------
__global__ void __launch_bounds__(256) split_x_kernel(const float* __restrict__ x) {
    int i = blockIdx.x * 256 + threadIdx.x;
    float v = x[i];
    __nv_bfloat16 hi = __float2bfloat16(v);
    g_xh[i] = hi;
    g_xl[i] = __float2bfloat16(v - __bfloat162float(hi));
    g_xf[i] = __float2half_rn(v);
}

__global__ void __launch_bounds__(256) split_w_kernel(
    const float* __restrict__ Wq, const float* __restrict__ Wk, const float* __restrict__ Wv)
{
    const float* W = (blockIdx.z == 0) ? Wq : (blockIdx.z == 1) ? Wk : Wv;
    __shared__ float t[32][33];
    int n0 = blockIdx.x * 32, k0 = blockIdx.y * 32;
    int tx = threadIdx.x, ty = threadIdx.y;   // block (32, 8)
    for (int r = ty; r < 32; r += 8)
        t[r][tx] = W[(size_t)(k0 + r) * DD + n0 + tx];
    __syncthreads();
    if (blockIdx.z < 2) {
        size_t base = (size_t)blockIdx.z * DD * DD;
        for (int r = ty; r < 32; r += 8) {
            float v = t[tx][r];
            __nv_bfloat16 hi = __float2bfloat16(v);
            size_t idx = base + (size_t)(n0 + r) * DD + k0 + tx;
            g_wth[idx] = hi;
            g_wtl[idx] = __float2bfloat16(v - __bfloat162float(hi));
        }
    } else {
        for (int r = ty; r < 32; r += 8) {
            size_t idx = (size_t)(n0 + r) * DD + k0 + tx;
            g_wvf[idx] = __float2half_rn(t[tx][r]);
        }
    }
}

// ---------------------------------------------------------------------------
// Projection via mma.sync (R11 config, unchanged). Q/K: 3-pass split-bf16;
// V: single fp16 pass. 3-stage cp.async ring.
// ---------------------------------------------------------------------------
#define BK 32
#define STAGE_BYTES 32768
#define PROJ_SMEM 98304                  // 3 stages; Cs(67.6KB) overlays

__global__ void __launch_bounds__(256, 2) proj_mma_kernel(
    const float* __restrict__ bq, const float* __restrict__ bk, const float* __restrict__ bv)
{
    extern __shared__ __align__(1024) char smem[];
    const uint32_t smem_base = smem_to_u32(smem);
    float* Cs = (float*)smem;

    const int tid  = threadIdx.x;
    const int lane = tid & 31;
    const int warp = tid >> 5;
    const int wm   = warp >> 2;
    const int wn   = warp & 3;

    const int ntile = blockIdx.x;
    const int mtile = blockIdx.y;
    const int wsel  = ntile >> 3;
    const int ncol0 = (ntile & 7) * 128;
    const int m0    = mtile * 128;

    int ldsw[2];
    size_t ldga[2], ldgb[2];
    #pragma unroll
    for (int q = 0; q < 2; q++) {
        int idx = q * 256 + tid;
        int row = idx >> 2, c = idx & 3;
        ldsw[q]  = row * 64 + ((c ^ ((row >> 1) & 3)) << 4);
        ldga[q]  = (size_t)(m0 + row) * DD + c * 8;
        ldgb[q]  = (size_t)(ncol0 + row) * DD + c * 8;
    }

    int rA[4], gA[4];
    #pragma unroll
    for (int mt = 0; mt < 4; mt++) {
        rA[mt] = wm * 64 + mt * 16 + (lane & 15);
        gA[mt] = (rA[mt] >> 1) & 3;
    }
    const int khalfA = lane >> 4;

    float acc[4][4][4];
    #pragma unroll
    for (int i = 0; i < 4; i++)
        #pragma unroll
        for (int j = 0; j < 4; j++)
            #pragma unroll
            for (int r = 0; r < 4; r++) acc[i][j][r] = 0.f;

    const int NKC = DD / BK;              // 32

    if (wsel < 2) {
        const __nv_bfloat16* Ah_g = g_xh;
        const __nv_bfloat16* Al_g = g_xl;
        const __nv_bfloat16* Bh_g = g_wth + (size_t)wsel * DD * DD;
        const __nv_bfloat16* Bl_g = g_wtl + (size_t)wsel * DD * DD;

        #pragma unroll
        for (int ps = 0; ps < 2; ps++) {
            uint32_t sb = smem_base + ps * STAGE_BYTES;
            size_t koff = (size_t)ps * BK;
            #pragma unroll
            for (int q = 0; q < 2; q++) {
                CP_ASYNC_16(sb +         ldsw[q], Ah_g + ldga[q] + koff);
                CP_ASYNC_16(sb +  8192 + ldsw[q], Al_g + ldga[q] + koff);
                CP_ASYNC_16(sb + 16384 + ldsw[q], Bh_g + ldgb[q] + koff);
                CP_ASYNC_16(sb + 24576 + ldsw[q], Bl_g + ldgb[q] + koff);
            }
            CP_ASYNC_COMMIT();
        }

        for (int kc = 0; kc < NKC; kc++) {
            if (kc + 1 < NKC) CP_ASYNC_WAIT_1();
            else              CP_ASYNC_WAIT_ALL();
            __syncthreads();

            if (kc + 2 < NKC) {
                uint32_t sb = smem_base + ((kc + 2) % 3) * STAGE_BYTES;
                size_t koff = (size_t)(kc + 2) * BK;
                #pragma unroll
                for (int q = 0; q < 2; q++) {
                    CP_ASYNC_16(sb +         ldsw[q], Ah_g + ldga[q] + koff);
                    CP_ASYNC_16(sb +  8192 + ldsw[q], Al_g + ldga[q] + koff);
                    CP_ASYNC_16(sb + 16384 + ldsw[q], Bh_g + ldgb[q] + koff);
                    CP_ASYNC_16(sb + 24576 + ldsw[q], Bl_g + ldgb[q] + koff);
                }
                CP_ASYNC_COMMIT();
            }

            const uint32_t sb = smem_base + (kc % 3) * STAGE_BYTES;
            const uint32_t ah = sb, al = sb + 8192, bh = sb + 16384, bl = sb + 24576;

            #pragma unroll
            for (int kf = 0; kf < 2; kf++) {
                const int cA = kf * 2 + khalfA;

                uint32_t B_h[4][2], B_l[4][2];
                #pragma unroll
                for (int ntp = 0; ntp < 2; ntp++) {
                    int row = wn * 32 + ntp * 16 + ((lane >> 4) & 1) * 8 + (lane & 7);
                    int chunk = kf * 2 + ((lane >> 3) & 1);
                    uint32_t boff = row * 64 + (((chunk ^ ((row >> 1) & 3))) << 4);
                    LDMATRIX_X4(B_h[2*ntp][0], B_h[2*ntp][1],
                                B_h[2*ntp+1][0], B_h[2*ntp+1][1], bh + boff);
                    LDMATRIX_X4(B_l[2*ntp][0], B_l[2*ntp][1],
                                B_l[2*ntp+1][0], B_l[2*ntp+1][1], bl + boff);
                }
                uint32_t A[4][4];
                #pragma unroll
                for (int mt = 0; mt < 4; mt++) {
                    uint32_t aoff = rA[mt] * 64 + (((cA ^ gA[mt])) << 4);
                    LDMATRIX_X4(A[mt][0], A[mt][1], A[mt][2], A[mt][3], ah + aoff);
                }
                #pragma unroll
                for (int mt = 0; mt < 4; mt++)
                    #pragma unroll
                    for (int nt = 0; nt < 4; nt++) {
                        MMA_BF16(acc[mt][nt], A[mt][0], A[mt][1], A[mt][2], A[mt][3],
                                 B_h[nt][0], B_h[nt][1]);
                        MMA_BF16(acc[mt][nt], A[mt][0], A[mt][1], A[mt][2], A[mt][3],
                                 B_l[nt][0], B_l[nt][1]);
                    }
                #pragma unroll
                for (int mt = 0; mt < 4; mt++) {
                    uint32_t aoff = rA[mt] * 64 + (((cA ^ gA[mt])) << 4);
                    LDMATRIX_X4(A[mt][0], A[mt][1], A[mt][2], A[mt][3], al + aoff);
                }
                #pragma unroll
                for (int mt = 0; mt < 4; mt++)
                    #pragma unroll
                    for (int nt = 0; nt < 4; nt++)
                        MMA_BF16(acc[mt][nt], A[mt][0], A[mt][1], A[mt][2], A[mt][3],
                                 B_h[nt][0], B_h[nt][1]);
            }
        }
    } else {
        // V path: 1-pass fp16
        const __half* Af_g = g_xf;
        const __half* Bf_g = g_wvf;

        #pragma unroll
        for (int ps = 0; ps < 2; ps++) {
            uint32_t sb = smem_base + ps * STAGE_BYTES;
            size_t koff = (size_t)ps * BK;
            #pragma unroll
            for (int q = 0; q < 2; q++) {
                CP_ASYNC_16(sb +         ldsw[q], Af_g + ldga[q] + koff);
                CP_ASYNC_16(sb + 16384 + ldsw[q], Bf_g + ldgb[q] + koff);
            }
            CP_ASYNC_COMMIT();
        }

        for (int kc = 0; kc < NKC; kc++) {
            if (kc + 1 < NKC) CP_ASYNC_WAIT_1();
            else              CP_ASYNC_WAIT_ALL();
            __syncthreads();

            if (kc + 2 < NKC) {
                uint32_t sb = smem_base + ((kc + 2) % 3) * STAGE_BYTES;
                size_t koff = (size_t)(kc + 2) * BK;
                #pragma unroll
                for (int q = 0; q < 2; q++) {
                    CP_ASYNC_16(sb +         ldsw[q], Af_g + ldga[q] + koff);
                    CP_ASYNC_16(sb + 16384 + ldsw[q], Bf_g + ldgb[q] + koff);
                }
                CP_ASYNC_COMMIT();
            }

            const uint32_t sb = smem_base + (kc % 3) * STAGE_BYTES;
            const uint32_t af = sb, bf = sb + 16384;

            #pragma unroll
            for (int kf = 0; kf < 2; kf++) {
                const int cA = kf * 2 + khalfA;

                uint32_t B_f[4][2];
                #pragma unroll
                for (int ntp = 0; ntp < 2; ntp++) {
                    int row = wn * 32 + ntp * 16 + ((lane >> 4) & 1) * 8 + (lane & 7);
                    int chunk = kf * 2 + ((lane >> 3) & 1);
                    uint32_t boff = row * 64 + (((chunk ^ ((row >> 1) & 3))) << 4);
                    LDMATRIX_X4(B_f[2*ntp][0], B_f[2*ntp][1],
                                B_f[2*ntp+1][0], B_f[2*ntp+1][1], bf + boff);
                }
                uint32_t A[4][4];
                #pragma unroll
                for (int mt = 0; mt < 4; mt++) {
                    uint32_t aoff = rA[mt] * 64 + (((cA ^ gA[mt])) << 4);
                    LDMATRIX_X4(A[mt][0], A[mt][1], A[mt][2], A[mt][3], af + aoff);
                }
                #pragma unroll
                for (int mt = 0; mt < 4; mt++)
                    #pragma unroll
                    for (int nt = 0; nt < 4; nt++)
                        MMA_F16(acc[mt][nt], A[mt][0], A[mt][1], A[mt][2], A[mt][3],
                                B_f[nt][0], B_f[nt][1]);
            }
        }
    }
    __syncthreads();

    // ---- epilogue: bias (+GELU +log2e on Q), stage fp32, then store ----
    const float* bias = (wsel == 0) ? bq : (wsel == 1) ? bk : bv;

    const int fr = lane >> 2;
    const int fc = (lane & 3) * 2;
    #pragma unroll
    for (int mt = 0; mt < 4; mt++) {
        #pragma unroll
        for (int nt = 0; nt < 4; nt++) {
            int row0 = wm * 64 + mt * 16 + fr;
            int col0 = wn * 32 + nt * 8 + fc;
            float b0 = bias[ncol0 + col0], b1 = bias[ncol0 + col0 + 1];
            #pragma unroll
            for (int half = 0; half < 2; half++) {
                int r = row0 + half * 8;
                float v0 = acc[mt][nt][half * 2 + 0] + b0;
                float v1 = acc[mt][nt][half * 2 + 1] + b1;
                if (wsel == 0) {
                    v0 = 0.5f * v0 * (1.0f + erff(v0 * 0.70710678118654752f));
                    v1 = 0.5f * v1 * (1.0f + erff(v1 * 0.70710678118654752f));
                    v0 *= 1.44269504088896340736f;   // log2(e): softmax in base-2
                    v1 *= 1.44269504088896340736f;
                }
                Cs[r * 132 + col0]     = v0;
                Cs[r * 132 + col0 + 1] = v1;
            }
        }
    }
    __syncthreads();

    const int b  = m0 >> 11;
    const int s0 = m0 & 2047;
    if (wsel < 2) {
        __nv_bfloat16* dsth = (wsel == 0) ? g_qh : g_kh;
        __nv_bfloat16* dstl = (wsel == 0) ? g_ql : g_kl;
        #pragma unroll
        for (int hb = 0; hb < 2; hb++) {
            int h = (ncol0 >> 6) + hb;
            size_t base = (((size_t)(b * HH + h)) * SS + s0) * DH;
            for (int i = tid; i < 128 * 64; i += 256) {
                int s = i >> 6, dh = i & 63;
                float v = Cs[s * 132 + hb * 64 + dh];
                __nv_bfloat16 hi = __float2bfloat16(v);
                dsth[base + (size_t)s * DH + dh] = hi;
                dstl[base + (size_t)s * DH + dh] =
                    __float2bfloat16(v - __bfloat162float(hi));
            }
        }
    } else {
        #pragma unroll
        for (int hb = 0; hb < 2; hb++) {
            int h = (ncol0 >> 6) + hb;
            size_t base = (((size_t)(b * HH + h)) * SS + s0) * DH;
            for (int i = tid; i < 128 * 64; i += 256) {
                int s = i >> 6, dh = i & 63;
                g_vf[base + (size_t)s * DH + dh] =
                    __float2half_rn(Cs[s * 132 + hb * 64 + dh]);
            }
        }
    }
}

// ---------------------------------------------------------------------------
// Flash attention via mma.sync. 128-thread CTAs (4 warps, 64 q-rows),
// 4 CTAs/SM. q-lo register-resident; q-hi in 8KB smem, reloaded per ks.
// 2-stage KV ring, online max base-2, fp16 P via ex2.approx.f16x2
// (half the MUFU ops of scalar ex2.f32), single fp16 PV pass.
// ---------------------------------------------------------------------------
#define FQT 64
#define FKT 64
#define FNIT (SS/FKT)
#define FQB 8192                        // Q-hi region
#define FST 24576                       // K/V stage stride (Kh|Kl|Vf x 8KB)
#define FLASH_SMEM (FQB + 2*FST)        // 57344 -> 4 CTAs/SM

__global__ void __launch_bounds__(128, 4) flash_mma_kernel(float* __restrict__ out)
{
    extern __shared__ __align__(1024) char smem[];
    const uint32_t sq = smem_to_u32(smem);      // Q hi
    const uint32_t sb = sq + FQB;               // K/V stages
    const int tid = threadIdx.x, lane = tid & 31, warp = tid >> 5;  // warp 0-3
    const int qb = blockIdx.x * FQT;
    const int h  = blockIdx.y, b = blockIdx.z;
    const size_t gbase = ((size_t)(b * HH + h)) * SS * DH;
    const __nv_bfloat16* Qh_g = g_qh + gbase;
    const __nv_bfloat16* Ql_g = g_ql + gbase;
    const __nv_bfloat16* Kh_g = g_kh + gbase;
    const __nv_bfloat16* Kl_g = g_kl + gbase;
    const __half*        Vf_g = g_vf + gbase;

    // ---- prologue: Qh -> sq, Ql -> stage0 area (temp), then extract ----
    {
        #pragma unroll
        for (int q = 0; q < 4; q++) {
            int id = q * 128 + tid;            // 512 chunks (64 rows x 8)
            int row = id >> 3, c = id & 7;
            uint32_t o = row * 128 + ((c ^ (row & 7)) << 4);
            size_t src = (size_t)(qb + row) * DH + c * 8;
            CP_ASYNC_16(sq + o, Qh_g + src);
            CP_ASYNC_16(sb + o, Ql_g + src);   // temp in stage-0 Kh slot
        }
        CP_ASYNC_COMMIT();
        CP_ASYNC_WAIT_ALL();
        __syncthreads();
    }
    // extract q-lo fragments to registers (resident)
    uint32_t ql[4][4];
    #pragma unroll
    for (int ks = 0; ks < 4; ks++) {
        int row = warp * 16 + (lane & 15);
        int chunk = 2 * ks + (lane >> 4);
        uint32_t addr = sb + row * 128 + ((chunk ^ (row & 7)) << 4);
        LDMATRIX_X4(ql[ks][0], ql[ks][1], ql[ks][2], ql[ks][3], addr);
    }
    __syncthreads();   // all warps extracted before KV overwrites stage 0

    // KV stage 0
    {
        #pragma unroll
        for (int q = 0; q < 4; q++) {
            int id = q * 128 + tid;
            int row = id >> 3, c = id & 7;
            uint32_t o = row * 128 + ((c ^ (row & 7)) << 4);
            size_t src = (size_t)row * DH + c * 8;
            CP_ASYNC_16(sb +         o, Kh_g + src);
            CP_ASYNC_16(sb +  8192 + o, Kl_g + src);
            CP_ASYNC_16(sb + 16384 + o, Vf_g + src);
        }
        CP_ASYNC_COMMIT();
    }

    float oacc[8][4];
    #pragma unroll
    for (int i = 0; i < 8; i++)
        #pragma unroll
        for (int j = 0; j < 4; j++) oacc[i][j] = 0.f;
    float m0r = -INFINITY, m1r = -INFINITY, l0 = 0.f, l1 = 0.f;

    for (int it = 0; it < FNIT; it++) {
        CP_ASYNC_WAIT_ALL();
        __syncthreads();

        if (it + 1 < FNIT) {
            uint32_t buf = sb + ((it + 1) & 1) * FST;
            size_t kadd = (size_t)(it + 1) * FKT * DH;
            #pragma unroll
            for (int q = 0; q < 4; q++) {
                int id = q * 128 + tid;
                int row = id >> 3, c = id & 7;
                uint32_t o = row * 128 + ((c ^ (row & 7)) << 4);
                size_t src = kadd + (size_t)row * DH + c * 8;
                CP_ASYNC_16(buf +         o, Kh_g + src);
                CP_ASYNC_16(buf +  8192 + o, Kl_g + src);
                CP_ASYNC_16(buf + 16384 + o, Vf_g + src);
            }
            CP_ASYNC_COMMIT();
        }

        const uint32_t buf = sb + (it & 1) * FST;
        const uint32_t kh = buf, kl = buf + 8192, vf = buf + 16384;

        // ---- S = Q K^T (3 split passes); q-hi from smem, q-lo resident ----
        float sacc[8][4];
        #pragma unroll
        for (int i = 0; i < 8; i++)
            #pragma unroll
            for (int j = 0; j < 4; j++) sacc[i][j] = 0.f;

        #pragma unroll
        for (int ks = 0; ks < 4; ks++) {
            int qrow = warp * 16 + (lane & 15);
            int qchunk = 2 * ks + (lane >> 4);
            uint32_t qaddr = sq + qrow * 128 + ((qchunk ^ (qrow & 7)) << 4);
            uint32_t qh0, qh1, qh2, qh3;
            LDMATRIX_X4(qh0, qh1, qh2, qh3, qaddr);
            #pragma unroll
            for (int ntp = 0; ntp < 4; ntp++) {
                int row = ntp * 16 + ((lane >> 4) & 1) * 8 + (lane & 7);
                int chunk = 2 * ks + ((lane >> 3) & 1);
                uint32_t addr = kh + row * 128 + ((chunk ^ (row & 7)) << 4);
                uint32_t bh0, bh1, bh2, bh3, bl0, bl1, bl2, bl3;
                LDMATRIX_X4(bh0, bh1, bh2, bh3, addr);
                LDMATRIX_X4(bl0, bl1, bl2, bl3, addr + 8192);
                MMA_BF16(sacc[2*ntp],   qh0, qh1, qh2, qh3, bh0, bh1);
                MMA_BF16(sacc[2*ntp],   ql[ks][0], ql[ks][1], ql[ks][2], ql[ks][3], bh0, bh1);
                MMA_BF16(sacc[2*ntp],   qh0, qh1, qh2, qh3, bl0, bl1);
                MMA_BF16(sacc[2*ntp+1], qh0, qh1, qh2, qh3, bh2, bh3);
                MMA_BF16(sacc[2*ntp+1], ql[ks][0], ql[ks][1], ql[ks][2], ql[ks][3], bh2, bh3);
                MMA_BF16(sacc[2*ntp+1], qh0, qh1, qh2, qh3, bl2, bl3);
            }
        }

        // ---- online softmax, base 2; exp via ex2.approx.f16x2 ----
        float tm0 = -INFINITY, tm1 = -INFINITY;
        #pragma unroll
        for (int nt = 0; nt < 8; nt++) {
            tm0 = fmaxf(tm0, fmaxf(sacc[nt][0], sacc[nt][1]));
            tm1 = fmaxf(tm1, fmaxf(sacc[nt][2], sacc[nt][3]));
        }
        tm0 = fmaxf(tm0, __shfl_xor_sync(0xffffffffu, tm0, 1));
        tm0 = fmaxf(tm0, __shfl_xor_sync(0xffffffffu, tm0, 2));
        tm1 = fmaxf(tm1, __shfl_xor_sync(0xffffffffu, tm1, 1));
        tm1 = fmaxf(tm1, __shfl_xor_sync(0xffffffffu, tm1, 2));
        float mn0 = fmaxf(m0r, tm0), mn1 = fmaxf(m1r, tm1);
        float a0 = ex2f(m0r - mn0), a1 = ex2f(m1r - mn1);
        m0r = mn0; m1r = mn1;

        float rs0 = 0.f, rs1 = 0.f;
        uint32_t ph[4][4];
        #pragma unroll
        for (int nt = 0; nt < 8; nt++) {
            // diffs in fp32 (exact where it matters), pair-exp in f16x2
            uint32_t h2a = ex2_h2(sacc[nt][0] - mn0, sacc[nt][1] - mn0);
            uint32_t h2b = ex2_h2(sacc[nt][2] - mn1, sacc[nt][3] - mn1);
            int ks = nt >> 1, half = (nt & 1) * 2;
            ph[ks][half]     = h2a;
            ph[ks][half + 1] = h2b;
            float2 fa = __half22float2(*(__half2*)&h2a);
            float2 fb = __half22float2(*(__half2*)&h2b);
            rs0 += fa.x + fa.y;
            rs1 += fb.x + fb.y;
        }
        l0 = l0 * a0 + rs0;
        l1 = l1 * a1 + rs1;
        #pragma unroll
        for (int nt = 0; nt < 8; nt++) {
            oacc[nt][0] *= a0; oacc[nt][1] *= a0;
            oacc[nt][2] *= a1; oacc[nt][3] *= a1;
        }

        // ---- O += P V, single fp16 pass; V via ldmatrix.trans ----
        #pragma unroll
        for (int ks = 0; ks < 4; ks++) {
            #pragma unroll
            for (int ntp = 0; ntp < 4; ntp++) {
                int row = ks * 16 + ((lane >> 3) & 1) * 8 + (lane & 7);
                int chunk = 2 * ntp + (lane >> 4);
                uint32_t addr = vf + row * 128 + ((chunk ^ (row & 7)) << 4);
                uint32_t b0, b1, b2, b3;
                LDMATRIX_X4_T(b0, b1, b2, b3, addr);
                MMA_F16(oacc[2*ntp],   ph[ks][0], ph[ks][1], ph[ks][2], ph[ks][3], b0, b1);
                MMA_F16(oacc[2*ntp+1], ph[ks][0], ph[ks][1], ph[ks][2], ph[ks][3], b2, b3);
            }
        }
        // top-of-iteration barrier of it+1 orders these reads before the
        // prefetch that overwrites this buffer.
    }

    // ---- epilogue: reduce l across the 4-lane row group, store fp32 ----
    {
        l0 += __shfl_xor_sync(0xffffffffu, l0, 1);
        l0 += __shfl_xor_sync(0xffffffffu, l0, 2);
        l1 += __shfl_xor_sync(0xffffffffu, l1, 1);
        l1 += __shfl_xor_sync(0xffffffffu, l1, 2);
        const int r = lane >> 2, c2 = (lane & 3) * 2;
        float inv0 = 1.0f / l0, inv1 = 1.0f / l1;
        int row0 = qb + warp * 16 + r;
        size_t o0 = ((size_t)b * SS + row0) * DD + h * DH;
        size_t o1 = ((size_t)b * SS + row0 + 8) * DD + h * DH;
        #pragma unroll
        for (int nt = 0; nt < 8; nt++) {
            *(float2*)(out + o0 + nt * 8 + c2) =
                make_float2(oacc[nt][0] * inv0, oacc[nt][1] * inv0);
            *(float2*)(out + o1 + nt * 8 + c2) =
                make_float2(oacc[nt][2] * inv1, oacc[nt][3] * inv1);
        }
    }
}

// ---------------------------------------------------------------------------
extern "C" void kernel_launch(void* const* d_in, const int* in_sizes, int n_in,
                              void* d_out, int out_size) {
    const float* x  = (const float*)d_in[0];
    const float* Wq = (const float*)d_in[1];
    const float* bq = (const float*)d_in[2];
    const float* Wk = (const float*)d_in[3];
    const float* bk = (const float*)d_in[4];
    const float* Wv = (const float*)d_in[5];
    const float* bv = (const float*)d_in[6];
    float* out = (float*)d_out;

    split_x_kernel<<<M_TOTAL * DD / 256, 256>>>(x);
    split_w_kernel<<<dim3(DD/32, DD/32, 3), dim3(32, 8)>>>(Wq, Wk, Wv);

    cudaFuncSetAttribute(proj_mma_kernel,
                         cudaFuncAttributeMaxDynamicSharedMemorySize, PROJ_SMEM);
    proj_mma_kernel<<<dim3(N_TOTAL/128, M_TOTAL/128), 256, PROJ_SMEM>>>(bq, bk, bv);

    cudaFuncSetAttribute(flash_mma_kernel,
                         cudaFuncAttributeMaxDynamicSharedMemorySize, FLASH_SMEM);
    flash_mma_kernel<<<dim3(SS/FQT, HH, BB), 128, FLASH_SMEM>>>(out);
}

// round 14
// speedup vs baseline: 1.1925x; 1.0256x over previous
#include <cuda_runtime.h>
#include <cuda_bf16.h>
#include <cuda_fp16.h>
#include <math.h>
#include <cstdint>

#define BB 2
#define SS 2048
#define DD 1024
#define HH 16
#define DH 64
#define M_TOTAL (BB*SS)      // 4096
#define N_TOTAL (3*DD)       // 3072

// ---------------- device scratch (no cudaMalloc allowed) -------------------
__device__ __align__(16) __nv_bfloat16 g_xh[M_TOTAL*DD];
__device__ __align__(16) __nv_bfloat16 g_xl[M_TOTAL*DD];
__device__ __align__(16) __half        g_xf[M_TOTAL*DD];   // fp16 x (V proj)
__device__ __align__(16) __nv_bfloat16 g_wth[2*DD*DD];     // Wq^T, Wk^T hi
__device__ __align__(16) __nv_bfloat16 g_wtl[2*DD*DD];     // Wq^T, Wk^T lo
__device__ __align__(16) __half        g_wvf[DD*DD];       // Wv^T fp16
// projected Q/K bf16 hi/lo, V fp16, [B,H,S,DH]  (Q pre-scaled by log2(e))
__device__ __align__(16) __nv_bfloat16 g_qh[BB*HH*SS*DH];
__device__ __align__(16) __nv_bfloat16 g_ql[BB*HH*SS*DH];
__device__ __align__(16) __nv_bfloat16 g_kh[BB*HH*SS*DH];
__device__ __align__(16) __nv_bfloat16 g_kl[BB*HH*SS*DH];
__device__ __align__(16) __half        g_vf[BB*HH*SS*DH];

// ---------------- warp-mma helpers (plain sm_80+ PTX) ----------------------
__device__ __forceinline__ uint32_t smem_to_u32(const void* p) {
    uint32_t a;
    asm("{ .reg .u64 t; cvta.to.shared.u64 t, %1; cvt.u32.u64 %0, t; }"
        : "=r"(a) : "l"(p));
    return a;
}
__device__ __forceinline__ float ex2f(float x) {
    float y;
    asm("ex2.approx.f32 %0, %1;" : "=f"(y) : "f"(x));
    return y;
}
// pack two fp32 into f16x2 ({lo=a, hi=b}) and 2^x both halves in one MUFU op
__device__ __forceinline__ uint32_t ex2_h2(float a, float b) {
    uint32_t h2;
    asm("cvt.rn.f16x2.f32 %0, %1, %2;" : "=r"(h2) : "f"(b), "f"(a));
    asm("ex2.approx.f16x2 %0, %1;" : "=r"(h2) : "r"(h2));
    return h2;
}

#define CP_ASYNC_16(dst, src) \
    asm volatile("cp.async.cg.shared.global [%0], [%1], 16;" :: "r"(dst), "l"(src))
#define CP_ASYNC_COMMIT() asm volatile("cp.async.commit_group;" ::: "memory")
#define CP_ASYNC_WAIT_ALL() asm volatile("cp.async.wait_group 0;" ::: "memory")

#define LDMATRIX_X4(r0, r1, r2, r3, addr) \
    asm volatile("ldmatrix.sync.aligned.m8n8.x4.shared.b16 {%0,%1,%2,%3}, [%4];" \
        : "=r"(r0), "=r"(r1), "=r"(r2), "=r"(r3) : "r"(addr))
#define LDMATRIX_X4_T(r0, r1, r2, r3, addr) \
    asm volatile("ldmatrix.sync.aligned.m8n8.x4.trans.shared.b16 {%0,%1,%2,%3}, [%4];" \
        : "=r"(r0), "=r"(r1), "=r"(r2), "=r"(r3) : "r"(addr))

#define MMA_BF16(cc, a0, a1, a2, a3, b0, b1) \
    asm volatile("mma.sync.aligned.m16n8k16.row.col.f32.bf16.bf16.f32 " \
        "{%0,%1,%2,%3}, {%4,%5,%6,%7}, {%8,%9}, {%0,%1,%2,%3};" \
        : "+f"((cc)[0]), "+f"((cc)[1]), "+f"((cc)[2]), "+f"((cc)[3]) \
        : "r"(a0), "r"(a1), "r"(a2), "r"(a3), "r"(b0), "r"(b1))

#define MMA_F16(cc, a0, a1, a2, a3, b0, b1) \
    asm volatile("mma.sync.aligned.m16n8k16.row.col.f32.f16.f16.f32 " \
        "{%0,%1,%2,%3}, {%4,%5,%6,%7}, {%8,%9}, {%0,%1,%2,%3};" \
        : "+f"((cc)[0]), "+f"((cc)[1]), "+f"((cc)[2]), "+f"((cc)[3]) \
        : "r"(a0), "r"(a1), "r"(a2), "r"(a3), "r"(b0), "r"(b1))

// ---------------------------------------------------------------------------
// Split kernels
// ---------------------------------------------------------------------------
__global__ void __launch_bounds__(256) split_x_kernel(const float* __restrict__ x) {
    int i = blockIdx.x * 256 + threadIdx.x;
    float v = x[i];
    __nv_bfloat16 hi = __float2bfloat16(v);
    g_xh[i] = hi;
    g_xl[i] = __float2bfloat16(v - __bfloat162float(hi));
    g_xf[i] = __float2half_rn(v);
}

__global__ void __launch_bounds__(256) split_w_kernel(
    const float* __restrict__ Wq, const float* __restrict__ Wk, const float* __restrict__ Wv)
{
    const float* W = (blockIdx.z == 0) ? Wq : (blockIdx.z == 1) ? Wk : Wv;
    __shared__ float t[32][33];
    int n0 = blockIdx.x * 32, k0 = blockIdx.y * 32;
    int tx = threadIdx.x, ty = threadIdx.y;   // block (32, 8)
    for (int r = ty; r < 32; r += 8)
        t[r][tx] = W[(size_t)(k0 + r) * DD + n0 + tx];
    __syncthreads();
    if (blockIdx.z < 2) {
        size_t base = (size_t)blockIdx.z * DD * DD;
        for (int r = ty; r < 32; r += 8) {
            float v = t[tx][r];
            __nv_bfloat16 hi = __float2bfloat16(v);
            size_t idx = base + (size_t)(n0 + r) * DD + k0 + tx;
            g_wth[idx] = hi;
            g_wtl[idx] = __float2bfloat16(v - __bfloat162float(hi));
        }
    } else {
        for (int r = ty; r < 32; r += 8) {
            size_t idx = (size_t)(n0 + r) * DD + k0 + tx;
            g_wvf[idx] = __float2half_rn(t[tx][r]);
        }
    }
}

// ---------------------------------------------------------------------------
// Projection via mma.sync. NEW: 128-thread CTAs (4 warps), tile 64M x 128N,
// warp tile 64M x 32N, 4 CTAs/SM (4 barrier domains — R12's flash lever).
// Q/K: 3-pass split-bf16; V: single fp16 pass. 2-stage cp.async ring.
// Stage: Ah 4K | Al 4K | Bh 8K | Bl 8K = 24KB. SMEM = 48KB -> 4 CTAs/SM.
// ---------------------------------------------------------------------------
#define BK 32
#define PSTG 24576
#define PROJ_SMEM (2*PSTG)               // 49152; Cs (64x132 fp32) overlays

__global__ void __launch_bounds__(128, 4) proj_mma_kernel(
    const float* __restrict__ bq, const float* __restrict__ bk, const float* __restrict__ bv)
{
    extern __shared__ __align__(1024) char smem[];
    const uint32_t smem_base = smem_to_u32(smem);
    float* Cs = (float*)smem;

    const int tid  = threadIdx.x;
    const int lane = tid & 31;
    const int wn   = tid >> 5;            // warp = n-slice 0..3

    const int ntile = blockIdx.x;         // 0..23
    const int mtile = blockIdx.y;         // 0..63
    const int wsel  = ntile >> 3;
    const int ncol0 = (ntile & 7) * 128;
    const int m0    = mtile * 64;

    // A loads: 64 rows x 32k x 2B = 4KB = 256 chunks; 2 per thread
    int la_sw[2]; size_t la_g[2];
    #pragma unroll
    for (int q = 0; q < 2; q++) {
        int id = q * 128 + tid;
        int row = id >> 2, c = id & 3;
        la_sw[q] = row * 64 + ((c ^ ((row >> 1) & 3)) << 4);
        la_g[q]  = (size_t)(m0 + row) * DD + c * 8;
    }
    // B loads: 128 rows x 32k x 2B = 8KB = 512 chunks; 4 per thread
    int lb_sw[4]; size_t lb_g[4];
    #pragma unroll
    for (int q = 0; q < 4; q++) {
        int id = q * 128 + tid;
        int row = id >> 2, c = id & 3;
        lb_sw[q] = row * 64 + ((c ^ ((row >> 1) & 3)) << 4);
        lb_g[q]  = (size_t)(ncol0 + row) * DD + c * 8;
    }

    int rA[4], gA[4];
    #pragma unroll
    for (int mt = 0; mt < 4; mt++) {
        rA[mt] = mt * 16 + (lane & 15);
        gA[mt] = (rA[mt] >> 1) & 3;
    }
    const int khalfA = lane >> 4;

    float acc[4][4][4];
    #pragma unroll
    for (int i = 0; i < 4; i++)
        #pragma unroll
        for (int j = 0; j < 4; j++)
            #pragma unroll
            for (int r = 0; r < 4; r++) acc[i][j][r] = 0.f;

    const int NKC = DD / BK;              // 32

    if (wsel < 2) {
        // ================= Q/K path: 3-pass split-bf16 =================
        const __nv_bfloat16* Ah_g = g_xh;
        const __nv_bfloat16* Al_g = g_xl;
        const __nv_bfloat16* Bh_g = g_wth + (size_t)wsel * DD * DD;
        const __nv_bfloat16* Bl_g = g_wtl + (size_t)wsel * DD * DD;

        {   // stage 0
            uint32_t sb = smem_base;
            #pragma unroll
            for (int q = 0; q < 2; q++) {
                CP_ASYNC_16(sb +        la_sw[q], Ah_g + la_g[q]);
                CP_ASYNC_16(sb + 4096 + la_sw[q], Al_g + la_g[q]);
            }
            #pragma unroll
            for (int q = 0; q < 4; q++) {
                CP_ASYNC_16(sb +  8192 + lb_sw[q], Bh_g + lb_g[q]);
                CP_ASYNC_16(sb + 16384 + lb_sw[q], Bl_g + lb_g[q]);
            }
            CP_ASYNC_COMMIT();
        }

        for (int kc = 0; kc < NKC; kc++) {
            CP_ASYNC_WAIT_ALL();
            __syncthreads();

            if (kc + 1 < NKC) {
                uint32_t sb = smem_base + ((kc + 1) & 1) * PSTG;
                size_t koff = (size_t)(kc + 1) * BK;
                #pragma unroll
                for (int q = 0; q < 2; q++) {
                    CP_ASYNC_16(sb +        la_sw[q], Ah_g + la_g[q] + koff);
                    CP_ASYNC_16(sb + 4096 + la_sw[q], Al_g + la_g[q] + koff);
                }
                #pragma unroll
                for (int q = 0; q < 4; q++) {
                    CP_ASYNC_16(sb +  8192 + lb_sw[q], Bh_g + lb_g[q] + koff);
                    CP_ASYNC_16(sb + 16384 + lb_sw[q], Bl_g + lb_g[q] + koff);
                }
                CP_ASYNC_COMMIT();
            }

            const uint32_t sb = smem_base + (kc & 1) * PSTG;
            const uint32_t ah = sb, al = sb + 4096, bh = sb + 8192, bl = sb + 16384;

            #pragma unroll
            for (int kf = 0; kf < 2; kf++) {
                const int cA = kf * 2 + khalfA;

                uint32_t B_h[4][2], B_l[4][2];
                #pragma unroll
                for (int ntp = 0; ntp < 2; ntp++) {
                    int row = wn * 32 + ntp * 16 + ((lane >> 4) & 1) * 8 + (lane & 7);
                    int chunk = kf * 2 + ((lane >> 3) & 1);
                    uint32_t boff = row * 64 + (((chunk ^ ((row >> 1) & 3))) << 4);
                    LDMATRIX_X4(B_h[2*ntp][0], B_h[2*ntp][1],
                                B_h[2*ntp+1][0], B_h[2*ntp+1][1], bh + boff);
                    LDMATRIX_X4(B_l[2*ntp][0], B_l[2*ntp][1],
                                B_l[2*ntp+1][0], B_l[2*ntp+1][1], bl + boff);
                }
                uint32_t A[4][4];
                #pragma unroll
                for (int mt = 0; mt < 4; mt++) {
                    uint32_t aoff = rA[mt] * 64 + (((cA ^ gA[mt])) << 4);
                    LDMATRIX_X4(A[mt][0], A[mt][1], A[mt][2], A[mt][3], ah + aoff);
                }
                #pragma unroll
                for (int mt = 0; mt < 4; mt++)
                    #pragma unroll
                    for (int nt = 0; nt < 4; nt++) {
                        MMA_BF16(acc[mt][nt], A[mt][0], A[mt][1], A[mt][2], A[mt][3],
                                 B_h[nt][0], B_h[nt][1]);
                        MMA_BF16(acc[mt][nt], A[mt][0], A[mt][1], A[mt][2], A[mt][3],
                                 B_l[nt][0], B_l[nt][1]);
                    }
                #pragma unroll
                for (int mt = 0; mt < 4; mt++) {
                    uint32_t aoff = rA[mt] * 64 + (((cA ^ gA[mt])) << 4);
                    LDMATRIX_X4(A[mt][0], A[mt][1], A[mt][2], A[mt][3], al + aoff);
                }
                #pragma unroll
                for (int mt = 0; mt < 4; mt++)
                    #pragma unroll
                    for (int nt = 0; nt < 4; nt++)
                        MMA_BF16(acc[mt][nt], A[mt][0], A[mt][1], A[mt][2], A[mt][3],
                                 B_h[nt][0], B_h[nt][1]);
            }
        }
    } else {
        // ================= V path: 1-pass fp16 =================
        const __half* Af_g = g_xf;
        const __half* Bf_g = g_wvf;

        {   // stage 0
            uint32_t sb = smem_base;
            #pragma unroll
            for (int q = 0; q < 2; q++)
                CP_ASYNC_16(sb + la_sw[q], Af_g + la_g[q]);
            #pragma unroll
            for (int q = 0; q < 4; q++)
                CP_ASYNC_16(sb + 8192 + lb_sw[q], Bf_g + lb_g[q]);
            CP_ASYNC_COMMIT();
        }

        for (int kc = 0; kc < NKC; kc++) {
            CP_ASYNC_WAIT_ALL();
            __syncthreads();

            if (kc + 1 < NKC) {
                uint32_t sb = smem_base + ((kc + 1) & 1) * PSTG;
                size_t koff = (size_t)(kc + 1) * BK;
                #pragma unroll
                for (int q = 0; q < 2; q++)
                    CP_ASYNC_16(sb + la_sw[q], Af_g + la_g[q] + koff);
                #pragma unroll
                for (int q = 0; q < 4; q++)
                    CP_ASYNC_16(sb + 8192 + lb_sw[q], Bf_g + lb_g[q] + koff);
                CP_ASYNC_COMMIT();
            }

            const uint32_t sb = smem_base + (kc & 1) * PSTG;
            const uint32_t af = sb, bf = sb + 8192;

            #pragma unroll
            for (int kf = 0; kf < 2; kf++) {
                const int cA = kf * 2 + khalfA;

                uint32_t B_f[4][2];
                #pragma unroll
                for (int ntp = 0; ntp < 2; ntp++) {
                    int row = wn * 32 + ntp * 16 + ((lane >> 4) & 1) * 8 + (lane & 7);
                    int chunk = kf * 2 + ((lane >> 3) & 1);
                    uint32_t boff = row * 64 + (((chunk ^ ((row >> 1) & 3))) << 4);
                    LDMATRIX_X4(B_f[2*ntp][0], B_f[2*ntp][1],
                                B_f[2*ntp+1][0], B_f[2*ntp+1][1], bf + boff);
                }
                uint32_t A[4][4];
                #pragma unroll
                for (int mt = 0; mt < 4; mt++) {
                    uint32_t aoff = rA[mt] * 64 + (((cA ^ gA[mt])) << 4);
                    LDMATRIX_X4(A[mt][0], A[mt][1], A[mt][2], A[mt][3], af + aoff);
                }
                #pragma unroll
                for (int mt = 0; mt < 4; mt++)
                    #pragma unroll
                    for (int nt = 0; nt < 4; nt++)
                        MMA_F16(acc[mt][nt], A[mt][0], A[mt][1], A[mt][2], A[mt][3],
                                B_f[nt][0], B_f[nt][1]);
            }
        }
    }
    __syncthreads();

    // ---- epilogue: bias (+GELU +log2e on Q), stage fp32, then store ----
    const float* bias = (wsel == 0) ? bq : (wsel == 1) ? bk : bv;

    const int fr = lane >> 2;
    const int fc = (lane & 3) * 2;
    #pragma unroll
    for (int mt = 0; mt < 4; mt++) {
        #pragma unroll
        for (int nt = 0; nt < 4; nt++) {
            int row0 = mt * 16 + fr;
            int col0 = wn * 32 + nt * 8 + fc;
            float b0 = bias[ncol0 + col0], b1 = bias[ncol0 + col0 + 1];
            #pragma unroll
            for (int half = 0; half < 2; half++) {
                int r = row0 + half * 8;
                float v0 = acc[mt][nt][half * 2 + 0] + b0;
                float v1 = acc[mt][nt][half * 2 + 1] + b1;
                if (wsel == 0) {
                    v0 = 0.5f * v0 * (1.0f + erff(v0 * 0.70710678118654752f));
                    v1 = 0.5f * v1 * (1.0f + erff(v1 * 0.70710678118654752f));
                    v0 *= 1.44269504088896340736f;   // log2(e): softmax in base-2
                    v1 *= 1.44269504088896340736f;
                }
                Cs[r * 132 + col0]     = v0;
                Cs[r * 132 + col0 + 1] = v1;
            }
        }
    }
    __syncthreads();

    const int b  = m0 >> 11;
    const int s0 = m0 & 2047;
    if (wsel < 2) {
        __nv_bfloat16* dsth = (wsel == 0) ? g_qh : g_kh;
        __nv_bfloat16* dstl = (wsel == 0) ? g_ql : g_kl;
        #pragma unroll
        for (int hb = 0; hb < 2; hb++) {
            int h = (ncol0 >> 6) + hb;
            size_t base = (((size_t)(b * HH + h)) * SS + s0) * DH;
            for (int i = tid; i < 64 * 64; i += 128) {
                int s = i >> 6, dh = i & 63;
                float v = Cs[s * 132 + hb * 64 + dh];
                __nv_bfloat16 hi = __float2bfloat16(v);
                dsth[base + (size_t)s * DH + dh] = hi;
                dstl[base + (size_t)s * DH + dh] =
                    __float2bfloat16(v - __bfloat162float(hi));
            }
        }
    } else {
        #pragma unroll
        for (int hb = 0; hb < 2; hb++) {
            int h = (ncol0 >> 6) + hb;
            size_t base = (((size_t)(b * HH + h)) * SS + s0) * DH;
            for (int i = tid; i < 64 * 64; i += 128) {
                int s = i >> 6, dh = i & 63;
                g_vf[base + (size_t)s * DH + dh] =
                    __float2half_rn(Cs[s * 132 + hb * 64 + dh]);
            }
        }
    }
}

// ---------------------------------------------------------------------------
// Flash attention via mma.sync (R13 config — best measured). 128-thread CTAs,
// 4 CTAs/SM, q-lo register-resident, q-hi 8KB smem, 2-stage KV ring,
// online max base-2, fp16 P via ex2.approx.f16x2, single fp16 PV pass.
// ---------------------------------------------------------------------------
#define FQT 64
#define FKT 64
#define FNIT (SS/FKT)
#define FQB 8192                        // Q-hi region
#define FST 24576                       // K/V stage stride (Kh|Kl|Vf x 8KB)
#define FLASH_SMEM (FQB + 2*FST)        // 57344 -> 4 CTAs/SM

__global__ void __launch_bounds__(128, 4) flash_mma_kernel(float* __restrict__ out)
{
    extern __shared__ __align__(1024) char smem[];
    const uint32_t sq = smem_to_u32(smem);      // Q hi
    const uint32_t sb = sq + FQB;               // K/V stages
    const int tid = threadIdx.x, lane = tid & 31, warp = tid >> 5;  // warp 0-3
    const int qb = blockIdx.x * FQT;
    const int h  = blockIdx.y, b = blockIdx.z;
    const size_t gbase = ((size_t)(b * HH + h)) * SS * DH;
    const __nv_bfloat16* Qh_g = g_qh + gbase;
    const __nv_bfloat16* Ql_g = g_ql + gbase;
    const __nv_bfloat16* Kh_g = g_kh + gbase;
    const __nv_bfloat16* Kl_g = g_kl + gbase;
    const __half*        Vf_g = g_vf + gbase;

    // ---- prologue: Qh -> sq, Ql -> stage0 area (temp), then extract ----
    {
        #pragma unroll
        for (int q = 0; q < 4; q++) {
            int id = q * 128 + tid;            // 512 chunks (64 rows x 8)
            int row = id >> 3, c = id & 7;
            uint32_t o = row * 128 + ((c ^ (row & 7)) << 4);
            size_t src = (size_t)(qb + row) * DH + c * 8;
            CP_ASYNC_16(sq + o, Qh_g + src);
            CP_ASYNC_16(sb + o, Ql_g + src);   // temp in stage-0 Kh slot
        }
        CP_ASYNC_COMMIT();
        CP_ASYNC_WAIT_ALL();
        __syncthreads();
    }
    // extract q-lo fragments to registers (resident)
    uint32_t ql[4][4];
    #pragma unroll
    for (int ks = 0; ks < 4; ks++) {
        int row = warp * 16 + (lane & 15);
        int chunk = 2 * ks + (lane >> 4);
        uint32_t addr = sb + row * 128 + ((chunk ^ (row & 7)) << 4);
        LDMATRIX_X4(ql[ks][0], ql[ks][1], ql[ks][2], ql[ks][3], addr);
    }
    __syncthreads();   // all warps extracted before KV overwrites stage 0

    // KV stage 0
    {
        #pragma unroll
        for (int q = 0; q < 4; q++) {
            int id = q * 128 + tid;
            int row = id >> 3, c = id & 7;
            uint32_t o = row * 128 + ((c ^ (row & 7)) << 4);
            size_t src = (size_t)row * DH + c * 8;
            CP_ASYNC_16(sb +         o, Kh_g + src);
            CP_ASYNC_16(sb +  8192 + o, Kl_g + src);
            CP_ASYNC_16(sb + 16384 + o, Vf_g + src);
        }
        CP_ASYNC_COMMIT();
    }

    float oacc[8][4];
    #pragma unroll
    for (int i = 0; i < 8; i++)
        #pragma unroll
        for (int j = 0; j < 4; j++) oacc[i][j] = 0.f;
    float m0r = -INFINITY, m1r = -INFINITY, l0 = 0.f, l1 = 0.f;

    for (int it = 0; it < FNIT; it++) {
        CP_ASYNC_WAIT_ALL();
        __syncthreads();

        if (it + 1 < FNIT) {
            uint32_t buf = sb + ((it + 1) & 1) * FST;
            size_t kadd = (size_t)(it + 1) * FKT * DH;
            #pragma unroll
            for (int q = 0; q < 4; q++) {
                int id = q * 128 + tid;
                int row = id >> 3, c = id & 7;
                uint32_t o = row * 128 + ((c ^ (row & 7)) << 4);
                size_t src = kadd + (size_t)row * DH + c * 8;
                CP_ASYNC_16(buf +         o, Kh_g + src);
                CP_ASYNC_16(buf +  8192 + o, Kl_g + src);
                CP_ASYNC_16(buf + 16384 + o, Vf_g + src);
            }
            CP_ASYNC_COMMIT();
        }

        const uint32_t buf = sb + (it & 1) * FST;
        const uint32_t kh = buf, kl = buf + 8192, vf = buf + 16384;

        // ---- S = Q K^T (3 split passes); q-hi from smem, q-lo resident ----
        float sacc[8][4];
        #pragma unroll
        for (int i = 0; i < 8; i++)
            #pragma unroll
            for (int j = 0; j < 4; j++) sacc[i][j] = 0.f;

        #pragma unroll
        for (int ks = 0; ks < 4; ks++) {
            int qrow = warp * 16 + (lane & 15);
            int qchunk = 2 * ks + (lane >> 4);
            uint32_t qaddr = sq + qrow * 128 + ((qchunk ^ (qrow & 7)) << 4);
            uint32_t qh0, qh1, qh2, qh3;
            LDMATRIX_X4(qh0, qh1, qh2, qh3, qaddr);
            #pragma unroll
            for (int ntp = 0; ntp < 4; ntp++) {
                int row = ntp * 16 + ((lane >> 4) & 1) * 8 + (lane & 7);
                int chunk = 2 * ks + ((lane >> 3) & 1);
                uint32_t addr = kh + row * 128 + ((chunk ^ (row & 7)) << 4);
                uint32_t bh0, bh1, bh2, bh3, bl0, bl1, bl2, bl3;
                LDMATRIX_X4(bh0, bh1, bh2, bh3, addr);
                LDMATRIX_X4(bl0, bl1, bl2, bl3, addr + 8192);
                MMA_BF16(sacc[2*ntp],   qh0, qh1, qh2, qh3, bh0, bh1);
                MMA_BF16(sacc[2*ntp],   ql[ks][0], ql[ks][1], ql[ks][2], ql[ks][3], bh0, bh1);
                MMA_BF16(sacc[2*ntp],   qh0, qh1, qh2, qh3, bl0, bl1);
                MMA_BF16(sacc[2*ntp+1], qh0, qh1, qh2, qh3, bh2, bh3);
                MMA_BF16(sacc[2*ntp+1], ql[ks][0], ql[ks][1], ql[ks][2], ql[ks][3], bh2, bh3);
                MMA_BF16(sacc[2*ntp+1], qh0, qh1, qh2, qh3, bl2, bl3);
            }
        }

        // ---- online softmax, base 2; exp via ex2.approx.f16x2 ----
        float tm0 = -INFINITY, tm1 = -INFINITY;
        #pragma unroll
        for (int nt = 0; nt < 8; nt++) {
            tm0 = fmaxf(tm0, fmaxf(sacc[nt][0], sacc[nt][1]));
            tm1 = fmaxf(tm1, fmaxf(sacc[nt][2], sacc[nt][3]));
        }
        tm0 = fmaxf(tm0, __shfl_xor_sync(0xffffffffu, tm0, 1));
        tm0 = fmaxf(tm0, __shfl_xor_sync(0xffffffffu, tm0, 2));
        tm1 = fmaxf(tm1, __shfl_xor_sync(0xffffffffu, tm1, 1));
        tm1 = fmaxf(tm1, __shfl_xor_sync(0xffffffffu, tm1, 2));
        float mn0 = fmaxf(m0r, tm0), mn1 = fmaxf(m1r, tm1);
        float a0 = ex2f(m0r - mn0), a1 = ex2f(m1r - mn1);
        m0r = mn0; m1r = mn1;

        float rs0 = 0.f, rs1 = 0.f;
        uint32_t ph[4][4];
        #pragma unroll
        for (int nt = 0; nt < 8; nt++) {
            uint32_t h2a = ex2_h2(sacc[nt][0] - mn0, sacc[nt][1] - mn0);
            uint32_t h2b = ex2_h2(sacc[nt][2] - mn1, sacc[nt][3] - mn1);
            int ks = nt >> 1, half = (nt & 1) * 2;
            ph[ks][half]     = h2a;
            ph[ks][half + 1] = h2b;
            float2 fa = __half22float2(*(__half2*)&h2a);
            float2 fb = __half22float2(*(__half2*)&h2b);
            rs0 += fa.x + fa.y;
            rs1 += fb.x + fb.y;
        }
        l0 = l0 * a0 + rs0;
        l1 = l1 * a1 + rs1;
        #pragma unroll
        for (int nt = 0; nt < 8; nt++) {
            oacc[nt][0] *= a0; oacc[nt][1] *= a0;
            oacc[nt][2] *= a1; oacc[nt][3] *= a1;
        }

        // ---- O += P V, single fp16 pass; V via ldmatrix.trans ----
        #pragma unroll
        for (int ks = 0; ks < 4; ks++) {
            #pragma unroll
            for (int ntp = 0; ntp < 4; ntp++) {
                int row = ks * 16 + ((lane >> 3) & 1) * 8 + (lane & 7);
                int chunk = 2 * ntp + (lane >> 4);
                uint32_t addr = vf + row * 128 + ((chunk ^ (row & 7)) << 4);
                uint32_t b0, b1, b2, b3;
                LDMATRIX_X4_T(b0, b1, b2, b3, addr);
                MMA_F16(oacc[2*ntp],   ph[ks][0], ph[ks][1], ph[ks][2], ph[ks][3], b0, b1);
                MMA_F16(oacc[2*ntp+1], ph[ks][0], ph[ks][1], ph[ks][2], ph[ks][3], b2, b3);
            }
        }
        // top-of-iteration barrier of it+1 orders these reads before the
        // prefetch that overwrites this buffer.
    }

    // ---- epilogue: reduce l across the 4-lane row group, store fp32 ----
    {
        l0 += __shfl_xor_sync(0xffffffffu, l0, 1);
        l0 += __shfl_xor_sync(0xffffffffu, l0, 2);
        l1 += __shfl_xor_sync(0xffffffffu, l1, 1);
        l1 += __shfl_xor_sync(0xffffffffu, l1, 2);
        const int r = lane >> 2, c2 = (lane & 3) * 2;
        float inv0 = 1.0f / l0, inv1 = 1.0f / l1;
        int row0 = qb + warp * 16 + r;
        size_t o0 = ((size_t)b * SS + row0) * DD + h * DH;
        size_t o1 = ((size_t)b * SS + row0 + 8) * DD + h * DH;
        #pragma unroll
        for (int nt = 0; nt < 8; nt++) {
            *(float2*)(out + o0 + nt * 8 + c2) =
                make_float2(oacc[nt][0] * inv0, oacc[nt][1] * inv0);
            *(float2*)(out + o1 + nt * 8 + c2) =
                make_float2(oacc[nt][2] * inv1, oacc[nt][3] * inv1);
        }
    }
}

// ---------------------------------------------------------------------------
extern "C" void kernel_launch(void* const* d_in, const int* in_sizes, int n_in,
                              void* d_out, int out_size) {
    const float* x  = (const float*)d_in[0];
    const float* Wq = (const float*)d_in[1];
    const float* bq = (const float*)d_in[2];
    const float* Wk = (const float*)d_in[3];
    const float* bk = (const float*)d_in[4];
    const float* Wv = (const float*)d_in[5];
    const float* bv = (const float*)d_in[6];
    float* out = (float*)d_out;

    split_x_kernel<<<M_TOTAL * DD / 256, 256>>>(x);
    split_w_kernel<<<dim3(DD/32, DD/32, 3), dim3(32, 8)>>>(Wq, Wk, Wv);

    cudaFuncSetAttribute(proj_mma_kernel,
                         cudaFuncAttributeMaxDynamicSharedMemorySize, PROJ_SMEM);
    proj_mma_kernel<<<dim3(N_TOTAL/128, M_TOTAL/64), 128, PROJ_SMEM>>>(bq, bk, bv);

    cudaFuncSetAttribute(flash_mma_kernel,
                         cudaFuncAttributeMaxDynamicSharedMemorySize, FLASH_SMEM);
    flash_mma_kernel<<<dim3(SS/FQT, HH, BB), 128, FLASH_SMEM>>>(out);
}

// round 15
// speedup vs baseline: 1.2222x; 1.0250x over previous
#include <cuda_runtime.h>
#include <cuda_bf16.h>
#include <cuda_fp16.h>
#include <math.h>
#include <cstdint>

#define BB 2
#define SS 2048
#define DD 1024
#define HH 16
#define DH 64
#define M_TOTAL (BB*SS)      // 4096
#define N_TOTAL (3*DD)       // 3072

// ---------------- device scratch (no cudaMalloc allowed) -------------------
__device__ __align__(16) __nv_bfloat16 g_xh[M_TOTAL*DD];
__device__ __align__(16) __nv_bfloat16 g_xl[M_TOTAL*DD];
__device__ __align__(16) __half        g_xf[M_TOTAL*DD];   // fp16 x (V proj)
__device__ __align__(16) __nv_bfloat16 g_wth[2*DD*DD];     // Wq^T, Wk^T hi
__device__ __align__(16) __nv_bfloat16 g_wtl[2*DD*DD];     // Wq^T, Wk^T lo
__device__ __align__(16) __half        g_wvf[DD*DD];       // Wv^T fp16
// projected Q/K bf16 hi/lo, V fp16, [B,H,S,DH]  (Q pre-scaled by log2(e))
__device__ __align__(16) __nv_bfloat16 g_qh[BB*HH*SS*DH];
__device__ __align__(16) __nv_bfloat16 g_ql[BB*HH*SS*DH];
__device__ __align__(16) __nv_bfloat16 g_kh[BB*HH*SS*DH];
__device__ __align__(16) __nv_bfloat16 g_kl[BB*HH*SS*DH];
__device__ __align__(16) __half        g_vf[BB*HH*SS*DH];

// ---------------- warp-mma helpers (plain sm_80+ PTX) ----------------------
__device__ __forceinline__ uint32_t smem_to_u32(const void* p) {
    uint32_t a;
    asm("{ .reg .u64 t; cvta.to.shared.u64 t, %1; cvt.u32.u64 %0, t; }"
        : "=r"(a) : "l"(p));
    return a;
}
__device__ __forceinline__ float ex2f(float x) {
    float y;
    asm("ex2.approx.f32 %0, %1;" : "=f"(y) : "f"(x));
    return y;
}
// pack two fp32 into f16x2 ({lo=a, hi=b}) and 2^x both halves in one MUFU op
__device__ __forceinline__ uint32_t ex2_h2(float a, float b) {
    uint32_t h2;
    asm("cvt.rn.f16x2.f32 %0, %1, %2;" : "=r"(h2) : "f"(b), "f"(a));
    asm("ex2.approx.f16x2 %0, %1;" : "=r"(h2) : "r"(h2));
    return h2;
}

#define CP_ASYNC_16(dst, src) \
    asm volatile("cp.async.cg.shared.global [%0], [%1], 16;" :: "r"(dst), "l"(src))
#define CP_ASYNC_COMMIT() asm volatile("cp.async.commit_group;" ::: "memory")
#define CP_ASYNC_WAIT_ALL() asm volatile("cp.async.wait_group 0;" ::: "memory")

#define LDMATRIX_X4(r0, r1, r2, r3, addr) \
    asm volatile("ldmatrix.sync.aligned.m8n8.x4.shared.b16 {%0,%1,%2,%3}, [%4];" \
        : "=r"(r0), "=r"(r1), "=r"(r2), "=r"(r3) : "r"(addr))
#define LDMATRIX_X4_T(r0, r1, r2, r3, addr) \
    asm volatile("ldmatrix.sync.aligned.m8n8.x4.trans.shared.b16 {%0,%1,%2,%3}, [%4];" \
        : "=r"(r0), "=r"(r1), "=r"(r2), "=r"(r3) : "r"(addr))

#define MMA_BF16(cc, a0, a1, a2, a3, b0, b1) \
    asm volatile("mma.sync.aligned.m16n8k16.row.col.f32.bf16.bf16.f32 " \
        "{%0,%1,%2,%3}, {%4,%5,%6,%7}, {%8,%9}, {%0,%1,%2,%3};" \
        : "+f"((cc)[0]), "+f"((cc)[1]), "+f"((cc)[2]), "+f"((cc)[3]) \
        : "r"(a0), "r"(a1), "r"(a2), "r"(a3), "r"(b0), "r"(b1))

#define MMA_F16(cc, a0, a1, a2, a3, b0, b1) \
    asm volatile("mma.sync.aligned.m16n8k16.row.col.f32.f16.f16.f32 " \
        "{%0,%1,%2,%3}, {%4,%5,%6,%7}, {%8,%9}, {%0,%1,%2,%3};" \
        : "+f"((cc)[0]), "+f"((cc)[1]), "+f"((cc)[2]), "+f"((cc)[3]) \
        : "r"(a0), "r"(a1), "r"(a2), "r"(a3), "r"(b0), "r"(b1))

// ---------------------------------------------------------------------------
// Split kernels
// ---------------------------------------------------------------------------
__global__ void __launch_bounds__(256) split_x_kernel(const float4* __restrict__ x) {
    int i = blockIdx.x * 256 + threadIdx.x;
    float4 v = x[i];
    __nv_bfloat162 h01 = __floats2bfloat162_rn(v.x, v.y);
    __nv_bfloat162 h23 = __floats2bfloat162_rn(v.z, v.w);
    float2 f01 = __bfloat1622float2(h01);
    float2 f23 = __bfloat1622float2(h23);
    __nv_bfloat162 l01 = __floats2bfloat162_rn(v.x - f01.x, v.y - f01.y);
    __nv_bfloat162 l23 = __floats2bfloat162_rn(v.z - f23.x, v.w - f23.y);
    ((__nv_bfloat162*)g_xh)[i*2]   = h01;
    ((__nv_bfloat162*)g_xh)[i*2+1] = h23;
    ((__nv_bfloat162*)g_xl)[i*2]   = l01;
    ((__nv_bfloat162*)g_xl)[i*2+1] = l23;
    __half2 p01 = __floats2half2_rn(v.x, v.y);
    __half2 p23 = __floats2half2_rn(v.z, v.w);
    ((__half2*)g_xf)[i*2]   = p01;
    ((__half2*)g_xf)[i*2+1] = p23;
}

__global__ void __launch_bounds__(256) split_w_kernel(
    const float* __restrict__ Wq, const float* __restrict__ Wk, const float* __restrict__ Wv)
{
    const float* W = (blockIdx.z == 0) ? Wq : (blockIdx.z == 1) ? Wk : Wv;
    __shared__ float t[32][33];
    int n0 = blockIdx.x * 32, k0 = blockIdx.y * 32;
    int tx = threadIdx.x, ty = threadIdx.y;   // block (32, 8)
    for (int r = ty; r < 32; r += 8)
        t[r][tx] = W[(size_t)(k0 + r) * DD + n0 + tx];
    __syncthreads();
    if (blockIdx.z < 2) {
        size_t base = (size_t)blockIdx.z * DD * DD;
        for (int r = ty; r < 32; r += 8) {
            float v = t[tx][r];
            __nv_bfloat16 hi = __float2bfloat16(v);
            size_t idx = base + (size_t)(n0 + r) * DD + k0 + tx;
            g_wth[idx] = hi;
            g_wtl[idx] = __float2bfloat16(v - __bfloat162float(hi));
        }
    } else {
        for (int r = ty; r < 32; r += 8) {
            size_t idx = (size_t)(n0 + r) * DD + k0 + tx;
            g_wvf[idx] = __float2half_rn(t[tx][r]);
        }
    }
}

// ---------------------------------------------------------------------------
// Projection via mma.sync (R14 config — best measured). 128-thread CTAs,
// tile 64M x 128N, 4 CTAs/SM. Q/K: 3-pass split-bf16; V: 1-pass fp16.
// ---------------------------------------------------------------------------
#define BK 32
#define PSTG 24576
#define PROJ_SMEM (2*PSTG)               // 49152; Cs (64x132 fp32) overlays

__global__ void __launch_bounds__(128, 4) proj_mma_kernel(
    const float* __restrict__ bq, const float* __restrict__ bk, const float* __restrict__ bv)
{
    extern __shared__ __align__(1024) char smem[];
    const uint32_t smem_base = smem_to_u32(smem);
    float* Cs = (float*)smem;

    const int tid  = threadIdx.x;
    const int lane = tid & 31;
    const int wn   = tid >> 5;            // warp = n-slice 0..3

    const int ntile = blockIdx.x;         // 0..23
    const int mtile = blockIdx.y;         // 0..63
    const int wsel  = ntile >> 3;
    const int ncol0 = (ntile & 7) * 128;
    const int m0    = mtile * 64;

    int la_sw[2]; size_t la_g[2];
    #pragma unroll
    for (int q = 0; q < 2; q++) {
        int id = q * 128 + tid;
        int row = id >> 2, c = id & 3;
        la_sw[q] = row * 64 + ((c ^ ((row >> 1) & 3)) << 4);
        la_g[q]  = (size_t)(m0 + row) * DD + c * 8;
    }
    int lb_sw[4]; size_t lb_g[4];
    #pragma unroll
    for (int q = 0; q < 4; q++) {
        int id = q * 128 + tid;
        int row = id >> 2, c = id & 3;
        lb_sw[q] = row * 64 + ((c ^ ((row >> 1) & 3)) << 4);
        lb_g[q]  = (size_t)(ncol0 + row) * DD + c * 8;
    }

    int rA[4], gA[4];
    #pragma unroll
    for (int mt = 0; mt < 4; mt++) {
        rA[mt] = mt * 16 + (lane & 15);
        gA[mt] = (rA[mt] >> 1) & 3;
    }
    const int khalfA = lane >> 4;

    float acc[4][4][4];
    #pragma unroll
    for (int i = 0; i < 4; i++)
        #pragma unroll
        for (int j = 0; j < 4; j++)
            #pragma unroll
            for (int r = 0; r < 4; r++) acc[i][j][r] = 0.f;

    const int NKC = DD / BK;              // 32

    if (wsel < 2) {
        // ================= Q/K path: 3-pass split-bf16 =================
        const __nv_bfloat16* Ah_g = g_xh;
        const __nv_bfloat16* Al_g = g_xl;
        const __nv_bfloat16* Bh_g = g_wth + (size_t)wsel * DD * DD;
        const __nv_bfloat16* Bl_g = g_wtl + (size_t)wsel * DD * DD;

        {
            uint32_t sb = smem_base;
            #pragma unroll
            for (int q = 0; q < 2; q++) {
                CP_ASYNC_16(sb +        la_sw[q], Ah_g + la_g[q]);
                CP_ASYNC_16(sb + 4096 + la_sw[q], Al_g + la_g[q]);
            }
            #pragma unroll
            for (int q = 0; q < 4; q++) {
                CP_ASYNC_16(sb +  8192 + lb_sw[q], Bh_g + lb_g[q]);
                CP_ASYNC_16(sb + 16384 + lb_sw[q], Bl_g + lb_g[q]);
            }
            CP_ASYNC_COMMIT();
        }

        for (int kc = 0; kc < NKC; kc++) {
            CP_ASYNC_WAIT_ALL();
            __syncthreads();

            if (kc + 1 < NKC) {
                uint32_t sb = smem_base + ((kc + 1) & 1) * PSTG;
                size_t koff = (size_t)(kc + 1) * BK;
                #pragma unroll
                for (int q = 0; q < 2; q++) {
                    CP_ASYNC_16(sb +        la_sw[q], Ah_g + la_g[q] + koff);
                    CP_ASYNC_16(sb + 4096 + la_sw[q], Al_g + la_g[q] + koff);
                }
                #pragma unroll
                for (int q = 0; q < 4; q++) {
                    CP_ASYNC_16(sb +  8192 + lb_sw[q], Bh_g + lb_g[q] + koff);
                    CP_ASYNC_16(sb + 16384 + lb_sw[q], Bl_g + lb_g[q] + koff);
                }
                CP_ASYNC_COMMIT();
            }

            const uint32_t sb = smem_base + (kc & 1) * PSTG;
            const uint32_t ah = sb, al = sb + 4096, bh = sb + 8192, bl = sb + 16384;

            #pragma unroll
            for (int kf = 0; kf < 2; kf++) {
                const int cA = kf * 2 + khalfA;

                uint32_t B_h[4][2], B_l[4][2];
                #pragma unroll
                for (int ntp = 0; ntp < 2; ntp++) {
                    int row = wn * 32 + ntp * 16 + ((lane >> 4) & 1) * 8 + (lane & 7);
                    int chunk = kf * 2 + ((lane >> 3) & 1);
                    uint32_t boff = row * 64 + (((chunk ^ ((row >> 1) & 3))) << 4);
                    LDMATRIX_X4(B_h[2*ntp][0], B_h[2*ntp][1],
                                B_h[2*ntp+1][0], B_h[2*ntp+1][1], bh + boff);
                    LDMATRIX_X4(B_l[2*ntp][0], B_l[2*ntp][1],
                                B_l[2*ntp+1][0], B_l[2*ntp+1][1], bl + boff);
                }
                uint32_t A[4][4];
                #pragma unroll
                for (int mt = 0; mt < 4; mt++) {
                    uint32_t aoff = rA[mt] * 64 + (((cA ^ gA[mt])) << 4);
                    LDMATRIX_X4(A[mt][0], A[mt][1], A[mt][2], A[mt][3], ah + aoff);
                }
                #pragma unroll
                for (int mt = 0; mt < 4; mt++)
                    #pragma unroll
                    for (int nt = 0; nt < 4; nt++) {
                        MMA_BF16(acc[mt][nt], A[mt][0], A[mt][1], A[mt][2], A[mt][3],
                                 B_h[nt][0], B_h[nt][1]);
                        MMA_BF16(acc[mt][nt], A[mt][0], A[mt][1], A[mt][2], A[mt][3],
                                 B_l[nt][0], B_l[nt][1]);
                    }
                #pragma unroll
                for (int mt = 0; mt < 4; mt++) {
                    uint32_t aoff = rA[mt] * 64 + (((cA ^ gA[mt])) << 4);
                    LDMATRIX_X4(A[mt][0], A[mt][1], A[mt][2], A[mt][3], al + aoff);
                }
                #pragma unroll
                for (int mt = 0; mt < 4; mt++)
                    #pragma unroll
                    for (int nt = 0; nt < 4; nt++)
                        MMA_BF16(acc[mt][nt], A[mt][0], A[mt][1], A[mt][2], A[mt][3],
                                 B_h[nt][0], B_h[nt][1]);
            }
        }
    } else {
        // ================= V path: 1-pass fp16 =================
        const __half* Af_g = g_xf;
        const __half* Bf_g = g_wvf;

        {
            uint32_t sb = smem_base;
            #pragma unroll
            for (int q = 0; q < 2; q++)
                CP_ASYNC_16(sb + la_sw[q], Af_g + la_g[q]);
            #pragma unroll
            for (int q = 0; q < 4; q++)
                CP_ASYNC_16(sb + 8192 + lb_sw[q], Bf_g + lb_g[q]);
            CP_ASYNC_COMMIT();
        }

        for (int kc = 0; kc < NKC; kc++) {
            CP_ASYNC_WAIT_ALL();
            __syncthreads();

            if (kc + 1 < NKC) {
                uint32_t sb = smem_base + ((kc + 1) & 1) * PSTG;
                size_t koff = (size_t)(kc + 1) * BK;
                #pragma unroll
                for (int q = 0; q < 2; q++)
                    CP_ASYNC_16(sb + la_sw[q], Af_g + la_g[q] + koff);
                #pragma unroll
                for (int q = 0; q < 4; q++)
                    CP_ASYNC_16(sb + 8192 + lb_sw[q], Bf_g + lb_g[q] + koff);
                CP_ASYNC_COMMIT();
            }

            const uint32_t sb = smem_base + (kc & 1) * PSTG;
            const uint32_t af = sb, bf = sb + 8192;

            #pragma unroll
            for (int kf = 0; kf < 2; kf++) {
                const int cA = kf * 2 + khalfA;

                uint32_t B_f[4][2];
                #pragma unroll
                for (int ntp = 0; ntp < 2; ntp++) {
                    int row = wn * 32 + ntp * 16 + ((lane >> 4) & 1) * 8 + (lane & 7);
                    int chunk = kf * 2 + ((lane >> 3) & 1);
                    uint32_t boff = row * 64 + (((chunk ^ ((row >> 1) & 3))) << 4);
                    LDMATRIX_X4(B_f[2*ntp][0], B_f[2*ntp][1],
                                B_f[2*ntp+1][0], B_f[2*ntp+1][1], bf + boff);
                }
                uint32_t A[4][4];
                #pragma unroll
                for (int mt = 0; mt < 4; mt++) {
                    uint32_t aoff = rA[mt] * 64 + (((cA ^ gA[mt])) << 4);
                    LDMATRIX_X4(A[mt][0], A[mt][1], A[mt][2], A[mt][3], af + aoff);
                }
                #pragma unroll
                for (int mt = 0; mt < 4; mt++)
                    #pragma unroll
                    for (int nt = 0; nt < 4; nt++)
                        MMA_F16(acc[mt][nt], A[mt][0], A[mt][1], A[mt][2], A[mt][3],
                                B_f[nt][0], B_f[nt][1]);
            }
        }
    }
    __syncthreads();

    // ---- epilogue: bias (+GELU +log2e on Q), stage fp32, then store ----
    const float* bias = (wsel == 0) ? bq : (wsel == 1) ? bk : bv;

    const int fr = lane >> 2;
    const int fc = (lane & 3) * 2;
    #pragma unroll
    for (int mt = 0; mt < 4; mt++) {
        #pragma unroll
        for (int nt = 0; nt < 4; nt++) {
            int row0 = mt * 16 + fr;
            int col0 = wn * 32 + nt * 8 + fc;
            float b0 = bias[ncol0 + col0], b1 = bias[ncol0 + col0 + 1];
            #pragma unroll
            for (int half = 0; half < 2; half++) {
                int r = row0 + half * 8;
                float v0 = acc[mt][nt][half * 2 + 0] + b0;
                float v1 = acc[mt][nt][half * 2 + 1] + b1;
                if (wsel == 0) {
                    v0 = 0.5f * v0 * (1.0f + erff(v0 * 0.70710678118654752f));
                    v1 = 0.5f * v1 * (1.0f + erff(v1 * 0.70710678118654752f));
                    v0 *= 1.44269504088896340736f;   // log2(e): softmax in base-2
                    v1 *= 1.44269504088896340736f;
                }
                Cs[r * 132 + col0]     = v0;
                Cs[r * 132 + col0 + 1] = v1;
            }
        }
    }
    __syncthreads();

    const int b  = m0 >> 11;
    const int s0 = m0 & 2047;
    if (wsel < 2) {
        __nv_bfloat16* dsth = (wsel == 0) ? g_qh : g_kh;
        __nv_bfloat16* dstl = (wsel == 0) ? g_ql : g_kl;
        #pragma unroll
        for (int hb = 0; hb < 2; hb++) {
            int h = (ncol0 >> 6) + hb;
            size_t base = (((size_t)(b * HH + h)) * SS + s0) * DH;
            for (int i = tid; i < 64 * 64; i += 128) {
                int s = i >> 6, dh = i & 63;
                float v = Cs[s * 132 + hb * 64 + dh];
                __nv_bfloat16 hi = __float2bfloat16(v);
                dsth[base + (size_t)s * DH + dh] = hi;
                dstl[base + (size_t)s * DH + dh] =
                    __float2bfloat16(v - __bfloat162float(hi));
            }
        }
    } else {
        #pragma unroll
        for (int hb = 0; hb < 2; hb++) {
            int h = (ncol0 >> 6) + hb;
            size_t base = (((size_t)(b * HH + h)) * SS + s0) * DH;
            for (int i = tid; i < 64 * 64; i += 128) {
                int s = i >> 6, dh = i & 63;
                g_vf[base + (size_t)s * DH + dh] =
                    __float2half_rn(Cs[s * 132 + hb * 64 + dh]);
            }
        }
    }
}

// ---------------------------------------------------------------------------
// Flash attention via mma.sync. 128-thread CTAs, 4 CTAs/SM, q-lo resident,
// q-hi 8KB smem, 2-stage KV ring, fp16 P via ex2.approx.f16x2, 1-pass PV.
// NEW: LAZY softmax rescale — m updates only when tile logits exceed m+12
// (p <= 2^12 fits fp16). Skipped iters avoid shuffles/a-ex2/rescale chain;
// arithmetic identical (a == 1 exactly on skipped iters).
// ---------------------------------------------------------------------------
#define FQT 64
#define FKT 64
#define FNIT (SS/FKT)
#define FQB 8192                        // Q-hi region
#define FST 24576                       // K/V stage stride (Kh|Kl|Vf x 8KB)
#define FLASH_SMEM (FQB + 2*FST)        // 57344 -> 4 CTAs/SM

__global__ void __launch_bounds__(128, 4) flash_mma_kernel(float* __restrict__ out)
{
    extern __shared__ __align__(1024) char smem[];
    const uint32_t sq = smem_to_u32(smem);      // Q hi
    const uint32_t sb = sq + FQB;               // K/V stages
    const int tid = threadIdx.x, lane = tid & 31, warp = tid >> 5;  // warp 0-3
    const int qb = blockIdx.x * FQT;
    const int h  = blockIdx.y, b = blockIdx.z;
    const size_t gbase = ((size_t)(b * HH + h)) * SS * DH;
    const __nv_bfloat16* Qh_g = g_qh + gbase;
    const __nv_bfloat16* Ql_g = g_ql + gbase;
    const __nv_bfloat16* Kh_g = g_kh + gbase;
    const __nv_bfloat16* Kl_g = g_kl + gbase;
    const __half*        Vf_g = g_vf + gbase;

    // ---- prologue: Qh -> sq, Ql -> stage0 area (temp), then extract ----
    {
        #pragma unroll
        for (int q = 0; q < 4; q++) {
            int id = q * 128 + tid;            // 512 chunks (64 rows x 8)
            int row = id >> 3, c = id & 7;
            uint32_t o = row * 128 + ((c ^ (row & 7)) << 4);
            size_t src = (size_t)(qb + row) * DH + c * 8;
            CP_ASYNC_16(sq + o, Qh_g + src);
            CP_ASYNC_16(sb + o, Ql_g + src);   // temp in stage-0 Kh slot
        }
        CP_ASYNC_COMMIT();
        CP_ASYNC_WAIT_ALL();
        __syncthreads();
    }
    // extract q-lo fragments to registers (resident)
    uint32_t ql[4][4];
    #pragma unroll
    for (int ks = 0; ks < 4; ks++) {
        int row = warp * 16 + (lane & 15);
        int chunk = 2 * ks + (lane >> 4);
        uint32_t addr = sb + row * 128 + ((chunk ^ (row & 7)) << 4);
        LDMATRIX_X4(ql[ks][0], ql[ks][1], ql[ks][2], ql[ks][3], addr);
    }
    __syncthreads();   // all warps extracted before KV overwrites stage 0

    // KV stage 0
    {
        #pragma unroll
        for (int q = 0; q < 4; q++) {
            int id = q * 128 + tid;
            int row = id >> 3, c = id & 7;
            uint32_t o = row * 128 + ((c ^ (row & 7)) << 4);
            size_t src = (size_t)row * DH + c * 8;
            CP_ASYNC_16(sb +         o, Kh_g + src);
            CP_ASYNC_16(sb +  8192 + o, Kl_g + src);
            CP_ASYNC_16(sb + 16384 + o, Vf_g + src);
        }
        CP_ASYNC_COMMIT();
    }

    float oacc[8][4];
    #pragma unroll
    for (int i = 0; i < 8; i++)
        #pragma unroll
        for (int j = 0; j < 4; j++) oacc[i][j] = 0.f;
    float m0r = -INFINITY, m1r = -INFINITY, l0 = 0.f, l1 = 0.f;

    for (int it = 0; it < FNIT; it++) {
        CP_ASYNC_WAIT_ALL();
        __syncthreads();

        if (it + 1 < FNIT) {
            uint32_t buf = sb + ((it + 1) & 1) * FST;
            size_t kadd = (size_t)(it + 1) * FKT * DH;
            #pragma unroll
            for (int q = 0; q < 4; q++) {
                int id = q * 128 + tid;
                int row = id >> 3, c = id & 7;
                uint32_t o = row * 128 + ((c ^ (row & 7)) << 4);
                size_t src = kadd + (size_t)row * DH + c * 8;
                CP_ASYNC_16(buf +         o, Kh_g + src);
                CP_ASYNC_16(buf +  8192 + o, Kl_g + src);
                CP_ASYNC_16(buf + 16384 + o, Vf_g + src);
            }
            CP_ASYNC_COMMIT();
        }

        const uint32_t buf = sb + (it & 1) * FST;
        const uint32_t kh = buf, kl = buf + 8192, vf = buf + 16384;

        // ---- S = Q K^T (3 split passes); q-hi from smem, q-lo resident ----
        float sacc[8][4];
        #pragma unroll
        for (int i = 0; i < 8; i++)
            #pragma unroll
            for (int j = 0; j < 4; j++) sacc[i][j] = 0.f;

        #pragma unroll
        for (int ks = 0; ks < 4; ks++) {
            int qrow = warp * 16 + (lane & 15);
            int qchunk = 2 * ks + (lane >> 4);
            uint32_t qaddr = sq + qrow * 128 + ((qchunk ^ (qrow & 7)) << 4);
            uint32_t qh0, qh1, qh2, qh3;
            LDMATRIX_X4(qh0, qh1, qh2, qh3, qaddr);
            #pragma unroll
            for (int ntp = 0; ntp < 4; ntp++) {
                int row = ntp * 16 + ((lane >> 4) & 1) * 8 + (lane & 7);
                int chunk = 2 * ks + ((lane >> 3) & 1);
                uint32_t addr = kh + row * 128 + ((chunk ^ (row & 7)) << 4);
                uint32_t bh0, bh1, bh2, bh3, bl0, bl1, bl2, bl3;
                LDMATRIX_X4(bh0, bh1, bh2, bh3, addr);
                LDMATRIX_X4(bl0, bl1, bl2, bl3, addr + 8192);
                MMA_BF16(sacc[2*ntp],   qh0, qh1, qh2, qh3, bh0, bh1);
                MMA_BF16(sacc[2*ntp],   ql[ks][0], ql[ks][1], ql[ks][2], ql[ks][3], bh0, bh1);
                MMA_BF16(sacc[2*ntp],   qh0, qh1, qh2, qh3, bl0, bl1);
                MMA_BF16(sacc[2*ntp+1], qh0, qh1, qh2, qh3, bh2, bh3);
                MMA_BF16(sacc[2*ntp+1], ql[ks][0], ql[ks][1], ql[ks][2], ql[ks][3], bh2, bh3);
                MMA_BF16(sacc[2*ntp+1], qh0, qh1, qh2, qh3, bl2, bl3);
            }
        }

        // ---- lazy online softmax, base 2 ----
        // per-lane local max (no shuffles yet)
        float tm0 = -INFINITY, tm1 = -INFINITY;
        #pragma unroll
        for (int nt = 0; nt < 8; nt++) {
            tm0 = fmaxf(tm0, fmaxf(sacc[nt][0], sacc[nt][1]));
            tm1 = fmaxf(tm1, fmaxf(sacc[nt][2], sacc[nt][3]));
        }
        // only rescale when p = 2^(s-m) could exceed 2^12 (fp16-safe slack)
        bool need = (tm0 > m0r + 12.f) || (tm1 > m1r + 12.f);
        if (__any_sync(0xffffffffu, need)) {
            tm0 = fmaxf(tm0, __shfl_xor_sync(0xffffffffu, tm0, 1));
            tm0 = fmaxf(tm0, __shfl_xor_sync(0xffffffffu, tm0, 2));
            tm1 = fmaxf(tm1, __shfl_xor_sync(0xffffffffu, tm1, 1));
            tm1 = fmaxf(tm1, __shfl_xor_sync(0xffffffffu, tm1, 2));
            float mn0 = fmaxf(m0r, tm0), mn1 = fmaxf(m1r, tm1);
            float a0 = ex2f(m0r - mn0), a1 = ex2f(m1r - mn1);
            m0r = mn0; m1r = mn1;
            l0 *= a0; l1 *= a1;
            #pragma unroll
            for (int nt = 0; nt < 8; nt++) {
                oacc[nt][0] *= a0; oacc[nt][1] *= a0;
                oacc[nt][2] *= a1; oacc[nt][3] *= a1;
            }
        }

        float rs0 = 0.f, rs1 = 0.f;
        uint32_t ph[4][4];
        #pragma unroll
        for (int nt = 0; nt < 8; nt++) {
            uint32_t h2a = ex2_h2(sacc[nt][0] - m0r, sacc[nt][1] - m0r);
            uint32_t h2b = ex2_h2(sacc[nt][2] - m1r, sacc[nt][3] - m1r);
            int ks = nt >> 1, half = (nt & 1) * 2;
            ph[ks][half]     = h2a;
            ph[ks][half + 1] = h2b;
            float2 fa = __half22float2(*(__half2*)&h2a);
            float2 fb = __half22float2(*(__half2*)&h2b);
            rs0 += fa.x + fa.y;
            rs1 += fb.x + fb.y;
        }
        l0 += rs0;
        l1 += rs1;

        // ---- O += P V, single fp16 pass; V via ldmatrix.trans ----
        #pragma unroll
        for (int ks = 0; ks < 4; ks++) {
            #pragma unroll
            for (int ntp = 0; ntp < 4; ntp++) {
                int row = ks * 16 + ((lane >> 3) & 1) * 8 + (lane & 7);
                int chunk = 2 * ntp + (lane >> 4);
                uint32_t addr = vf + row * 128 + ((chunk ^ (row & 7)) << 4);
                uint32_t b0, b1, b2, b3;
                LDMATRIX_X4_T(b0, b1, b2, b3, addr);
                MMA_F16(oacc[2*ntp],   ph[ks][0], ph[ks][1], ph[ks][2], ph[ks][3], b0, b1);
                MMA_F16(oacc[2*ntp+1], ph[ks][0], ph[ks][1], ph[ks][2], ph[ks][3], b2, b3);
            }
        }
        // top-of-iteration barrier of it+1 orders these reads before the
        // prefetch that overwrites this buffer.
    }

    // ---- epilogue: reduce l across the 4-lane row group, store fp32 ----
    {
        l0 += __shfl_xor_sync(0xffffffffu, l0, 1);
        l0 += __shfl_xor_sync(0xffffffffu, l0, 2);
        l1 += __shfl_xor_sync(0xffffffffu, l1, 1);
        l1 += __shfl_xor_sync(0xffffffffu, l1, 2);
        const int r = lane >> 2, c2 = (lane & 3) * 2;
        float inv0 = 1.0f / l0, inv1 = 1.0f / l1;
        int row0 = qb + warp * 16 + r;
        size_t o0 = ((size_t)b * SS + row0) * DD + h * DH;
        size_t o1 = ((size_t)b * SS + row0 + 8) * DD + h * DH;
        #pragma unroll
        for (int nt = 0; nt < 8; nt++) {
            *(float2*)(out + o0 + nt * 8 + c2) =
                make_float2(oacc[nt][0] * inv0, oacc[nt][1] * inv0);
            *(float2*)(out + o1 + nt * 8 + c2) =
                make_float2(oacc[nt][2] * inv1, oacc[nt][3] * inv1);
        }
    }
}

// ---------------------------------------------------------------------------
extern "C" void kernel_launch(void* const* d_in, const int* in_sizes, int n_in,
                              void* d_out, int out_size) {
    const float* x  = (const float*)d_in[0];
    const float* Wq = (const float*)d_in[1];
    const float* bq = (const float*)d_in[2];
    const float* Wk = (const float*)d_in[3];
    const float* bk = (const float*)d_in[4];
    const float* Wv = (const float*)d_in[5];
    const float* bv = (const float*)d_in[6];
    float* out = (float*)d_out;

    split_x_kernel<<<M_TOTAL * DD / 1024, 256>>>((const float4*)x);
    split_w_kernel<<<dim3(DD/32, DD/32, 3), dim3(32, 8)>>>(Wq, Wk, Wv);

    cudaFuncSetAttribute(proj_mma_kernel,
                         cudaFuncAttributeMaxDynamicSharedMemorySize, PROJ_SMEM);
    proj_mma_kernel<<<dim3(N_TOTAL/128, M_TOTAL/64), 128, PROJ_SMEM>>>(bq, bk, bv);

    cudaFuncSetAttribute(flash_mma_kernel,
                         cudaFuncAttributeMaxDynamicSharedMemorySize, FLASH_SMEM);
    flash_mma_kernel<<<dim3(SS/FQT, HH, BB), 128, FLASH_SMEM>>>(out);
}

// round 16
// speedup vs baseline: 1.2796x; 1.0469x over previous
#include <cuda_runtime.h>
#include <cuda_bf16.h>
#include <cuda_fp16.h>
#include <math.h>
#include <cstdint>

#define BB 2
#define SS 2048
#define DD 1024
#define HH 16
#define DH 64
#define M_TOTAL (BB*SS)      // 4096
#define N_TOTAL (3*DD)       // 3072

// ---------------- device scratch (no cudaMalloc allowed) -------------------
__device__ __align__(16) __nv_bfloat16 g_xh[M_TOTAL*DD];
__device__ __align__(16) __nv_bfloat16 g_xl[M_TOTAL*DD];
__device__ __align__(16) __half        g_xf[M_TOTAL*DD];   // fp16 x (V proj)
__device__ __align__(16) __nv_bfloat16 g_wth[2*DD*DD];     // Wq^T, Wk^T hi
__device__ __align__(16) __nv_bfloat16 g_wtl[2*DD*DD];     // Wq^T, Wk^T lo
__device__ __align__(16) __half        g_wvf[DD*DD];       // Wv^T fp16
// projected Q/K bf16 hi/lo, V fp16, [B,H,S,DH]  (Q pre-scaled by log2(e))
__device__ __align__(16) __nv_bfloat16 g_qh[BB*HH*SS*DH];
__device__ __align__(16) __nv_bfloat16 g_ql[BB*HH*SS*DH];
__device__ __align__(16) __nv_bfloat16 g_kh[BB*HH*SS*DH];
__device__ __align__(16) __nv_bfloat16 g_kl[BB*HH*SS*DH];
__device__ __align__(16) __half        g_vf[BB*HH*SS*DH];

// ---------------- warp-mma helpers (plain sm_80+ PTX) ----------------------
__device__ __forceinline__ uint32_t smem_to_u32(const void* p) {
    uint32_t a;
    asm("{ .reg .u64 t; cvta.to.shared.u64 t, %1; cvt.u32.u64 %0, t; }"
        : "=r"(a) : "l"(p));
    return a;
}
__device__ __forceinline__ float ex2f(float x) {
    float y;
    asm("ex2.approx.f32 %0, %1;" : "=f"(y) : "f"(x));
    return y;
}
__device__ __forceinline__ uint32_t pack_h2(float a, float b) {
    uint32_t h2;
    asm("cvt.rn.f16x2.f32 %0, %1, %2;" : "=r"(h2) : "f"(b), "f"(a));
    return h2;
}

#define CP_ASYNC_16(dst, src) \
    asm volatile("cp.async.cg.shared.global [%0], [%1], 16;" :: "r"(dst), "l"(src))
#define CP_ASYNC_COMMIT() asm volatile("cp.async.commit_group;" ::: "memory")
#define CP_ASYNC_WAIT_ALL() asm volatile("cp.async.wait_group 0;" ::: "memory")

#define LDMATRIX_X4(r0, r1, r2, r3, addr) \
    asm volatile("ldmatrix.sync.aligned.m8n8.x4.shared.b16 {%0,%1,%2,%3}, [%4];" \
        : "=r"(r0), "=r"(r1), "=r"(r2), "=r"(r3) : "r"(addr))
#define LDMATRIX_X4_T(r0, r1, r2, r3, addr) \
    asm volatile("ldmatrix.sync.aligned.m8n8.x4.trans.shared.b16 {%0,%1,%2,%3}, [%4];" \
        : "=r"(r0), "=r"(r1), "=r"(r2), "=r"(r3) : "r"(addr))

#define MMA_BF16(cc, a0, a1, a2, a3, b0, b1) \
    asm volatile("mma.sync.aligned.m16n8k16.row.col.f32.bf16.bf16.f32 " \
        "{%0,%1,%2,%3}, {%4,%5,%6,%7}, {%8,%9}, {%0,%1,%2,%3};" \
        : "+f"((cc)[0]), "+f"((cc)[1]), "+f"((cc)[2]), "+f"((cc)[3]) \
        : "r"(a0), "r"(a1), "r"(a2), "r"(a3), "r"(b0), "r"(b1))

#define MMA_F16(cc, a0, a1, a2, a3, b0, b1) \
    asm volatile("mma.sync.aligned.m16n8k16.row.col.f32.f16.f16.f32 " \
        "{%0,%1,%2,%3}, {%4,%5,%6,%7}, {%8,%9}, {%0,%1,%2,%3};" \
        : "+f"((cc)[0]), "+f"((cc)[1]), "+f"((cc)[2]), "+f"((cc)[3]) \
        : "r"(a0), "r"(a1), "r"(a2), "r"(a3), "r"(b0), "r"(b1))

// ---------------------------------------------------------------------------
// Split kernels
// ---------------------------------------------------------------------------
__global__ void __launch_bounds__(256) split_x_kernel(const float4* __restrict__ x) {
    int i = blockIdx.x * 256 + threadIdx.x;
    float4 v = x[i];
    __nv_bfloat162 h01 = __floats2bfloat162_rn(v.x, v.y);
    __nv_bfloat162 h23 = __floats2bfloat162_rn(v.z, v.w);
    float2 f01 = __bfloat1622float2(h01);
    float2 f23 = __bfloat1622float2(h23);
    __nv_bfloat162 l01 = __floats2bfloat162_rn(v.x - f01.x, v.y - f01.y);
    __nv_bfloat162 l23 = __floats2bfloat162_rn(v.z - f23.x, v.w - f23.y);
    ((__nv_bfloat162*)g_xh)[i*2]   = h01;
    ((__nv_bfloat162*)g_xh)[i*2+1] = h23;
    ((__nv_bfloat162*)g_xl)[i*2]   = l01;
    ((__nv_bfloat162*)g_xl)[i*2+1] = l23;
    __half2 p01 = __floats2half2_rn(v.x, v.y);
    __half2 p23 = __floats2half2_rn(v.z, v.w);
    ((__half2*)g_xf)[i*2]   = p01;
    ((__half2*)g_xf)[i*2+1] = p23;
}

__global__ void __launch_bounds__(256) split_w_kernel(
    const float* __restrict__ Wq, const float* __restrict__ Wk, const float* __restrict__ Wv)
{
    const float* W = (blockIdx.z == 0) ? Wq : (blockIdx.z == 1) ? Wk : Wv;
    __shared__ float t[32][33];
    int n0 = blockIdx.x * 32, k0 = blockIdx.y * 32;
    int tx = threadIdx.x, ty = threadIdx.y;   // block (32, 8)
    for (int r = ty; r < 32; r += 8)
        t[r][tx] = W[(size_t)(k0 + r) * DD + n0 + tx];
    __syncthreads();
    if (blockIdx.z < 2) {
        size_t base = (size_t)blockIdx.z * DD * DD;
        for (int r = ty; r < 32; r += 8) {
            float v = t[tx][r];
            __nv_bfloat16 hi = __float2bfloat16(v);
            size_t idx = base + (size_t)(n0 + r) * DD + k0 + tx;
            g_wth[idx] = hi;
            g_wtl[idx] = __float2bfloat16(v - __bfloat162float(hi));
        }
    } else {
        for (int r = ty; r < 32; r += 8) {
            size_t idx = (size_t)(n0 + r) * DD + k0 + tx;
            g_wvf[idx] = __float2half_rn(t[tx][r]);
        }
    }
}

// ---------------------------------------------------------------------------
// Projection via mma.sync. 128-thread CTAs, tile 64M x 128N, 4 CTAs/SM.
// Q/K: 3-pass split-bf16; V: 1-pass fp16. NEW: 1-D LPT grid — heavy Q/K
// tiles first (bids 0..1023), light V tiles last (1024..1535) so the light
// tiles drain into the final-wave tail.
// ---------------------------------------------------------------------------
#define BK 32
#define PSTG 24576
#define PROJ_SMEM (2*PSTG)               // 49152; Cs (64x132 fp32) overlays

__global__ void __launch_bounds__(128, 4) proj_mma_kernel(
    const float* __restrict__ bq, const float* __restrict__ bk, const float* __restrict__ bv)
{
    extern __shared__ __align__(1024) char smem[];
    const uint32_t smem_base = smem_to_u32(smem);
    float* Cs = (float*)smem;

    const int tid  = threadIdx.x;
    const int lane = tid & 31;
    const int wn   = tid >> 5;            // warp = n-slice 0..3

    // LPT mapping: heavy tiles (Q/K) on low bids, light (V) on high bids
    int wsel, n8, mtile;
    {
        int bid = blockIdx.x;
        if (bid < 1024) { wsel = bid & 1; n8 = (bid >> 1) & 7; mtile = bid >> 4; }
        else            { int v = bid - 1024; wsel = 2; n8 = v & 7; mtile = v >> 3; }
    }
    const int ncol0 = n8 * 128;
    const int m0    = mtile * 64;

    int la_sw[2]; size_t la_g[2];
    #pragma unroll
    for (int q = 0; q < 2; q++) {
        int id = q * 128 + tid;
        int row = id >> 2, c = id & 3;
        la_sw[q] = row * 64 + ((c ^ ((row >> 1) & 3)) << 4);
        la_g[q]  = (size_t)(m0 + row) * DD + c * 8;
    }
    int lb_sw[4]; size_t lb_g[4];
    #pragma unroll
    for (int q = 0; q < 4; q++) {
        int id = q * 128 + tid;
        int row = id >> 2, c = id & 3;
        lb_sw[q] = row * 64 + ((c ^ ((row >> 1) & 3)) << 4);
        lb_g[q]  = (size_t)(ncol0 + row) * DD + c * 8;
    }

    int rA[4], gA[4];
    #pragma unroll
    for (int mt = 0; mt < 4; mt++) {
        rA[mt] = mt * 16 + (lane & 15);
        gA[mt] = (rA[mt] >> 1) & 3;
    }
    const int khalfA = lane >> 4;

    float acc[4][4][4];
    #pragma unroll
    for (int i = 0; i < 4; i++)
        #pragma unroll
        for (int j = 0; j < 4; j++)
            #pragma unroll
            for (int r = 0; r < 4; r++) acc[i][j][r] = 0.f;

    const int NKC = DD / BK;              // 32

    if (wsel < 2) {
        // ================= Q/K path: 3-pass split-bf16 =================
        const __nv_bfloat16* Ah_g = g_xh;
        const __nv_bfloat16* Al_g = g_xl;
        const __nv_bfloat16* Bh_g = g_wth + (size_t)wsel * DD * DD;
        const __nv_bfloat16* Bl_g = g_wtl + (size_t)wsel * DD * DD;

        {
            uint32_t sb = smem_base;
            #pragma unroll
            for (int q = 0; q < 2; q++) {
                CP_ASYNC_16(sb +        la_sw[q], Ah_g + la_g[q]);
                CP_ASYNC_16(sb + 4096 + la_sw[q], Al_g + la_g[q]);
            }
            #pragma unroll
            for (int q = 0; q < 4; q++) {
                CP_ASYNC_16(sb +  8192 + lb_sw[q], Bh_g + lb_g[q]);
                CP_ASYNC_16(sb + 16384 + lb_sw[q], Bl_g + lb_g[q]);
            }
            CP_ASYNC_COMMIT();
        }

        for (int kc = 0; kc < NKC; kc++) {
            CP_ASYNC_WAIT_ALL();
            __syncthreads();

            if (kc + 1 < NKC) {
                uint32_t sb = smem_base + ((kc + 1) & 1) * PSTG;
                size_t koff = (size_t)(kc + 1) * BK;
                #pragma unroll
                for (int q = 0; q < 2; q++) {
                    CP_ASYNC_16(sb +        la_sw[q], Ah_g + la_g[q] + koff);
                    CP_ASYNC_16(sb + 4096 + la_sw[q], Al_g + la_g[q] + koff);
                }
                #pragma unroll
                for (int q = 0; q < 4; q++) {
                    CP_ASYNC_16(sb +  8192 + lb_sw[q], Bh_g + lb_g[q] + koff);
                    CP_ASYNC_16(sb + 16384 + lb_sw[q], Bl_g + lb_g[q] + koff);
                }
                CP_ASYNC_COMMIT();
            }

            const uint32_t sb = smem_base + (kc & 1) * PSTG;
            const uint32_t ah = sb, al = sb + 4096, bh = sb + 8192, bl = sb + 16384;

            #pragma unroll
            for (int kf = 0; kf < 2; kf++) {
                const int cA = kf * 2 + khalfA;

                uint32_t B_h[4][2], B_l[4][2];
                #pragma unroll
                for (int ntp = 0; ntp < 2; ntp++) {
                    int row = wn * 32 + ntp * 16 + ((lane >> 4) & 1) * 8 + (lane & 7);
                    int chunk = kf * 2 + ((lane >> 3) & 1);
                    uint32_t boff = row * 64 + (((chunk ^ ((row >> 1) & 3))) << 4);
                    LDMATRIX_X4(B_h[2*ntp][0], B_h[2*ntp][1],
                                B_h[2*ntp+1][0], B_h[2*ntp+1][1], bh + boff);
                    LDMATRIX_X4(B_l[2*ntp][0], B_l[2*ntp][1],
                                B_l[2*ntp+1][0], B_l[2*ntp+1][1], bl + boff);
                }
                uint32_t A[4][4];
                #pragma unroll
                for (int mt = 0; mt < 4; mt++) {
                    uint32_t aoff = rA[mt] * 64 + (((cA ^ gA[mt])) << 4);
                    LDMATRIX_X4(A[mt][0], A[mt][1], A[mt][2], A[mt][3], ah + aoff);
                }
                #pragma unroll
                for (int mt = 0; mt < 4; mt++)
                    #pragma unroll
                    for (int nt = 0; nt < 4; nt++) {
                        MMA_BF16(acc[mt][nt], A[mt][0], A[mt][1], A[mt][2], A[mt][3],
                                 B_h[nt][0], B_h[nt][1]);
                        MMA_BF16(acc[mt][nt], A[mt][0], A[mt][1], A[mt][2], A[mt][3],
                                 B_l[nt][0], B_l[nt][1]);
                    }
                #pragma unroll
                for (int mt = 0; mt < 4; mt++) {
                    uint32_t aoff = rA[mt] * 64 + (((cA ^ gA[mt])) << 4);
                    LDMATRIX_X4(A[mt][0], A[mt][1], A[mt][2], A[mt][3], al + aoff);
                }
                #pragma unroll
                for (int mt = 0; mt < 4; mt++)
                    #pragma unroll
                    for (int nt = 0; nt < 4; nt++)
                        MMA_BF16(acc[mt][nt], A[mt][0], A[mt][1], A[mt][2], A[mt][3],
                                 B_h[nt][0], B_h[nt][1]);
            }
        }
    } else {
        // ================= V path: 1-pass fp16 =================
        const __half* Af_g = g_xf;
        const __half* Bf_g = g_wvf;

        {
            uint32_t sb = smem_base;
            #pragma unroll
            for (int q = 0; q < 2; q++)
                CP_ASYNC_16(sb + la_sw[q], Af_g + la_g[q]);
            #pragma unroll
            for (int q = 0; q < 4; q++)
                CP_ASYNC_16(sb + 8192 + lb_sw[q], Bf_g + lb_g[q]);
            CP_ASYNC_COMMIT();
        }

        for (int kc = 0; kc < NKC; kc++) {
            CP_ASYNC_WAIT_ALL();
            __syncthreads();

            if (kc + 1 < NKC) {
                uint32_t sb = smem_base + ((kc + 1) & 1) * PSTG;
                size_t koff = (size_t)(kc + 1) * BK;
                #pragma unroll
                for (int q = 0; q < 2; q++)
                    CP_ASYNC_16(sb + la_sw[q], Af_g + la_g[q] + koff);
                #pragma unroll
                for (int q = 0; q < 4; q++)
                    CP_ASYNC_16(sb + 8192 + lb_sw[q], Bf_g + lb_g[q] + koff);
                CP_ASYNC_COMMIT();
            }

            const uint32_t sb = smem_base + (kc & 1) * PSTG;
            const uint32_t af = sb, bf = sb + 8192;

            #pragma unroll
            for (int kf = 0; kf < 2; kf++) {
                const int cA = kf * 2 + khalfA;

                uint32_t B_f[4][2];
                #pragma unroll
                for (int ntp = 0; ntp < 2; ntp++) {
                    int row = wn * 32 + ntp * 16 + ((lane >> 4) & 1) * 8 + (lane & 7);
                    int chunk = kf * 2 + ((lane >> 3) & 1);
                    uint32_t boff = row * 64 + (((chunk ^ ((row >> 1) & 3))) << 4);
                    LDMATRIX_X4(B_f[2*ntp][0], B_f[2*ntp][1],
                                B_f[2*ntp+1][0], B_f[2*ntp+1][1], bf + boff);
                }
                uint32_t A[4][4];
                #pragma unroll
                for (int mt = 0; mt < 4; mt++) {
                    uint32_t aoff = rA[mt] * 64 + (((cA ^ gA[mt])) << 4);
                    LDMATRIX_X4(A[mt][0], A[mt][1], A[mt][2], A[mt][3], af + aoff);
                }
                #pragma unroll
                for (int mt = 0; mt < 4; mt++)
                    #pragma unroll
                    for (int nt = 0; nt < 4; nt++)
                        MMA_F16(acc[mt][nt], A[mt][0], A[mt][1], A[mt][2], A[mt][3],
                                B_f[nt][0], B_f[nt][1]);
            }
        }
    }
    __syncthreads();

    // ---- epilogue: bias (+GELU +log2e on Q), stage fp32, then store ----
    const float* bias = (wsel == 0) ? bq : (wsel == 1) ? bk : bv;

    const int fr = lane >> 2;
    const int fc = (lane & 3) * 2;
    #pragma unroll
    for (int mt = 0; mt < 4; mt++) {
        #pragma unroll
        for (int nt = 0; nt < 4; nt++) {
            int row0 = mt * 16 + fr;
            int col0 = wn * 32 + nt * 8 + fc;
            float b0 = bias[ncol0 + col0], b1 = bias[ncol0 + col0 + 1];
            #pragma unroll
            for (int half = 0; half < 2; half++) {
                int r = row0 + half * 8;
                float v0 = acc[mt][nt][half * 2 + 0] + b0;
                float v1 = acc[mt][nt][half * 2 + 1] + b1;
                if (wsel == 0) {
                    v0 = 0.5f * v0 * (1.0f + erff(v0 * 0.70710678118654752f));
                    v1 = 0.5f * v1 * (1.0f + erff(v1 * 0.70710678118654752f));
                    v0 *= 1.44269504088896340736f;   // log2(e): softmax in base-2
                    v1 *= 1.44269504088896340736f;
                }
                Cs[r * 132 + col0]     = v0;
                Cs[r * 132 + col0 + 1] = v1;
            }
        }
    }
    __syncthreads();

    const int b  = m0 >> 11;
    const int s0 = m0 & 2047;
    if (wsel < 2) {
        __nv_bfloat16* dsth = (wsel == 0) ? g_qh : g_kh;
        __nv_bfloat16* dstl = (wsel == 0) ? g_ql : g_kl;
        #pragma unroll
        for (int hb = 0; hb < 2; hb++) {
            int h = (ncol0 >> 6) + hb;
            size_t base = (((size_t)(b * HH + h)) * SS + s0) * DH;
            for (int i = tid; i < 64 * 64; i += 128) {
                int s = i >> 6, dh = i & 63;
                float v = Cs[s * 132 + hb * 64 + dh];
                __nv_bfloat16 hi = __float2bfloat16(v);
                dsth[base + (size_t)s * DH + dh] = hi;
                dstl[base + (size_t)s * DH + dh] =
                    __float2bfloat16(v - __bfloat162float(hi));
            }
        }
    } else {
        #pragma unroll
        for (int hb = 0; hb < 2; hb++) {
            int h = (ncol0 >> 6) + hb;
            size_t base = (((size_t)(b * HH + h)) * SS + s0) * DH;
            for (int i = tid; i < 64 * 64; i += 128) {
                int s = i >> 6, dh = i & 63;
                g_vf[base + (size_t)s * DH + dh] =
                    __float2half_rn(Cs[s * 132 + hb * 64 + dh]);
            }
        }
    }
}

// ---------------------------------------------------------------------------
// Flash attention via mma.sync. 128-thread CTAs, 4 CTAs/SM, q-lo resident,
// q-hi 8KB smem, 2-stage KV ring, 1-pass fp16 PV. Lazy softmax rescale
// (12-unit slack, trigger-only reduce); exp computed with FP32 input
// (ex2.approx.f32) to avoid fp16 d-quantization, packed fp16 for the MMA.
// ---------------------------------------------------------------------------
#define FQT 64
#define FKT 64
#define FNIT (SS/FKT)
#define FQB 8192                        // Q-hi region
#define FST 24576                       // K/V stage stride (Kh|Kl|Vf x 8KB)
#define FLASH_SMEM (FQB + 2*FST)        // 57344 -> 4 CTAs/SM

__global__ void __launch_bounds__(128, 4) flash_mma_kernel(float* __restrict__ out)
{
    extern __shared__ __align__(1024) char smem[];
    const uint32_t sq = smem_to_u32(smem);      // Q hi
    const uint32_t sb = sq + FQB;               // K/V stages
    const int tid = threadIdx.x, lane = tid & 31, warp = tid >> 5;  // warp 0-3
    const int qb = blockIdx.x * FQT;
    const int h  = blockIdx.y, b = blockIdx.z;
    const size_t gbase = ((size_t)(b * HH + h)) * SS * DH;
    const __nv_bfloat16* Qh_g = g_qh + gbase;
    const __nv_bfloat16* Ql_g = g_ql + gbase;
    const __nv_bfloat16* Kh_g = g_kh + gbase;
    const __nv_bfloat16* Kl_g = g_kl + gbase;
    const __half*        Vf_g = g_vf + gbase;

    // ---- prologue: Qh -> sq, Ql -> stage0 area (temp), then extract ----
    {
        #pragma unroll
        for (int q = 0; q < 4; q++) {
            int id = q * 128 + tid;            // 512 chunks (64 rows x 8)
            int row = id >> 3, c = id & 7;
            uint32_t o = row * 128 + ((c ^ (row & 7)) << 4);
            size_t src = (size_t)(qb + row) * DH + c * 8;
            CP_ASYNC_16(sq + o, Qh_g + src);
            CP_ASYNC_16(sb + o, Ql_g + src);   // temp in stage-0 Kh slot
        }
        CP_ASYNC_COMMIT();
        CP_ASYNC_WAIT_ALL();
        __syncthreads();
    }
    // extract q-lo fragments to registers (resident)
    uint32_t ql[4][4];
    #pragma unroll
    for (int ks = 0; ks < 4; ks++) {
        int row = warp * 16 + (lane & 15);
        int chunk = 2 * ks + (lane >> 4);
        uint32_t addr = sb + row * 128 + ((chunk ^ (row & 7)) << 4);
        LDMATRIX_X4(ql[ks][0], ql[ks][1], ql[ks][2], ql[ks][3], addr);
    }
    __syncthreads();   // all warps extracted before KV overwrites stage 0

    // KV stage 0
    {
        #pragma unroll
        for (int q = 0; q < 4; q++) {
            int id = q * 128 + tid;
            int row = id >> 3, c = id & 7;
            uint32_t o = row * 128 + ((c ^ (row & 7)) << 4);
            size_t src = (size_t)row * DH + c * 8;
            CP_ASYNC_16(sb +         o, Kh_g + src);
            CP_ASYNC_16(sb +  8192 + o, Kl_g + src);
            CP_ASYNC_16(sb + 16384 + o, Vf_g + src);
        }
        CP_ASYNC_COMMIT();
    }

    float oacc[8][4];
    #pragma unroll
    for (int i = 0; i < 8; i++)
        #pragma unroll
        for (int j = 0; j < 4; j++) oacc[i][j] = 0.f;
    float m0r = -INFINITY, m1r = -INFINITY, l0 = 0.f, l1 = 0.f;

    for (int it = 0; it < FNIT; it++) {
        CP_ASYNC_WAIT_ALL();
        __syncthreads();

        if (it + 1 < FNIT) {
            uint32_t buf = sb + ((it + 1) & 1) * FST;
            size_t kadd = (size_t)(it + 1) * FKT * DH;
            #pragma unroll
            for (int q = 0; q < 4; q++) {
                int id = q * 128 + tid;
                int row = id >> 3, c = id & 7;
                uint32_t o = row * 128 + ((c ^ (row & 7)) << 4);
                size_t src = kadd + (size_t)row * DH + c * 8;
                CP_ASYNC_16(buf +         o, Kh_g + src);
                CP_ASYNC_16(buf +  8192 + o, Kl_g + src);
                CP_ASYNC_16(buf + 16384 + o, Vf_g + src);
            }
            CP_ASYNC_COMMIT();
        }

        const uint32_t buf = sb + (it & 1) * FST;
        const uint32_t kh = buf, kl = buf + 8192, vf = buf + 16384;

        // ---- S = Q K^T (3 split passes); q-hi from smem, q-lo resident ----
        float sacc[8][4];
        #pragma unroll
        for (int i = 0; i < 8; i++)
            #pragma unroll
            for (int j = 0; j < 4; j++) sacc[i][j] = 0.f;

        #pragma unroll
        for (int ks = 0; ks < 4; ks++) {
            int qrow = warp * 16 + (lane & 15);
            int qchunk = 2 * ks + (lane >> 4);
            uint32_t qaddr = sq + qrow * 128 + ((qchunk ^ (qrow & 7)) << 4);
            uint32_t qh0, qh1, qh2, qh3;
            LDMATRIX_X4(qh0, qh1, qh2, qh3, qaddr);
            #pragma unroll
            for (int ntp = 0; ntp < 4; ntp++) {
                int row = ntp * 16 + ((lane >> 4) & 1) * 8 + (lane & 7);
                int chunk = 2 * ks + ((lane >> 3) & 1);
                uint32_t addr = kh + row * 128 + ((chunk ^ (row & 7)) << 4);
                uint32_t bh0, bh1, bh2, bh3, bl0, bl1, bl2, bl3;
                LDMATRIX_X4(bh0, bh1, bh2, bh3, addr);
                LDMATRIX_X4(bl0, bl1, bl2, bl3, addr + 8192);
                MMA_BF16(sacc[2*ntp],   qh0, qh1, qh2, qh3, bh0, bh1);
                MMA_BF16(sacc[2*ntp],   ql[ks][0], ql[ks][1], ql[ks][2], ql[ks][3], bh0, bh1);
                MMA_BF16(sacc[2*ntp],   qh0, qh1, qh2, qh3, bl0, bl1);
                MMA_BF16(sacc[2*ntp+1], qh0, qh1, qh2, qh3, bh2, bh3);
                MMA_BF16(sacc[2*ntp+1], ql[ks][0], ql[ks][1], ql[ks][2], ql[ks][3], bh2, bh3);
                MMA_BF16(sacc[2*ntp+1], qh0, qh1, qh2, qh3, bl2, bl3);
            }
        }

        // ---- lazy online softmax, base 2, fp32 exp input ----
        float tm0 = -INFINITY, tm1 = -INFINITY;
        #pragma unroll
        for (int nt = 0; nt < 8; nt++) {
            tm0 = fmaxf(tm0, fmaxf(sacc[nt][0], sacc[nt][1]));
            tm1 = fmaxf(tm1, fmaxf(sacc[nt][2], sacc[nt][3]));
        }
        bool need = (tm0 > m0r + 12.f) || (tm1 > m1r + 12.f);
        if (__any_sync(0xffffffffu, need)) {
            tm0 = fmaxf(tm0, __shfl_xor_sync(0xffffffffu, tm0, 1));
            tm0 = fmaxf(tm0, __shfl_xor_sync(0xffffffffu, tm0, 2));
            tm1 = fmaxf(tm1, __shfl_xor_sync(0xffffffffu, tm1, 1));
            tm1 = fmaxf(tm1, __shfl_xor_sync(0xffffffffu, tm1, 2));
            float mn0 = fmaxf(m0r, tm0), mn1 = fmaxf(m1r, tm1);
            float a0 = ex2f(m0r - mn0), a1 = ex2f(m1r - mn1);
            m0r = mn0; m1r = mn1;
            l0 *= a0; l1 *= a1;
            #pragma unroll
            for (int nt = 0; nt < 8; nt++) {
                oacc[nt][0] *= a0; oacc[nt][1] *= a0;
                oacc[nt][2] *= a1; oacc[nt][3] *= a1;
            }
        }

        float rs0 = 0.f, rs1 = 0.f;
        uint32_t ph[4][4];
        #pragma unroll
        for (int nt = 0; nt < 8; nt++) {
            float p00 = ex2f(sacc[nt][0] - m0r);
            float p01 = ex2f(sacc[nt][1] - m0r);
            float p10 = ex2f(sacc[nt][2] - m1r);
            float p11 = ex2f(sacc[nt][3] - m1r);
            rs0 += p00 + p01; rs1 += p10 + p11;
            int ks = nt >> 1, half = (nt & 1) * 2;
            ph[ks][half]     = pack_h2(p00, p01);
            ph[ks][half + 1] = pack_h2(p10, p11);
        }
        l0 += rs0;
        l1 += rs1;

        // ---- O += P V, single fp16 pass; V via ldmatrix.trans ----
        #pragma unroll
        for (int ks = 0; ks < 4; ks++) {
            #pragma unroll
            for (int ntp = 0; ntp < 4; ntp++) {
                int row = ks * 16 + ((lane >> 3) & 1) * 8 + (lane & 7);
                int chunk = 2 * ntp + (lane >> 4);
                uint32_t addr = vf + row * 128 + ((chunk ^ (row & 7)) << 4);
                uint32_t b0, b1, b2, b3;
                LDMATRIX_X4_T(b0, b1, b2, b3, addr);
                MMA_F16(oacc[2*ntp],   ph[ks][0], ph[ks][1], ph[ks][2], ph[ks][3], b0, b1);
                MMA_F16(oacc[2*ntp+1], ph[ks][0], ph[ks][1], ph[ks][2], ph[ks][3], b2, b3);
            }
        }
        // top-of-iteration barrier of it+1 orders these reads before the
        // prefetch that overwrites this buffer.
    }

    // ---- epilogue: reduce l across the 4-lane row group, store fp32 ----
    {
        l0 += __shfl_xor_sync(0xffffffffu, l0, 1);
        l0 += __shfl_xor_sync(0xffffffffu, l0, 2);
        l1 += __shfl_xor_sync(0xffffffffu, l1, 1);
        l1 += __shfl_xor_sync(0xffffffffu, l1, 2);
        const int r = lane >> 2, c2 = (lane & 3) * 2;
        float inv0 = 1.0f / l0, inv1 = 1.0f / l1;
        int row0 = qb + warp * 16 + r;
        size_t o0 = ((size_t)b * SS + row0) * DD + h * DH;
        size_t o1 = ((size_t)b * SS + row0 + 8) * DD + h * DH;
        #pragma unroll
        for (int nt = 0; nt < 8; nt++) {
            *(float2*)(out + o0 + nt * 8 + c2) =
                make_float2(oacc[nt][0] * inv0, oacc[nt][1] * inv0);
            *(float2*)(out + o1 + nt * 8 + c2) =
                make_float2(oacc[nt][2] * inv1, oacc[nt][3] * inv1);
        }
    }
}

// ---------------------------------------------------------------------------
extern "C" void kernel_launch(void* const* d_in, const int* in_sizes, int n_in,
                              void* d_out, int out_size) {
    const float* x  = (const float*)d_in[0];
    const float* Wq = (const float*)d_in[1];
    const float* bq = (const float*)d_in[2];
    const float* Wk = (const float*)d_in[3];
    const float* bk = (const float*)d_in[4];
    const float* Wv = (const float*)d_in[5];
    const float* bv = (const float*)d_in[6];
    float* out = (float*)d_out;

    split_x_kernel<<<M_TOTAL * DD / 1024, 256>>>((const float4*)x);
    split_w_kernel<<<dim3(DD/32, DD/32, 3), dim3(32, 8)>>>(Wq, Wk, Wv);

    cudaFuncSetAttribute(proj_mma_kernel,
                         cudaFuncAttributeMaxDynamicSharedMemorySize, PROJ_SMEM);
    proj_mma_kernel<<<1536, 128, PROJ_SMEM>>>(bq, bk, bv);

    cudaFuncSetAttribute(flash_mma_kernel,
                         cudaFuncAttributeMaxDynamicSharedMemorySize, FLASH_SMEM);
    flash_mma_kernel<<<dim3(SS/FQT, HH, BB), 128, FLASH_SMEM>>>(out);
}

// round 17
// speedup vs baseline: 1.2813x; 1.0014x over previous
#include <cuda_runtime.h>
#include <cuda_bf16.h>
#include <cuda_fp16.h>
#include <math.h>
#include <cstdint>

#define BB 2
#define SS 2048
#define DD 1024
#define HH 16
#define DH 64
#define M_TOTAL (BB*SS)      // 4096
#define N_TOTAL (3*DD)       // 3072

// ---------------- device scratch (no cudaMalloc allowed) -------------------
__device__ __align__(16) __nv_bfloat16 g_xh[M_TOTAL*DD];
__device__ __align__(16) __nv_bfloat16 g_xl[M_TOTAL*DD];
__device__ __align__(16) __half        g_xf[M_TOTAL*DD];   // fp16 x (V proj)
__device__ __align__(16) __nv_bfloat16 g_wth[2*DD*DD];     // Wq^T, Wk^T hi
__device__ __align__(16) __nv_bfloat16 g_wtl[2*DD*DD];     // Wq^T, Wk^T lo
__device__ __align__(16) __half        g_wvf[DD*DD];       // Wv^T fp16
// projected Q/K bf16 hi/lo, V fp16, [B,H,S,DH]  (Q pre-scaled by log2(e))
__device__ __align__(16) __nv_bfloat16 g_qh[BB*HH*SS*DH];
__device__ __align__(16) __nv_bfloat16 g_ql[BB*HH*SS*DH];
__device__ __align__(16) __nv_bfloat16 g_kh[BB*HH*SS*DH];
__device__ __align__(16) __nv_bfloat16 g_kl[BB*HH*SS*DH];
__device__ __align__(16) __half        g_vf[BB*HH*SS*DH];

// ---------------- warp-mma helpers (plain sm_80+ PTX) ----------------------
__device__ __forceinline__ uint32_t smem_to_u32(const void* p) {
    uint32_t a;
    asm("{ .reg .u64 t; cvta.to.shared.u64 t, %1; cvt.u32.u64 %0, t; }"
        : "=r"(a) : "l"(p));
    return a;
}
__device__ __forceinline__ float ex2f(float x) {
    float y;
    asm("ex2.approx.f32 %0, %1;" : "=f"(y) : "f"(x));
    return y;
}
__device__ __forceinline__ uint32_t pack_h2(float a, float b) {
    uint32_t h2;
    asm("cvt.rn.f16x2.f32 %0, %1, %2;" : "=r"(h2) : "f"(b), "f"(a));
    return h2;
}

#define CP_ASYNC_16(dst, src) \
    asm volatile("cp.async.cg.shared.global [%0], [%1], 16;" :: "r"(dst), "l"(src))
#define CP_ASYNC_COMMIT() asm volatile("cp.async.commit_group;" ::: "memory")
#define CP_ASYNC_WAIT_ALL() asm volatile("cp.async.wait_group 0;" ::: "memory")

#define LDMATRIX_X4(r0, r1, r2, r3, addr) \
    asm volatile("ldmatrix.sync.aligned.m8n8.x4.shared.b16 {%0,%1,%2,%3}, [%4];" \
        : "=r"(r0), "=r"(r1), "=r"(r2), "=r"(r3) : "r"(addr))
#define LDMATRIX_X4_T(r0, r1, r2, r3, addr) \
    asm volatile("ldmatrix.sync.aligned.m8n8.x4.trans.shared.b16 {%0,%1,%2,%3}, [%4];" \
        : "=r"(r0), "=r"(r1), "=r"(r2), "=r"(r3) : "r"(addr))

#define MMA_BF16(cc, a0, a1, a2, a3, b0, b1) \
    asm volatile("mma.sync.aligned.m16n8k16.row.col.f32.bf16.bf16.f32 " \
        "{%0,%1,%2,%3}, {%4,%5,%6,%7}, {%8,%9}, {%0,%1,%2,%3};" \
        : "+f"((cc)[0]), "+f"((cc)[1]), "+f"((cc)[2]), "+f"((cc)[3]) \
        : "r"(a0), "r"(a1), "r"(a2), "r"(a3), "r"(b0), "r"(b1))

#define MMA_F16(cc, a0, a1, a2, a3, b0, b1) \
    asm volatile("mma.sync.aligned.m16n8k16.row.col.f32.f16.f16.f32 " \
        "{%0,%1,%2,%3}, {%4,%5,%6,%7}, {%8,%9}, {%0,%1,%2,%3};" \
        : "+f"((cc)[0]), "+f"((cc)[1]), "+f"((cc)[2]), "+f"((cc)[3]) \
        : "r"(a0), "r"(a1), "r"(a2), "r"(a3), "r"(b0), "r"(b1))

// ---------------------------------------------------------------------------
// Split kernels
// ---------------------------------------------------------------------------
__global__ void __launch_bounds__(256) split_x_kernel(const float4* __restrict__ x) {
    int i = blockIdx.x * 256 + threadIdx.x;
    float4 v = x[i];
    __nv_bfloat162 h01 = __floats2bfloat162_rn(v.x, v.y);
    __nv_bfloat162 h23 = __floats2bfloat162_rn(v.z, v.w);
    float2 f01 = __bfloat1622float2(h01);
    float2 f23 = __bfloat1622float2(h23);
    __nv_bfloat162 l01 = __floats2bfloat162_rn(v.x - f01.x, v.y - f01.y);
    __nv_bfloat162 l23 = __floats2bfloat162_rn(v.z - f23.x, v.w - f23.y);
    ((__nv_bfloat162*)g_xh)[i*2]   = h01;
    ((__nv_bfloat162*)g_xh)[i*2+1] = h23;
    ((__nv_bfloat162*)g_xl)[i*2]   = l01;
    ((__nv_bfloat162*)g_xl)[i*2+1] = l23;
    __half2 p01 = __floats2half2_rn(v.x, v.y);
    __half2 p23 = __floats2half2_rn(v.z, v.w);
    ((__half2*)g_xf)[i*2]   = p01;
    ((__half2*)g_xf)[i*2+1] = p23;
}

__global__ void __launch_bounds__(256) split_w_kernel(
    const float* __restrict__ Wq, const float* __restrict__ Wk, const float* __restrict__ Wv)
{
    const float* W = (blockIdx.z == 0) ? Wq : (blockIdx.z == 1) ? Wk : Wv;
    __shared__ float t[32][33];
    int n0 = blockIdx.x * 32, k0 = blockIdx.y * 32;
    int tx = threadIdx.x, ty = threadIdx.y;   // block (32, 8)
    for (int r = ty; r < 32; r += 8)
        t[r][tx] = W[(size_t)(k0 + r) * DD + n0 + tx];
    __syncthreads();
    if (blockIdx.z < 2) {
        size_t base = (size_t)blockIdx.z * DD * DD;
        for (int r = ty; r < 32; r += 8) {
            float v = t[tx][r];
            __nv_bfloat16 hi = __float2bfloat16(v);
            size_t idx = base + (size_t)(n0 + r) * DD + k0 + tx;
            g_wth[idx] = hi;
            g_wtl[idx] = __float2bfloat16(v - __bfloat162float(hi));
        }
    } else {
        for (int r = ty; r < 32; r += 8) {
            size_t idx = (size_t)(n0 + r) * DD + k0 + tx;
            g_wvf[idx] = __float2half_rn(t[tx][r]);
        }
    }
}

// ---------------------------------------------------------------------------
// Projection via mma.sync. 128-thread CTAs, tile 64M x 128N, 4 CTAs/SM,
// 1-D LPT grid (heavy Q/K first, light V last). Q/K: 3-pass split-bf16;
// V: 1-pass fp16. NEW: fragment-direct epilogue stores (no smem staging,
// no epilogue barriers) — hi/lo split computed on registers.
// ---------------------------------------------------------------------------
#define BK 32
#define PSTG 24576
#define PROJ_SMEM (2*PSTG)               // 49152

__global__ void __launch_bounds__(128, 4) proj_mma_kernel(
    const float* __restrict__ bq, const float* __restrict__ bk, const float* __restrict__ bv)
{
    extern __shared__ __align__(1024) char smem[];
    const uint32_t smem_base = smem_to_u32(smem);

    const int tid  = threadIdx.x;
    const int lane = tid & 31;
    const int wn   = tid >> 5;            // warp = n-slice 0..3

    // LPT mapping: heavy tiles (Q/K) on low bids, light (V) on high bids
    int wsel, n8, mtile;
    {
        int bid = blockIdx.x;
        if (bid < 1024) { wsel = bid & 1; n8 = (bid >> 1) & 7; mtile = bid >> 4; }
        else            { int v = bid - 1024; wsel = 2; n8 = v & 7; mtile = v >> 3; }
    }
    const int ncol0 = n8 * 128;
    const int m0    = mtile * 64;

    int la_sw[2]; size_t la_g[2];
    #pragma unroll
    for (int q = 0; q < 2; q++) {
        int id = q * 128 + tid;
        int row = id >> 2, c = id & 3;
        la_sw[q] = row * 64 + ((c ^ ((row >> 1) & 3)) << 4);
        la_g[q]  = (size_t)(m0 + row) * DD + c * 8;
    }
    int lb_sw[4]; size_t lb_g[4];
    #pragma unroll
    for (int q = 0; q < 4; q++) {
        int id = q * 128 + tid;
        int row = id >> 2, c = id & 3;
        lb_sw[q] = row * 64 + ((c ^ ((row >> 1) & 3)) << 4);
        lb_g[q]  = (size_t)(ncol0 + row) * DD + c * 8;
    }

    int rA[4], gA[4];
    #pragma unroll
    for (int mt = 0; mt < 4; mt++) {
        rA[mt] = mt * 16 + (lane & 15);
        gA[mt] = (rA[mt] >> 1) & 3;
    }
    const int khalfA = lane >> 4;

    float acc[4][4][4];
    #pragma unroll
    for (int i = 0; i < 4; i++)
        #pragma unroll
        for (int j = 0; j < 4; j++)
            #pragma unroll
            for (int r = 0; r < 4; r++) acc[i][j][r] = 0.f;

    const int NKC = DD / BK;              // 32

    if (wsel < 2) {
        // ================= Q/K path: 3-pass split-bf16 =================
        const __nv_bfloat16* Ah_g = g_xh;
        const __nv_bfloat16* Al_g = g_xl;
        const __nv_bfloat16* Bh_g = g_wth + (size_t)wsel * DD * DD;
        const __nv_bfloat16* Bl_g = g_wtl + (size_t)wsel * DD * DD;

        {
            uint32_t sb = smem_base;
            #pragma unroll
            for (int q = 0; q < 2; q++) {
                CP_ASYNC_16(sb +        la_sw[q], Ah_g + la_g[q]);
                CP_ASYNC_16(sb + 4096 + la_sw[q], Al_g + la_g[q]);
            }
            #pragma unroll
            for (int q = 0; q < 4; q++) {
                CP_ASYNC_16(sb +  8192 + lb_sw[q], Bh_g + lb_g[q]);
                CP_ASYNC_16(sb + 16384 + lb_sw[q], Bl_g + lb_g[q]);
            }
            CP_ASYNC_COMMIT();
        }

        for (int kc = 0; kc < NKC; kc++) {
            CP_ASYNC_WAIT_ALL();
            __syncthreads();

            if (kc + 1 < NKC) {
                uint32_t sb = smem_base + ((kc + 1) & 1) * PSTG;
                size_t koff = (size_t)(kc + 1) * BK;
                #pragma unroll
                for (int q = 0; q < 2; q++) {
                    CP_ASYNC_16(sb +        la_sw[q], Ah_g + la_g[q] + koff);
                    CP_ASYNC_16(sb + 4096 + la_sw[q], Al_g + la_g[q] + koff);
                }
                #pragma unroll
                for (int q = 0; q < 4; q++) {
                    CP_ASYNC_16(sb +  8192 + lb_sw[q], Bh_g + lb_g[q] + koff);
                    CP_ASYNC_16(sb + 16384 + lb_sw[q], Bl_g + lb_g[q] + koff);
                }
                CP_ASYNC_COMMIT();
            }

            const uint32_t sb = smem_base + (kc & 1) * PSTG;
            const uint32_t ah = sb, al = sb + 4096, bh = sb + 8192, bl = sb + 16384;

            #pragma unroll
            for (int kf = 0; kf < 2; kf++) {
                const int cA = kf * 2 + khalfA;

                uint32_t B_h[4][2], B_l[4][2];
                #pragma unroll
                for (int ntp = 0; ntp < 2; ntp++) {
                    int row = wn * 32 + ntp * 16 + ((lane >> 4) & 1) * 8 + (lane & 7);
                    int chunk = kf * 2 + ((lane >> 3) & 1);
                    uint32_t boff = row * 64 + (((chunk ^ ((row >> 1) & 3))) << 4);
                    LDMATRIX_X4(B_h[2*ntp][0], B_h[2*ntp][1],
                                B_h[2*ntp+1][0], B_h[2*ntp+1][1], bh + boff);
                    LDMATRIX_X4(B_l[2*ntp][0], B_l[2*ntp][1],
                                B_l[2*ntp+1][0], B_l[2*ntp+1][1], bl + boff);
                }
                uint32_t A[4][4];
                #pragma unroll
                for (int mt = 0; mt < 4; mt++) {
                    uint32_t aoff = rA[mt] * 64 + (((cA ^ gA[mt])) << 4);
                    LDMATRIX_X4(A[mt][0], A[mt][1], A[mt][2], A[mt][3], ah + aoff);
                }
                #pragma unroll
                for (int mt = 0; mt < 4; mt++)
                    #pragma unroll
                    for (int nt = 0; nt < 4; nt++) {
                        MMA_BF16(acc[mt][nt], A[mt][0], A[mt][1], A[mt][2], A[mt][3],
                                 B_h[nt][0], B_h[nt][1]);
                        MMA_BF16(acc[mt][nt], A[mt][0], A[mt][1], A[mt][2], A[mt][3],
                                 B_l[nt][0], B_l[nt][1]);
                    }
                #pragma unroll
                for (int mt = 0; mt < 4; mt++) {
                    uint32_t aoff = rA[mt] * 64 + (((cA ^ gA[mt])) << 4);
                    LDMATRIX_X4(A[mt][0], A[mt][1], A[mt][2], A[mt][3], al + aoff);
                }
                #pragma unroll
                for (int mt = 0; mt < 4; mt++)
                    #pragma unroll
                    for (int nt = 0; nt < 4; nt++)
                        MMA_BF16(acc[mt][nt], A[mt][0], A[mt][1], A[mt][2], A[mt][3],
                                 B_h[nt][0], B_h[nt][1]);
            }
        }
    } else {
        // ================= V path: 1-pass fp16 =================
        const __half* Af_g = g_xf;
        const __half* Bf_g = g_wvf;

        {
            uint32_t sb = smem_base;
            #pragma unroll
            for (int q = 0; q < 2; q++)
                CP_ASYNC_16(sb + la_sw[q], Af_g + la_g[q]);
            #pragma unroll
            for (int q = 0; q < 4; q++)
                CP_ASYNC_16(sb + 8192 + lb_sw[q], Bf_g + lb_g[q]);
            CP_ASYNC_COMMIT();
        }

        for (int kc = 0; kc < NKC; kc++) {
            CP_ASYNC_WAIT_ALL();
            __syncthreads();

            if (kc + 1 < NKC) {
                uint32_t sb = smem_base + ((kc + 1) & 1) * PSTG;
                size_t koff = (size_t)(kc + 1) * BK;
                #pragma unroll
                for (int q = 0; q < 2; q++)
                    CP_ASYNC_16(sb + la_sw[q], Af_g + la_g[q] + koff);
                #pragma unroll
                for (int q = 0; q < 4; q++)
                    CP_ASYNC_16(sb + 8192 + lb_sw[q], Bf_g + lb_g[q] + koff);
                CP_ASYNC_COMMIT();
            }

            const uint32_t sb = smem_base + (kc & 1) * PSTG;
            const uint32_t af = sb, bf = sb + 8192;

            #pragma unroll
            for (int kf = 0; kf < 2; kf++) {
                const int cA = kf * 2 + khalfA;

                uint32_t B_f[4][2];
                #pragma unroll
                for (int ntp = 0; ntp < 2; ntp++) {
                    int row = wn * 32 + ntp * 16 + ((lane >> 4) & 1) * 8 + (lane & 7);
                    int chunk = kf * 2 + ((lane >> 3) & 1);
                    uint32_t boff = row * 64 + (((chunk ^ ((row >> 1) & 3))) << 4);
                    LDMATRIX_X4(B_f[2*ntp][0], B_f[2*ntp][1],
                                B_f[2*ntp+1][0], B_f[2*ntp+1][1], bf + boff);
                }
                uint32_t A[4][4];
                #pragma unroll
                for (int mt = 0; mt < 4; mt++) {
                    uint32_t aoff = rA[mt] * 64 + (((cA ^ gA[mt])) << 4);
                    LDMATRIX_X4(A[mt][0], A[mt][1], A[mt][2], A[mt][3], af + aoff);
                }
                #pragma unroll
                for (int mt = 0; mt < 4; mt++)
                    #pragma unroll
                    for (int nt = 0; nt < 4; nt++)
                        MMA_F16(acc[mt][nt], A[mt][0], A[mt][1], A[mt][2], A[mt][3],
                                B_f[nt][0], B_f[nt][1]);
            }
        }
    }

    // ---- epilogue: bias (+GELU +log2e on Q), fragment-direct stores ----
    const float* bias = (wsel == 0) ? bq : (wsel == 1) ? bk : bv;
    __nv_bfloat16* dsth = (wsel == 0) ? g_qh : g_kh;
    __nv_bfloat16* dstl = (wsel == 0) ? g_ql : g_kl;

    const int b  = m0 >> 11;
    const int s0 = m0 & 2047;
    const int fr = lane >> 2;
    const int fc = (lane & 3) * 2;
    #pragma unroll
    for (int mt = 0; mt < 4; mt++) {
        #pragma unroll
        for (int nt = 0; nt < 4; nt++) {
            int col = ncol0 + wn * 32 + nt * 8 + fc;   // global N col (pair base)
            float b0 = bias[col], b1 = bias[col + 1];
            int hh = col >> 6, dh = col & 63;
            size_t hbase = (((size_t)(b * HH + hh)) * SS + s0) * DH + dh;
            #pragma unroll
            for (int half = 0; half < 2; half++) {
                int r = mt * 16 + fr + half * 8;
                float v0 = acc[mt][nt][half * 2 + 0] + b0;
                float v1 = acc[mt][nt][half * 2 + 1] + b1;
                size_t idx = hbase + (size_t)r * DH;
                if (wsel == 0) {
                    v0 = 0.5f * v0 * (1.0f + erff(v0 * 0.70710678118654752f));
                    v1 = 0.5f * v1 * (1.0f + erff(v1 * 0.70710678118654752f));
                    v0 *= 1.44269504088896340736f;   // log2(e): softmax in base-2
                    v1 *= 1.44269504088896340736f;
                }
                if (wsel < 2) {
                    __nv_bfloat162 hi2 = __floats2bfloat162_rn(v0, v1);
                    float2 f = __bfloat1622float2(hi2);
                    __nv_bfloat162 lo2 = __floats2bfloat162_rn(v0 - f.x, v1 - f.y);
                    *(__nv_bfloat162*)&dsth[idx] = hi2;
                    *(__nv_bfloat162*)&dstl[idx] = lo2;
                } else {
                    *(__half2*)&g_vf[idx] = __floats2half2_rn(v0, v1);
                }
            }
        }
    }
}

// ---------------------------------------------------------------------------
// Flash attention via mma.sync (R16 config — best measured). 128-thread CTAs,
// 4 CTAs/SM, q-lo resident, q-hi 8KB smem, 2-stage KV ring, lazy softmax
// rescale (12-unit slack), fp32-input exp, fp16 P, single fp16 PV pass.
// ---------------------------------------------------------------------------
#define FQT 64
#define FKT 64
#define FNIT (SS/FKT)
#define FQB 8192                        // Q-hi region
#define FST 24576                       // K/V stage stride (Kh|Kl|Vf x 8KB)
#define FLASH_SMEM (FQB + 2*FST)        // 57344 -> 4 CTAs/SM

__global__ void __launch_bounds__(128, 4) flash_mma_kernel(float* __restrict__ out)
{
    extern __shared__ __align__(1024) char smem[];
    const uint32_t sq = smem_to_u32(smem);      // Q hi
    const uint32_t sb = sq + FQB;               // K/V stages
    const int tid = threadIdx.x, lane = tid & 31, warp = tid >> 5;  // warp 0-3
    const int qb = blockIdx.x * FQT;
    const int h  = blockIdx.y, b = blockIdx.z;
    const size_t gbase = ((size_t)(b * HH + h)) * SS * DH;
    const __nv_bfloat16* Qh_g = g_qh + gbase;
    const __nv_bfloat16* Ql_g = g_ql + gbase;
    const __nv_bfloat16* Kh_g = g_kh + gbase;
    const __nv_bfloat16* Kl_g = g_kl + gbase;
    const __half*        Vf_g = g_vf + gbase;

    // ---- prologue: Qh -> sq, Ql -> stage0 area (temp), then extract ----
    {
        #pragma unroll
        for (int q = 0; q < 4; q++) {
            int id = q * 128 + tid;            // 512 chunks (64 rows x 8)
            int row = id >> 3, c = id & 7;
            uint32_t o = row * 128 + ((c ^ (row & 7)) << 4);
            size_t src = (size_t)(qb + row) * DH + c * 8;
            CP_ASYNC_16(sq + o, Qh_g + src);
            CP_ASYNC_16(sb + o, Ql_g + src);   // temp in stage-0 Kh slot
        }
        CP_ASYNC_COMMIT();
        CP_ASYNC_WAIT_ALL();
        __syncthreads();
    }
    // extract q-lo fragments to registers (resident)
    uint32_t ql[4][4];
    #pragma unroll
    for (int ks = 0; ks < 4; ks++) {
        int row = warp * 16 + (lane & 15);
        int chunk = 2 * ks + (lane >> 4);
        uint32_t addr = sb + row * 128 + ((chunk ^ (row & 7)) << 4);
        LDMATRIX_X4(ql[ks][0], ql[ks][1], ql[ks][2], ql[ks][3], addr);
    }
    __syncthreads();   // all warps extracted before KV overwrites stage 0

    // KV stage 0
    {
        #pragma unroll
        for (int q = 0; q < 4; q++) {
            int id = q * 128 + tid;
            int row = id >> 3, c = id & 7;
            uint32_t o = row * 128 + ((c ^ (row & 7)) << 4);
            size_t src = (size_t)row * DH + c * 8;
            CP_ASYNC_16(sb +         o, Kh_g + src);
            CP_ASYNC_16(sb +  8192 + o, Kl_g + src);
            CP_ASYNC_16(sb + 16384 + o, Vf_g + src);
        }
        CP_ASYNC_COMMIT();
    }

    float oacc[8][4];
    #pragma unroll
    for (int i = 0; i < 8; i++)
        #pragma unroll
        for (int j = 0; j < 4; j++) oacc[i][j] = 0.f;
    float m0r = -INFINITY, m1r = -INFINITY, l0 = 0.f, l1 = 0.f;

    for (int it = 0; it < FNIT; it++) {
        CP_ASYNC_WAIT_ALL();
        __syncthreads();

        if (it + 1 < FNIT) {
            uint32_t buf = sb + ((it + 1) & 1) * FST;
            size_t kadd = (size_t)(it + 1) * FKT * DH;
            #pragma unroll
            for (int q = 0; q < 4; q++) {
                int id = q * 128 + tid;
                int row = id >> 3, c = id & 7;
                uint32_t o = row * 128 + ((c ^ (row & 7)) << 4);
                size_t src = kadd + (size_t)row * DH + c * 8;
                CP_ASYNC_16(buf +         o, Kh_g + src);
                CP_ASYNC_16(buf +  8192 + o, Kl_g + src);
                CP_ASYNC_16(buf + 16384 + o, Vf_g + src);
            }
            CP_ASYNC_COMMIT();
        }

        const uint32_t buf = sb + (it & 1) * FST;
        const uint32_t kh = buf, kl = buf + 8192, vf = buf + 16384;

        // ---- S = Q K^T (3 split passes); q-hi from smem, q-lo resident ----
        float sacc[8][4];
        #pragma unroll
        for (int i = 0; i < 8; i++)
            #pragma unroll
            for (int j = 0; j < 4; j++) sacc[i][j] = 0.f;

        #pragma unroll
        for (int ks = 0; ks < 4; ks++) {
            int qrow = warp * 16 + (lane & 15);
            int qchunk = 2 * ks + (lane >> 4);
            uint32_t qaddr = sq + qrow * 128 + ((qchunk ^ (qrow & 7)) << 4);
            uint32_t qh0, qh1, qh2, qh3;
            LDMATRIX_X4(qh0, qh1, qh2, qh3, qaddr);
            #pragma unroll
            for (int ntp = 0; ntp < 4; ntp++) {
                int row = ntp * 16 + ((lane >> 4) & 1) * 8 + (lane & 7);
                int chunk = 2 * ks + ((lane >> 3) & 1);
                uint32_t addr = kh + row * 128 + ((chunk ^ (row & 7)) << 4);
                uint32_t bh0, bh1, bh2, bh3, bl0, bl1, bl2, bl3;
                LDMATRIX_X4(bh0, bh1, bh2, bh3, addr);
                LDMATRIX_X4(bl0, bl1, bl2, bl3, addr + 8192);
                MMA_BF16(sacc[2*ntp],   qh0, qh1, qh2, qh3, bh0, bh1);
                MMA_BF16(sacc[2*ntp],   ql[ks][0], ql[ks][1], ql[ks][2], ql[ks][3], bh0, bh1);
                MMA_BF16(sacc[2*ntp],   qh0, qh1, qh2, qh3, bl0, bl1);
                MMA_BF16(sacc[2*ntp+1], qh0, qh1, qh2, qh3, bh2, bh3);
                MMA_BF16(sacc[2*ntp+1], ql[ks][0], ql[ks][1], ql[ks][2], ql[ks][3], bh2, bh3);
                MMA_BF16(sacc[2*ntp+1], qh0, qh1, qh2, qh3, bl2, bl3);
            }
        }

        // ---- lazy online softmax, base 2, fp32 exp input ----
        float tm0 = -INFINITY, tm1 = -INFINITY;
        #pragma unroll
        for (int nt = 0; nt < 8; nt++) {
            tm0 = fmaxf(tm0, fmaxf(sacc[nt][0], sacc[nt][1]));
            tm1 = fmaxf(tm1, fmaxf(sacc[nt][2], sacc[nt][3]));
        }
        bool need = (tm0 > m0r + 12.f) || (tm1 > m1r + 12.f);
        if (__any_sync(0xffffffffu, need)) {
            tm0 = fmaxf(tm0, __shfl_xor_sync(0xffffffffu, tm0, 1));
            tm0 = fmaxf(tm0, __shfl_xor_sync(0xffffffffu, tm0, 2));
            tm1 = fmaxf(tm1, __shfl_xor_sync(0xffffffffu, tm1, 1));
            tm1 = fmaxf(tm1, __shfl_xor_sync(0xffffffffu, tm1, 2));
            float mn0 = fmaxf(m0r, tm0), mn1 = fmaxf(m1r, tm1);
            float a0 = ex2f(m0r - mn0), a1 = ex2f(m1r - mn1);
            m0r = mn0; m1r = mn1;
            l0 *= a0; l1 *= a1;
            #pragma unroll
            for (int nt = 0; nt < 8; nt++) {
                oacc[nt][0] *= a0; oacc[nt][1] *= a0;
                oacc[nt][2] *= a1; oacc[nt][3] *= a1;
            }
        }

        float rs0 = 0.f, rs1 = 0.f;
        uint32_t ph[4][4];
        #pragma unroll
        for (int nt = 0; nt < 8; nt++) {
            float p00 = ex2f(sacc[nt][0] - m0r);
            float p01 = ex2f(sacc[nt][1] - m0r);
            float p10 = ex2f(sacc[nt][2] - m1r);
            float p11 = ex2f(sacc[nt][3] - m1r);
            rs0 += p00 + p01; rs1 += p10 + p11;
            int ks = nt >> 1, half = (nt & 1) * 2;
            ph[ks][half]     = pack_h2(p00, p01);
            ph[ks][half + 1] = pack_h2(p10, p11);
        }
        l0 += rs0;
        l1 += rs1;

        // ---- O += P V, single fp16 pass; V via ldmatrix.trans ----
        #pragma unroll
        for (int ks = 0; ks < 4; ks++) {
            #pragma unroll
            for (int ntp = 0; ntp < 4; ntp++) {
                int row = ks * 16 + ((lane >> 3) & 1) * 8 + (lane & 7);
                int chunk = 2 * ntp + (lane >> 4);
                uint32_t addr = vf + row * 128 + ((chunk ^ (row & 7)) << 4);
                uint32_t b0, b1, b2, b3;
                LDMATRIX_X4_T(b0, b1, b2, b3, addr);
                MMA_F16(oacc[2*ntp],   ph[ks][0], ph[ks][1], ph[ks][2], ph[ks][3], b0, b1);
                MMA_F16(oacc[2*ntp+1], ph[ks][0], ph[ks][1], ph[ks][2], ph[ks][3], b2, b3);
            }
        }
        // top-of-iteration barrier of it+1 orders these reads before the
        // prefetch that overwrites this buffer.
    }

    // ---- epilogue: reduce l across the 4-lane row group, store fp32 ----
    {
        l0 += __shfl_xor_sync(0xffffffffu, l0, 1);
        l0 += __shfl_xor_sync(0xffffffffu, l0, 2);
        l1 += __shfl_xor_sync(0xffffffffu, l1, 1);
        l1 += __shfl_xor_sync(0xffffffffu, l1, 2);
        const int r = lane >> 2, c2 = (lane & 3) * 2;
        float inv0 = 1.0f / l0, inv1 = 1.0f / l1;
        int row0 = qb + warp * 16 + r;
        size_t o0 = ((size_t)b * SS + row0) * DD + h * DH;
        size_t o1 = ((size_t)b * SS + row0 + 8) * DD + h * DH;
        #pragma unroll
        for (int nt = 0; nt < 8; nt++) {
            *(float2*)(out + o0 + nt * 8 + c2) =
                make_float2(oacc[nt][0] * inv0, oacc[nt][1] * inv0);
            *(float2*)(out + o1 + nt * 8 + c2) =
                make_float2(oacc[nt][2] * inv1, oacc[nt][3] * inv1);
        }
    }
}

// ---------------------------------------------------------------------------
extern "C" void kernel_launch(void* const* d_in, const int* in_sizes, int n_in,
                              void* d_out, int out_size) {
    const float* x  = (const float*)d_in[0];
    const float* Wq = (const float*)d_in[1];
    const float* bq = (const float*)d_in[2];
    const float* Wk = (const float*)d_in[3];
    const float* bk = (const float*)d_in[4];
    const float* Wv = (const float*)d_in[5];
    const float* bv = (const float*)d_in[6];
    float* out = (float*)d_out;

    split_x_kernel<<<M_TOTAL * DD / 1024, 256>>>((const float4*)x);
    split_w_kernel<<<dim3(DD/32, DD/32, 3), dim3(32, 8)>>>(Wq, Wk, Wv);

    cudaFuncSetAttribute(proj_mma_kernel,
                         cudaFuncAttributeMaxDynamicSharedMemorySize, PROJ_SMEM);
    proj_mma_kernel<<<1536, 128, PROJ_SMEM>>>(bq, bk, bv);

    cudaFuncSetAttribute(flash_mma_kernel,
                         cudaFuncAttributeMaxDynamicSharedMemorySize, FLASH_SMEM);
    flash_mma_kernel<<<dim3(SS/FQT, HH, BB), 128, FLASH_SMEM>>>(out);
}